// round 1
// baseline (speedup 1.0000x reference)
#include <cuda_runtime.h>
#include <math.h>

// Problem constants (fixed by the dataset shapes)
#define TT   1024      // sequence length
#define DD   1024      // model dim
#define HN   16        // heads
#define HD   64        // head dim
#define LAT  512       // latent dim
#define RDIM 64        // rope dim
#define NL   8         // layers
#define VV   32000     // vocab
#define FF   4096      // mlp hidden

// ---------------- scratch buffers (device globals, no allocation) ----------
__device__ float g_x  [TT * DD];
__device__ float g_nx [TT * DD];
__device__ float g_ql [TT * LAT];
__device__ float g_ckv[TT * LAT];
__device__ float g_q  [TT * DD];
__device__ float g_qr [TT * HN * RDIM];
__device__ float g_k  [TT * DD];
__device__ float g_v  [TT * DD];
__device__ float g_kr [TT * RDIM];
__device__ float g_att[TT * DD];
__device__ float g_tmp[TT * FF];

// ---------------- embedding -----------------------------------------------
__global__ void embed_kernel(const int* __restrict__ idx,
                             const float* __restrict__ wte,
                             float* __restrict__ x) {
    int t = blockIdx.x;
    int row = idx[t];
    for (int d = threadIdx.x; d < DD; d += blockDim.x)
        x[t * DD + d] = wte[row * DD + d];
}

// ---------------- rms norm (row length 1024) -------------------------------
__global__ void rmsnorm_kernel(const float* __restrict__ in,
                               float* __restrict__ out) {
    __shared__ float red[256];
    int row = blockIdx.x;
    int tid = threadIdx.x;
    const float* p = in + row * DD;
    float s = 0.f;
    for (int d = tid; d < DD; d += 256) { float v = p[d]; s += v * v; }
    red[tid] = s; __syncthreads();
    for (int off = 128; off > 0; off >>= 1) {
        if (tid < off) red[tid] += red[tid + off];
        __syncthreads();
    }
    float r = rsqrtf(red[0] / (float)DD + 1e-5f);
    float* o = out + row * DD;
    for (int d = tid; d < DD; d += 256) o[d] = p[d] * r;
}

// ---------------- RoPE: x layout [T][HH][RDIM], grid (T,HH), 32 threads ----
__global__ void rope_kernel(float* __restrict__ x) {
    int t = blockIdx.x, h = blockIdx.y, j = threadIdx.x;
    float f = powf(10000.f, -(float)j / 32.f);
    float ang = (float)t * f;
    float sv, cv;
    sincosf(ang, &sv, &cv);
    float* p = x + (t * gridDim.y + h) * RDIM;
    float x0 = p[j], x1 = p[j + 32];
    p[j]      = x0 * cv - x1 * sv;   // i < 32: x*cos - x[i+32]*sin
    p[j + 32] = x1 * cv + x0 * sv;   // i >=32: x*cos + x[i-32]*sin
}

// ---------------- attention: one block per (query t, head h) ---------------
__global__ void attn_kernel(const float* __restrict__ q,
                            const float* __restrict__ k,
                            const float* __restrict__ v,
                            const float* __restrict__ qr,
                            const float* __restrict__ kr,
                            float* __restrict__ out) {
    __shared__ float qh[HD];
    __shared__ float qrh[RDIM];
    __shared__ float sc[TT];
    __shared__ float red[128];

    int tq = blockIdx.x, h = blockIdx.y, tid = threadIdx.x;
    const float scale = rsqrtf((float)(HD + RDIM));

    if (tid < HD)  qh[tid]  = q [tq * DD + h * HD + tid];
    if (tid < RDIM) qrh[tid] = qr[tq * (HN * RDIM) + h * RDIM + tid];
    __syncthreads();

    // scores for causal keys
    for (int tk = tid; tk <= tq; tk += 128) {
        const float* krow  = k  + tk * DD + h * HD;
        const float* krrow = kr + tk * RDIM;
        float s = 0.f;
        #pragma unroll
        for (int d = 0; d < HD; d++)   s += qh[d]  * krow[d];
        #pragma unroll
        for (int r = 0; r < RDIM; r++) s += qrh[r] * krrow[r];
        sc[tk] = s * scale;
    }
    __syncthreads();

    // max
    float m = -INFINITY;
    for (int tk = tid; tk <= tq; tk += 128) m = fmaxf(m, sc[tk]);
    red[tid] = m; __syncthreads();
    for (int off = 64; off > 0; off >>= 1) {
        if (tid < off) red[tid] = fmaxf(red[tid], red[tid + off]);
        __syncthreads();
    }
    float mx = red[0]; __syncthreads();

    // exp + sum
    float ls = 0.f;
    for (int tk = tid; tk <= tq; tk += 128) {
        float e = __expf(sc[tk] - mx);
        sc[tk] = e;
        ls += e;
    }
    red[tid] = ls; __syncthreads();
    for (int off = 64; off > 0; off >>= 1) {
        if (tid < off) red[tid] += red[tid + off];
        __syncthreads();
    }
    float rinv = 1.f / red[0]; __syncthreads();

    // weighted sum over v: 2 partitions x 64 dims
    int d = tid & 63, part = tid >> 6;
    float acc = 0.f;
    for (int tk = part; tk <= tq; tk += 2)
        acc += sc[tk] * v[tk * DD + h * HD + d];
    red[tid] = acc; __syncthreads();
    if (tid < 64)
        out[tq * DD + h * HD + tid] = (red[tid] + red[tid + 64]) * rinv;
}

// ---------------- NT GEMM: C[M,N] = A[M,K] * B[N,K]^T (+epilogue) ----------
// BM=BN=64, BK=16, 256 threads, 4x4 per thread. Requires M%64==0, N%64==0, K%16==0.
// epi: 0 = store, 1 = store + residual R, 2 = relu
__global__ void gemm_nt(const float* __restrict__ A, const float* __restrict__ B,
                        float* __restrict__ C, const float* __restrict__ R,
                        int M, int N, int K, int epi) {
    __shared__ float As[16][64];
    __shared__ float Bs[16][64];

    int tid = threadIdx.x;
    int tx = tid & 15, ty = tid >> 4;
    int ldrow = tid >> 2, ldk = (tid & 3) << 2;
    int bm = blockIdx.y * 64, bn = blockIdx.x * 64;

    const float* Ag = A + (size_t)(bm + ldrow) * K + ldk;
    const float* Bg = B + (size_t)(bn + ldrow) * K + ldk;

    float acc[4][4] = {};

    for (int k0 = 0; k0 < K; k0 += 16) {
        float4 av = *(const float4*)(Ag + k0);
        float4 bv = *(const float4*)(Bg + k0);
        As[ldk + 0][ldrow] = av.x; As[ldk + 1][ldrow] = av.y;
        As[ldk + 2][ldrow] = av.z; As[ldk + 3][ldrow] = av.w;
        Bs[ldk + 0][ldrow] = bv.x; Bs[ldk + 1][ldrow] = bv.y;
        Bs[ldk + 2][ldrow] = bv.z; Bs[ldk + 3][ldrow] = bv.w;
        __syncthreads();
        #pragma unroll
        for (int kk = 0; kk < 16; kk++) {
            float4 a = *(const float4*)&As[kk][ty << 2];
            float4 b = *(const float4*)&Bs[kk][tx << 2];
            float ar[4] = {a.x, a.y, a.z, a.w};
            float br[4] = {b.x, b.y, b.z, b.w};
            #pragma unroll
            for (int i = 0; i < 4; i++)
                #pragma unroll
                for (int j = 0; j < 4; j++)
                    acc[i][j] += ar[i] * br[j];
        }
        __syncthreads();
    }

    #pragma unroll
    for (int i = 0; i < 4; i++) {
        int row = bm + (ty << 2) + i;
        size_t cbase = (size_t)row * N + bn + (tx << 2);
        float4 o = make_float4(acc[i][0], acc[i][1], acc[i][2], acc[i][3]);
        if (epi == 1) {
            float4 r = *(const float4*)(R + cbase);
            o.x += r.x; o.y += r.y; o.z += r.z; o.w += r.w;
        } else if (epi == 2) {
            o.x = fmaxf(o.x, 0.f); o.y = fmaxf(o.y, 0.f);
            o.z = fmaxf(o.z, 0.f); o.w = fmaxf(o.w, 0.f);
        }
        *(float4*)(C + cbase) = o;
    }
}

// ---------------- host orchestration ---------------------------------------
static inline void gemm(const float* A, const float* B, float* C, const float* R,
                        int M, int N, int K, int epi) {
    dim3 grid(N / 64, M / 64);
    gemm_nt<<<grid, 256>>>(A, B, C, R, M, N, K, epi);
}

extern "C" void kernel_launch(void* const* d_in, const int* in_sizes, int n_in,
                              void* d_out, int out_size) {
    const int*   idx     = (const int*)  d_in[0];
    const float* wte     = (const float*)d_in[1];
    const float* wqdown  = (const float*)d_in[2];
    const float* wqup    = (const float*)d_in[3];
    const float* wqr     = (const float*)d_in[4];
    const float* wkvdown = (const float*)d_in[5];
    const float* wkup    = (const float*)d_in[6];
    const float* wvup    = (const float*)d_in[7];
    const float* wkr     = (const float*)d_in[8];
    const float* wo      = (const float*)d_in[9];
    const float* fc1     = (const float*)d_in[10];
    const float* fc2     = (const float*)d_in[11];
    const float* lm_head = (const float*)d_in[12];
    float* out = (float*)d_out;

    void *px, *pnx, *pql, *pckv, *pq, *pqr, *pk, *pv, *pkr, *patt, *ptmp;
    cudaGetSymbolAddress(&px,   g_x);
    cudaGetSymbolAddress(&pnx,  g_nx);
    cudaGetSymbolAddress(&pql,  g_ql);
    cudaGetSymbolAddress(&pckv, g_ckv);
    cudaGetSymbolAddress(&pq,   g_q);
    cudaGetSymbolAddress(&pqr,  g_qr);
    cudaGetSymbolAddress(&pk,   g_k);
    cudaGetSymbolAddress(&pv,   g_v);
    cudaGetSymbolAddress(&pkr,  g_kr);
    cudaGetSymbolAddress(&patt, g_att);
    cudaGetSymbolAddress(&ptmp, g_tmp);
    float* x   = (float*)px;   float* nx  = (float*)pnx;
    float* ql  = (float*)pql;  float* ckv = (float*)pckv;
    float* q   = (float*)pq;   float* qr  = (float*)pqr;
    float* k   = (float*)pk;   float* v   = (float*)pv;
    float* kr  = (float*)pkr;  float* att = (float*)patt;
    float* tmp = (float*)ptmp;

    embed_kernel<<<TT, 256>>>(idx, wte, x);
    rmsnorm_kernel<<<TT, 256>>>(x, x);

    for (int l = 0; l < NL; l++) {
        const float* wqd_l = wqdown  + (size_t)l * LAT * DD;
        const float* wqu_l = wqup    + (size_t)l * DD * LAT;
        const float* wqr_l = wqr     + (size_t)l * (HN * RDIM) * LAT;
        const float* wkd_l = wkvdown + (size_t)l * LAT * DD;
        const float* wku_l = wkup    + (size_t)l * DD * LAT;
        const float* wvu_l = wvup    + (size_t)l * DD * LAT;
        const float* wkr_l = wkr     + (size_t)l * RDIM * DD;
        const float* wo_l  = wo      + (size_t)l * DD * DD;
        const float* fc1_l = fc1     + (size_t)l * FF * DD;
        const float* fc2_l = fc2     + (size_t)l * DD * FF;

        rmsnorm_kernel<<<TT, 256>>>(x, nx);

        gemm(nx,  wqd_l, ql,  nullptr, TT, LAT,       DD,  0);
        gemm(ql,  wqu_l, q,   nullptr, TT, DD,        LAT, 0);
        gemm(ql,  wqr_l, qr,  nullptr, TT, HN * RDIM, LAT, 0);
        gemm(nx,  wkd_l, ckv, nullptr, TT, LAT,       DD,  0);
        gemm(ckv, wku_l, k,   nullptr, TT, DD,        LAT, 0);
        gemm(ckv, wvu_l, v,   nullptr, TT, DD,        LAT, 0);
        gemm(nx,  wkr_l, kr,  nullptr, TT, RDIM,      DD,  0);

        rope_kernel<<<dim3(TT, HN), 32>>>(qr);
        rope_kernel<<<dim3(TT, 1), 32>>>(kr);

        attn_kernel<<<dim3(TT, HN), 128>>>(q, k, v, qr, kr, att);

        gemm(att, wo_l, x, x, TT, DD, DD, 1);          // x += attn @ wo^T

        rmsnorm_kernel<<<TT, 256>>>(x, nx);
        gemm(nx,  fc1_l, tmp, nullptr, TT, FF, DD, 2); // relu
        gemm(tmp, fc2_l, x,   x,       TT, DD, FF, 1); // x += h @ fc2^T
    }

    gemm(x, lm_head, out, nullptr, TT, VV, DD, 0);     // logits
}

// round 2
// speedup vs baseline: 1.0036x; 1.0036x over previous
#include <cuda_runtime.h>
#include <math.h>

// Problem constants (fixed by the dataset shapes)
#define TT   1024      // sequence length
#define DD   1024      // model dim
#define HN   16        // heads
#define HD   64        // head dim
#define LAT  512       // latent dim
#define RDIM 64        // rope dim
#define NL   8         // layers
#define VV   32000     // vocab
#define FF   4096      // mlp hidden

// ---------------- scratch buffers (device globals, no allocation) ----------
__device__ float g_x  [TT * DD];
__device__ float g_nx [TT * DD];
__device__ float g_ql [TT * LAT];
__device__ float g_ckv[TT * LAT];
__device__ float g_q  [TT * DD];
__device__ float g_qr [TT * HN * RDIM];
__device__ float g_k  [TT * DD];
__device__ float g_v  [TT * DD];
__device__ float g_kr [TT * RDIM];
__device__ float g_att[TT * DD];
__device__ float g_tmp[TT * FF];

// ---------------- embedding -----------------------------------------------
__global__ void embed_kernel(const int* __restrict__ idx,
                             const float* __restrict__ wte,
                             float* __restrict__ x) {
    int t = blockIdx.x;
    int row = idx[t];
    for (int d = threadIdx.x; d < DD; d += blockDim.x)
        x[t * DD + d] = wte[row * DD + d];
}

// ---------------- rms norm (row length 1024) -------------------------------
__global__ void rmsnorm_kernel(const float* __restrict__ in,
                               float* __restrict__ out) {
    __shared__ float red[256];
    int row = blockIdx.x;
    int tid = threadIdx.x;
    const float* p = in + row * DD;
    float s = 0.f;
    for (int d = tid; d < DD; d += 256) { float v = p[d]; s += v * v; }
    red[tid] = s; __syncthreads();
    for (int off = 128; off > 0; off >>= 1) {
        if (tid < off) red[tid] += red[tid + off];
        __syncthreads();
    }
    float r = rsqrtf(red[0] / (float)DD + 1e-5f);
    float* o = out + row * DD;
    for (int d = tid; d < DD; d += 256) o[d] = p[d] * r;
}

// ---------------- RoPE: x layout [T][HH][RDIM], grid (T,HH), 32 threads ----
__global__ void rope_kernel(float* __restrict__ x) {
    int t = blockIdx.x, h = blockIdx.y, j = threadIdx.x;
    float f = powf(10000.f, -(float)j / 32.f);
    float ang = (float)t * f;
    float sv, cv;
    sincosf(ang, &sv, &cv);
    float* p = x + (t * gridDim.y + h) * RDIM;
    float x0 = p[j], x1 = p[j + 32];
    p[j]      = x0 * cv - x1 * sv;   // i < 32: x*cos - x[i+32]*sin
    p[j + 32] = x1 * cv + x0 * sv;   // i >=32: x*cos + x[i-32]*sin
}

// ---------------- attention: one block per (query t, head h) ---------------
__global__ void attn_kernel(const float* __restrict__ q,
                            const float* __restrict__ k,
                            const float* __restrict__ v,
                            const float* __restrict__ qr,
                            const float* __restrict__ kr,
                            float* __restrict__ out) {
    __shared__ float qh[HD];
    __shared__ float qrh[RDIM];
    __shared__ float sc[TT];
    __shared__ float red[128];

    int tq = blockIdx.x, h = blockIdx.y, tid = threadIdx.x;
    const float scale = rsqrtf((float)(HD + RDIM));

    if (tid < HD)  qh[tid]  = q [tq * DD + h * HD + tid];
    if (tid < RDIM) qrh[tid] = qr[tq * (HN * RDIM) + h * RDIM + tid];
    __syncthreads();

    // scores for causal keys
    for (int tk = tid; tk <= tq; tk += 128) {
        const float* krow  = k  + tk * DD + h * HD;
        const float* krrow = kr + tk * RDIM;
        float s = 0.f;
        #pragma unroll
        for (int d = 0; d < HD; d++)   s += qh[d]  * krow[d];
        #pragma unroll
        for (int r = 0; r < RDIM; r++) s += qrh[r] * krrow[r];
        sc[tk] = s * scale;
    }
    __syncthreads();

    // max
    float m = -INFINITY;
    for (int tk = tid; tk <= tq; tk += 128) m = fmaxf(m, sc[tk]);
    red[tid] = m; __syncthreads();
    for (int off = 64; off > 0; off >>= 1) {
        if (tid < off) red[tid] = fmaxf(red[tid], red[tid + off]);
        __syncthreads();
    }
    float mx = red[0]; __syncthreads();

    // exp + sum
    float ls = 0.f;
    for (int tk = tid; tk <= tq; tk += 128) {
        float e = __expf(sc[tk] - mx);
        sc[tk] = e;
        ls += e;
    }
    red[tid] = ls; __syncthreads();
    for (int off = 64; off > 0; off >>= 1) {
        if (tid < off) red[tid] += red[tid + off];
        __syncthreads();
    }
    float rinv = 1.f / red[0]; __syncthreads();

    // weighted sum over v: 2 partitions x 64 dims
    int d = tid & 63, part = tid >> 6;
    float acc = 0.f;
    for (int tk = part; tk <= tq; tk += 2)
        acc += sc[tk] * v[tk * DD + h * HD + d];
    red[tid] = acc; __syncthreads();
    if (tid < 64)
        out[tq * DD + h * HD + tid] = (red[tid] + red[tid + 64]) * rinv;
}

// ---------------- NT GEMM: C[M,N] = A[M,K] * B[N,K]^T (+epilogue) ----------
// BM=BN=64, BK=16, 256 threads, 4x4 per thread. Requires M%64==0, N%64==0, K%16==0.
// epi: 0 = store, 1 = store + residual R, 2 = relu
__global__ void gemm_nt(const float* __restrict__ A, const float* __restrict__ B,
                        float* __restrict__ C, const float* __restrict__ R,
                        int M, int N, int K, int epi) {
    __shared__ float As[16][64];
    __shared__ float Bs[16][64];

    int tid = threadIdx.x;
    int tx = tid & 15, ty = tid >> 4;
    int ldrow = tid >> 2, ldk = (tid & 3) << 2;
    int bm = blockIdx.y * 64, bn = blockIdx.x * 64;

    const float* Ag = A + (size_t)(bm + ldrow) * K + ldk;
    const float* Bg = B + (size_t)(bn + ldrow) * K + ldk;

    float acc[4][4] = {};

    for (int k0 = 0; k0 < K; k0 += 16) {
        float4 av = *(const float4*)(Ag + k0);
        float4 bv = *(const float4*)(Bg + k0);
        As[ldk + 0][ldrow] = av.x; As[ldk + 1][ldrow] = av.y;
        As[ldk + 2][ldrow] = av.z; As[ldk + 3][ldrow] = av.w;
        Bs[ldk + 0][ldrow] = bv.x; Bs[ldk + 1][ldrow] = bv.y;
        Bs[ldk + 2][ldrow] = bv.z; Bs[ldk + 3][ldrow] = bv.w;
        __syncthreads();
        #pragma unroll
        for (int kk = 0; kk < 16; kk++) {
            float4 a = *(const float4*)&As[kk][ty << 2];
            float4 b = *(const float4*)&Bs[kk][tx << 2];
            float ar[4] = {a.x, a.y, a.z, a.w};
            float br[4] = {b.x, b.y, b.z, b.w};
            #pragma unroll
            for (int i = 0; i < 4; i++)
                #pragma unroll
                for (int j = 0; j < 4; j++)
                    acc[i][j] += ar[i] * br[j];
        }
        __syncthreads();
    }

    #pragma unroll
    for (int i = 0; i < 4; i++) {
        int row = bm + (ty << 2) + i;
        size_t cbase = (size_t)row * N + bn + (tx << 2);
        float4 o = make_float4(acc[i][0], acc[i][1], acc[i][2], acc[i][3]);
        if (epi == 1) {
            float4 r = *(const float4*)(R + cbase);
            o.x += r.x; o.y += r.y; o.z += r.z; o.w += r.w;
        } else if (epi == 2) {
            o.x = fmaxf(o.x, 0.f); o.y = fmaxf(o.y, 0.f);
            o.z = fmaxf(o.z, 0.f); o.w = fmaxf(o.w, 0.f);
        }
        *(float4*)(C + cbase) = o;
    }
}

// ---------------- host orchestration ---------------------------------------
static inline void gemm(const float* A, const float* B, float* C, const float* R,
                        int M, int N, int K, int epi) {
    dim3 grid(N / 64, M / 64);
    gemm_nt<<<grid, 256>>>(A, B, C, R, M, N, K, epi);
}

extern "C" void kernel_launch(void* const* d_in, const int* in_sizes, int n_in,
                              void* d_out, int out_size) {
    const int*   idx     = (const int*)  d_in[0];
    const float* wte     = (const float*)d_in[1];
    const float* wqdown  = (const float*)d_in[2];
    const float* wqup    = (const float*)d_in[3];
    const float* wqr     = (const float*)d_in[4];
    const float* wkvdown = (const float*)d_in[5];
    const float* wkup    = (const float*)d_in[6];
    const float* wvup    = (const float*)d_in[7];
    const float* wkr     = (const float*)d_in[8];
    const float* wo      = (const float*)d_in[9];
    const float* fc1     = (const float*)d_in[10];
    const float* fc2     = (const float*)d_in[11];
    const float* lm_head = (const float*)d_in[12];
    float* out = (float*)d_out;

    void *px, *pnx, *pql, *pckv, *pq, *pqr, *pk, *pv, *pkr, *patt, *ptmp;
    cudaGetSymbolAddress(&px,   g_x);
    cudaGetSymbolAddress(&pnx,  g_nx);
    cudaGetSymbolAddress(&pql,  g_ql);
    cudaGetSymbolAddress(&pckv, g_ckv);
    cudaGetSymbolAddress(&pq,   g_q);
    cudaGetSymbolAddress(&pqr,  g_qr);
    cudaGetSymbolAddress(&pk,   g_k);
    cudaGetSymbolAddress(&pv,   g_v);
    cudaGetSymbolAddress(&pkr,  g_kr);
    cudaGetSymbolAddress(&patt, g_att);
    cudaGetSymbolAddress(&ptmp, g_tmp);
    float* x   = (float*)px;   float* nx  = (float*)pnx;
    float* ql  = (float*)pql;  float* ckv = (float*)pckv;
    float* q   = (float*)pq;   float* qr  = (float*)pqr;
    float* k   = (float*)pk;   float* v   = (float*)pv;
    float* kr  = (float*)pkr;  float* att = (float*)patt;
    float* tmp = (float*)ptmp;

    embed_kernel<<<TT, 256>>>(idx, wte, x);
    rmsnorm_kernel<<<TT, 256>>>(x, x);

    for (int l = 0; l < NL; l++) {
        const float* wqd_l = wqdown  + (size_t)l * LAT * DD;
        const float* wqu_l = wqup    + (size_t)l * DD * LAT;
        const float* wqr_l = wqr     + (size_t)l * (HN * RDIM) * LAT;
        const float* wkd_l = wkvdown + (size_t)l * LAT * DD;
        const float* wku_l = wkup    + (size_t)l * DD * LAT;
        const float* wvu_l = wvup    + (size_t)l * DD * LAT;
        const float* wkr_l = wkr     + (size_t)l * RDIM * DD;
        const float* wo_l  = wo      + (size_t)l * DD * DD;
        const float* fc1_l = fc1     + (size_t)l * FF * DD;
        const float* fc2_l = fc2     + (size_t)l * DD * FF;

        rmsnorm_kernel<<<TT, 256>>>(x, nx);

        gemm(nx,  wqd_l, ql,  nullptr, TT, LAT,       DD,  0);
        gemm(ql,  wqu_l, q,   nullptr, TT, DD,        LAT, 0);
        gemm(ql,  wqr_l, qr,  nullptr, TT, HN * RDIM, LAT, 0);
        gemm(nx,  wkd_l, ckv, nullptr, TT, LAT,       DD,  0);
        gemm(ckv, wku_l, k,   nullptr, TT, DD,        LAT, 0);
        gemm(ckv, wvu_l, v,   nullptr, TT, DD,        LAT, 0);
        gemm(nx,  wkr_l, kr,  nullptr, TT, RDIM,      DD,  0);

        rope_kernel<<<dim3(TT, HN), 32>>>(qr);
        rope_kernel<<<dim3(TT, 1), 32>>>(kr);

        attn_kernel<<<dim3(TT, HN), 128>>>(q, k, v, qr, kr, att);

        gemm(att, wo_l, x, x, TT, DD, DD, 1);          // x += attn @ wo^T

        rmsnorm_kernel<<<TT, 256>>>(x, nx);
        gemm(nx,  fc1_l, tmp, nullptr, TT, FF, DD, 2); // relu
        gemm(tmp, fc2_l, x,   x,       TT, DD, FF, 1); // x += h @ fc2^T
    }

    gemm(x, lm_head, out, nullptr, TT, VV, DD, 0);     // logits
}

// round 6
// speedup vs baseline: 5.7538x; 5.7334x over previous
#include <cuda_runtime.h>
#include <cuda_bf16.h>
#include <cstdint>
#include <math.h>

#define TT 1024
#define DD 1024
#define HN 16
#define HD 64
#define LAT 512
#define RDIM 64
#define NL 8
#define VV 32000
#define FF 4096

typedef __nv_bfloat16 bf16;

// ---- device scratch --------------------------------------------------------
__device__ __align__(256) float g_x [TT*DD];
__device__ __align__(256) float g_q [TT*DD];
__device__ __align__(256) float g_qr[TT*DD];
__device__ __align__(256) float g_k [TT*DD];
__device__ __align__(256) float g_v [TT*DD];
__device__ __align__(256) float g_kr[TT*RDIM];

__device__ __align__(256) bf16 g_nx_hi [TT*DD],  g_nx_lo [TT*DD];
__device__ __align__(256) bf16 g_ql_hi [TT*LAT], g_ql_lo [TT*LAT];
__device__ __align__(256) bf16 g_ckv_hi[TT*LAT], g_ckv_lo[TT*LAT];
__device__ __align__(256) bf16 g_att_hi[TT*DD],  g_att_lo[TT*DD];
__device__ __align__(256) bf16 g_tmp_hi[TT*FF],  g_tmp_lo[TT*FF];
__device__ __align__(256) bf16 g_x_hi  [TT*DD],  g_x_lo  [TT*DD];

// 6 latent-sized weights per layer (wqdown,wqup,wqr,wkvdown,wkup,wvup) + kr + wo + fc1 + fc2, then lm_head
#define TOTAL_W (NL*(6*LAT*DD + RDIM*DD + DD*DD + 2*FF*DD) + VV*DD)
__device__ __align__(256) bf16 g_whi[TOTAL_W];
__device__ __align__(256) bf16 g_wlo[TOTAL_W];

// ---- helpers -----------------------------------------------------------------
__device__ __forceinline__ void split2(float x, bf16& h, bf16& l) {
    h = __float2bfloat16_rn(x);
    l = __float2bfloat16_rn(x - __bfloat162float(h));
}

__device__ __forceinline__ void cp16(uint32_t dst, const void* src) {
    asm volatile("cp.async.cg.shared.global [%0], [%1], 16;" :: "r"(dst), "l"(src));
}
#define CP_COMMIT() asm volatile("cp.async.commit_group;" ::: "memory")
#define CP_WAIT1()  asm volatile("cp.async.wait_group 1;" ::: "memory")
#define CP_WAIT0()  asm volatile("cp.async.wait_group 0;" ::: "memory")

__device__ __forceinline__ void mma16816(float* c, const uint32_t* a, const uint32_t* b) {
    asm volatile(
        "mma.sync.aligned.m16n8k16.row.col.f32.bf16.bf16.f32 "
        "{%0,%1,%2,%3}, {%4,%5,%6,%7}, {%8,%9}, {%0,%1,%2,%3};"
        : "+f"(c[0]), "+f"(c[1]), "+f"(c[2]), "+f"(c[3])
        : "r"(a[0]), "r"(a[1]), "r"(a[2]), "r"(a[3]), "r"(b[0]), "r"(b[1]));
}

// smem word address with XOR swizzle (BK=32 bf16 -> 16 b32 words per row)
__device__ __forceinline__ int sadr(int row, int w) {
    return row * 16 + (((w >> 2) ^ (row & 3)) << 2) + (w & 3);
}

// ---- weight conversion ------------------------------------------------------
__global__ void cvt_split(const float* __restrict__ in, bf16* __restrict__ hi,
                          bf16* __restrict__ lo, int n) {
    int i = (blockIdx.x * blockDim.x + threadIdx.x) * 4;
    int stride = gridDim.x * blockDim.x * 4;
    for (; i < n; i += stride) {
        float4 v = *(const float4*)(in + i);
        bf16 h, l;
        split2(v.x, h, l); hi[i+0]=h; lo[i+0]=l;
        split2(v.y, h, l); hi[i+1]=h; lo[i+1]=l;
        split2(v.z, h, l); hi[i+2]=h; lo[i+2]=l;
        split2(v.w, h, l); hi[i+3]=h; lo[i+3]=l;
    }
}

// ---- embedding --------------------------------------------------------------
__global__ void embed_kernel(const int* __restrict__ idx, const float* __restrict__ wte,
                             float* __restrict__ x) {
    int t = blockIdx.x;
    int row = idx[t];
    float4 v = *(const float4*)(wte + (size_t)row * DD + threadIdx.x * 4);
    *(float4*)(x + (size_t)t * DD + threadIdx.x * 4) = v;
}

// ---- rmsnorm ----------------------------------------------------------------
__global__ void rmsnorm_kernel(const float* __restrict__ in, float* __restrict__ out,
                               bf16* __restrict__ ohi, bf16* __restrict__ olo) {
    __shared__ float red[8];
    int row = blockIdx.x, tid = threadIdx.x;
    float4 v = *(const float4*)(in + (size_t)row * DD + tid * 4);
    float s = v.x*v.x + v.y*v.y + v.z*v.z + v.w*v.w;
    #pragma unroll
    for (int o = 16; o > 0; o >>= 1) s += __shfl_xor_sync(0xffffffff, s, o);
    if ((tid & 31) == 0) red[tid >> 5] = s;
    __syncthreads();
    if (tid < 8) {
        float t2 = red[tid];
        #pragma unroll
        for (int o = 4; o > 0; o >>= 1) t2 += __shfl_xor_sync(0xff, t2, o);
        if (tid == 0) red[0] = t2;
    }
    __syncthreads();
    float r = rsqrtf(red[0] / (float)DD + 1e-5f);
    float4 o4 = make_float4(v.x*r, v.y*r, v.z*r, v.w*r);
    if (out) *(float4*)(out + (size_t)row * DD + tid * 4) = o4;
    if (ohi) {
        size_t b = (size_t)row * DD + tid * 4;
        bf16 h, l;
        split2(o4.x, h, l); ohi[b+0]=h; olo[b+0]=l;
        split2(o4.y, h, l); ohi[b+1]=h; olo[b+1]=l;
        split2(o4.z, h, l); ohi[b+2]=h; olo[b+2]=l;
        split2(o4.w, h, l); ohi[b+3]=h; olo[b+3]=l;
    }
}

// ---- RoPE -------------------------------------------------------------------
__global__ void rope_kernel(float* __restrict__ x, int nh) {
    int t = blockIdx.x, h = blockIdx.y, j = threadIdx.x;
    float f = powf(10000.f, -(float)j / 32.f);
    float sv, cv;
    sincosf((float)t * f, &sv, &cv);
    float* p = x + ((size_t)t * nh + h) * RDIM;
    float x0 = p[j], x1 = p[j + 32];
    p[j]      = x0 * cv - x1 * sv;
    p[j + 32] = x1 * cv + x0 * sv;
}

// ---- split-bf16 NT GEMM via mma.sync ------------------------------------------
// C[M,N] = (Ahi+Alo)[M,K] * (Bhi+Blo)[N,K]^T.  BM=128, BK=32, 256 threads.
// Warp layout 4(M) x 2(N); warp tile 32 x (BN/2).
template<int BN>
__global__ void __launch_bounds__(256) gemm_mma(
    const bf16* __restrict__ Ahi, const bf16* __restrict__ Alo,
    const bf16* __restrict__ Bhi, const bf16* __restrict__ Blo,
    float* __restrict__ C, const float* __restrict__ Rres,
    bf16* __restrict__ Chi, bf16* __restrict__ Clo,
    int M, int N, int K, int relu)
{
    extern __shared__ uint32_t smw[];
    constexpr int AT  = 128 * 16;          // words per A tile (one dtype)
    constexpr int BT  = BN * 16;
    constexpr int STG = 2 * AT + 2 * BT;   // words per stage: Ahi Alo Bhi Blo
    constexpr int NT  = BN / 16;           // 8x8 n-subtiles per warp

    int tid = threadIdx.x, lane = tid & 31, w = tid >> 5;
    int wm = w & 3, wn = w >> 2;
    int bm = blockIdx.y * 128, bn = blockIdx.x * BN;

    uint32_t sbase = (uint32_t)__cvta_generic_to_shared(smw);

    auto load_stage = [&](int i, int st) {
        int k0 = i * 32;
        uint32_t so = sbase + (uint32_t)(st * STG) * 4;
        for (int e = tid; e < 512; e += 256) {
            int r = e >> 2, kq = e & 3;
            size_t g = (size_t)(bm + r) * K + k0 + kq * 8;
            uint32_t d = so + (uint32_t)(r * 16 + ((kq ^ (r & 3)) << 2)) * 4;
            cp16(d, Ahi + g);
            cp16(d + AT * 4, Alo + g);
        }
        for (int e = tid; e < BN * 4; e += 256) {
            int r = e >> 2, kq = e & 3;
            size_t g = (size_t)(bn + r) * K + k0 + kq * 8;
            uint32_t d = so + (uint32_t)(2 * AT + r * 16 + ((kq ^ (r & 3)) << 2)) * 4;
            cp16(d, Bhi + g);
            cp16(d + BT * 4, Blo + g);
        }
        CP_COMMIT();
    };

    float acc[2][NT][4];
    #pragma unroll
    for (int mt = 0; mt < 2; mt++)
        #pragma unroll
        for (int nt = 0; nt < NT; nt++)
            #pragma unroll
            for (int c = 0; c < 4; c++) acc[mt][nt][c] = 0.f;

    int nk = K >> 5;
    load_stage(0, 0);
    for (int i = 0; i < nk; i++) {
        if (i + 1 < nk) { load_stage(i + 1, (i + 1) & 1); CP_WAIT1(); }
        else            { CP_WAIT0(); }
        __syncthreads();

        const uint32_t* Sa = smw + (i & 1) * STG;
        const uint32_t* Sb = Sa + 2 * AT;
        #pragma unroll
        for (int ks = 0; ks < 2; ks++) {
            int w0 = ks * 8 + (lane & 3);
            uint32_t ah[2][4], al[2][4];
            #pragma unroll
            for (int mt = 0; mt < 2; mt++) {
                int r0 = wm * 32 + mt * 16 + (lane >> 2);
                int i00 = sadr(r0, w0),     i10 = sadr(r0 + 8, w0);
                int i01 = sadr(r0, w0 + 4), i11 = sadr(r0 + 8, w0 + 4);
                ah[mt][0] = Sa[i00]; ah[mt][1] = Sa[i10];
                ah[mt][2] = Sa[i01]; ah[mt][3] = Sa[i11];
                al[mt][0] = Sa[AT + i00]; al[mt][1] = Sa[AT + i10];
                al[mt][2] = Sa[AT + i01]; al[mt][3] = Sa[AT + i11];
            }
            #pragma unroll
            for (int nt = 0; nt < NT; nt++) {
                int n0 = wn * (BN / 2) + nt * 8 + (lane >> 2);
                int j0 = sadr(n0, w0), j1 = sadr(n0, w0 + 4);
                uint32_t bh[2] = { Sb[j0], Sb[j1] };
                uint32_t bl[2] = { Sb[BT + j0], Sb[BT + j1] };
                #pragma unroll
                for (int mt = 0; mt < 2; mt++) {
                    mma16816(acc[mt][nt], ah[mt], bh);
                    mma16816(acc[mt][nt], ah[mt], bl);
                    mma16816(acc[mt][nt], al[mt], bh);
                }
            }
        }
        __syncthreads();
    }

    // ---- epilogue -------------------------------------------------------------
    #pragma unroll
    for (int mt = 0; mt < 2; mt++) {
        #pragma unroll
        for (int nt = 0; nt < NT; nt++) {
            int col = bn + wn * (BN / 2) + nt * 8 + (lane & 3) * 2;
            #pragma unroll
            for (int half = 0; half < 2; half++) {
                int row = bm + wm * 32 + mt * 16 + (lane >> 2) + half * 8;
                float v0 = acc[mt][nt][half * 2 + 0];
                float v1 = acc[mt][nt][half * 2 + 1];
                size_t base = (size_t)row * N + col;
                if (Rres) {
                    float2 rr = *(const float2*)(Rres + base);
                    v0 += rr.x; v1 += rr.y;
                }
                if (relu) { v0 = fmaxf(v0, 0.f); v1 = fmaxf(v1, 0.f); }
                if (C) *(float2*)(C + base) = make_float2(v0, v1);
                if (Chi) {
                    bf16 h0, l0, h1, l1;
                    split2(v0, h0, l0);
                    split2(v1, h1, l1);
                    *(__nv_bfloat162*)(Chi + base) = __halves2bfloat162(h0, h1);
                    *(__nv_bfloat162*)(Clo + base) = __halves2bfloat162(l0, l1);
                }
            }
        }
    }
}

// ---- tiled fp32 attention ------------------------------------------------------
#define PQ 65
#define PV2 68
__global__ void __launch_bounds__(256, 1) attn_tc(
    const float* __restrict__ q,  const float* __restrict__ qr,
    const float* __restrict__ k,  const float* __restrict__ v,
    const float* __restrict__ kr,
    bf16* __restrict__ atthi, bf16* __restrict__ attlo)
{
    extern __shared__ float sm[];
    float* Qt   = sm;                 // [128][PQ] dim-major
    float* Kt   = Qt + 128 * PQ;      // [128][PQ]
    float* Vt   = Kt + 128 * PQ;      // [64][PV2] row-major
    float* Pt   = Vt + 64 * PV2;      // [64][PQ]
    float* rowM = Pt + 64 * PQ;
    float* rowL = rowM + 64;
    float* rowA = rowL + 64;

    int h = blockIdx.y, tid = threadIdx.x;
    int qq = tid & 15, kq = tid >> 4;
    const float scale = rsqrtf(128.f);

    for (int half = 0; half < 2; half++) {
        int qt = half ? (15 - (int)blockIdx.x) : (int)blockIdx.x;
        for (int idx = tid * 4; idx < 64 * 128; idx += 1024) {
            int row = idx >> 7, d = idx & 127;
            int t = qt * 64 + row;
            const float* src = (d < 64) ? (q  + (size_t)t * DD + h * HD + d)
                                        : (qr + (size_t)t * DD + h * HD + (d - 64));
            float4 vv = *(const float4*)src;
            Qt[(d+0)*PQ+row]=vv.x; Qt[(d+1)*PQ+row]=vv.y;
            Qt[(d+2)*PQ+row]=vv.z; Qt[(d+3)*PQ+row]=vv.w;
        }
        if (tid < 64) { rowM[tid] = -1e30f; rowL[tid] = 0.f; }
        float O[4][4] = {};
        __syncthreads();

        for (int kt = 0; kt <= qt; kt++) {
            for (int idx = tid * 4; idx < 64 * 128; idx += 1024) {
                int row = idx >> 7, d = idx & 127;
                int t = kt * 64 + row;
                const float* src = (d < 64) ? (k  + (size_t)t * DD + h * HD + d)
                                            : (kr + (size_t)t * RDIM + (d - 64));
                float4 vv = *(const float4*)src;
                Kt[(d+0)*PQ+row]=vv.x; Kt[(d+1)*PQ+row]=vv.y;
                Kt[(d+2)*PQ+row]=vv.z; Kt[(d+3)*PQ+row]=vv.w;
            }
            for (int idx = tid * 4; idx < 64 * 64; idx += 1024) {
                int row = idx >> 6, d = idx & 63;
                float4 vv = *(const float4*)(v + (size_t)(kt*64+row) * DD + h * HD + d);
                *(float4*)(Vt + row * PV2 + d) = vv;
            }
            __syncthreads();

            float s[4][4] = {};
            #pragma unroll 2
            for (int d = 0; d < 128; d++) {
                float qv[4], kv[4];
                #pragma unroll
                for (int i = 0; i < 4; i++) qv[i] = Qt[d*PQ + qq + 16*i];
                #pragma unroll
                for (int j = 0; j < 4; j++) kv[j] = Kt[d*PQ + kq + 16*j];
                #pragma unroll
                for (int i = 0; i < 4; i++)
                    #pragma unroll
                    for (int j = 0; j < 4; j++)
                        s[i][j] += qv[i] * kv[j];
            }
            #pragma unroll
            for (int i = 0; i < 4; i++)
                #pragma unroll
                for (int j = 0; j < 4; j++) {
                    int tq = qt*64 + qq + 16*i, tk = kt*64 + kq + 16*j;
                    s[i][j] = (tk <= tq) ? s[i][j] * scale : -1e30f;
                    Pt[(qq+16*i)*PQ + kq + 16*j] = s[i][j];
                }
            __syncthreads();

            if (tid < 64) {
                float m = -1e30f;
                #pragma unroll 8
                for (int kk = 0; kk < 64; kk++) m = fmaxf(m, Pt[tid*PQ + kk]);
                float mo = rowM[tid];
                float mn = fmaxf(mo, m);
                rowM[tid] = mn;
                rowA[tid] = __expf(mo - mn);
            }
            __syncthreads();

            #pragma unroll
            for (int i = 0; i < 4; i++) {
                float mn = rowM[qq + 16*i];
                float al = rowA[qq + 16*i];
                #pragma unroll
                for (int j = 0; j < 4; j++) {
                    float e = __expf(s[i][j] - mn);
                    Pt[(qq+16*i)*PQ + kq + 16*j] = e;
                    O[i][j] *= al;
                }
            }
            __syncthreads();

            if (tid < 64) {
                float sum = 0.f;
                #pragma unroll 8
                for (int kk = 0; kk < 64; kk++) sum += Pt[tid*PQ + kk];
                rowL[tid] = rowL[tid] * rowA[tid] + sum;
            }

            #pragma unroll 2
            for (int kk = 0; kk < 64; kk++) {
                float pv[4], vv[4];
                #pragma unroll
                for (int i = 0; i < 4; i++) pv[i] = Pt[(qq+16*i)*PQ + kk];
                #pragma unroll
                for (int j = 0; j < 4; j++) vv[j] = Vt[kk*PV2 + kq + 16*j];
                #pragma unroll
                for (int i = 0; i < 4; i++)
                    #pragma unroll
                    for (int j = 0; j < 4; j++)
                        O[i][j] += pv[i] * vv[j];
            }
            __syncthreads();
        }

        #pragma unroll
        for (int i = 0; i < 4; i++) {
            int t = qt*64 + qq + 16*i;
            float rl = 1.f / rowL[qq + 16*i];
            #pragma unroll
            for (int j = 0; j < 4; j++) {
                float val = O[i][j] * rl;
                bf16 hh, ll;
                split2(val, hh, ll);
                size_t o = (size_t)t * DD + h * HD + kq + 16*j;
                atthi[o] = hh; attlo[o] = ll;
            }
        }
        __syncthreads();
    }
}

// ---- host orchestration ---------------------------------------------------------
#define SMEM128 ((2 * (2*128*16 + 2*128*16)) * 4)   // 65536 B
#define SMEM64G ((2 * (2*128*16 + 2*64*16)) * 4)    // 49152 B
#define SMEMATT ((128*PQ*2 + 64*PV2 + 64*PQ + 192) * 4)

static void gemm128(const bf16* Ah, const bf16* Al, const bf16* Bh, const bf16* Bl,
                    float* C, const float* R, bf16* Ch, bf16* Cl,
                    int M, int N, int K, int relu) {
    dim3 grid(N / 128, M / 128);
    gemm_mma<128><<<grid, 256, SMEM128>>>(Ah, Al, Bh, Bl, C, R, Ch, Cl, M, N, K, relu);
}
static void gemm64(const bf16* Ah, const bf16* Al, const bf16* Bh, const bf16* Bl,
                   float* C, int M, int N, int K) {
    dim3 grid(N / 64, M / 128);
    gemm_mma<64><<<grid, 256, SMEM64G>>>(Ah, Al, Bh, Bl, C, nullptr, nullptr, nullptr, M, N, K, 0);
}

extern "C" void kernel_launch(void* const* d_in, const int* in_sizes, int n_in,
                              void* d_out, int out_size) {
    const int*   idx     = (const int*)  d_in[0];
    const float* wte     = (const float*)d_in[1];
    const float* w_f32[11] = {
        (const float*)d_in[2],  (const float*)d_in[3],  (const float*)d_in[4],
        (const float*)d_in[5],  (const float*)d_in[6],  (const float*)d_in[7],
        (const float*)d_in[8],  (const float*)d_in[9],  (const float*)d_in[10],
        (const float*)d_in[11], (const float*)d_in[12] };
    const size_t w_sz[11] = {
        (size_t)NL*LAT*DD, (size_t)NL*DD*LAT, (size_t)NL*DD*LAT,
        (size_t)NL*LAT*DD, (size_t)NL*DD*LAT, (size_t)NL*DD*LAT,
        (size_t)NL*RDIM*DD, (size_t)NL*DD*DD, (size_t)NL*FF*DD,
        (size_t)NL*DD*FF, (size_t)VV*DD };
    float* out = (float*)d_out;

    cudaFuncSetAttribute(gemm_mma<128>, cudaFuncAttributeMaxDynamicSharedMemorySize, SMEM128);
    cudaFuncSetAttribute(gemm_mma<64>,  cudaFuncAttributeMaxDynamicSharedMemorySize, SMEM64G);
    cudaFuncSetAttribute(attn_tc,       cudaFuncAttributeMaxDynamicSharedMemorySize, SMEMATT);

    void* p;
    cudaGetSymbolAddress(&p, g_x);      float* x    = (float*)p;
    cudaGetSymbolAddress(&p, g_q);      float* qf   = (float*)p;
    cudaGetSymbolAddress(&p, g_qr);     float* qrf  = (float*)p;
    cudaGetSymbolAddress(&p, g_k);      float* kf   = (float*)p;
    cudaGetSymbolAddress(&p, g_v);      float* vf   = (float*)p;
    cudaGetSymbolAddress(&p, g_kr);     float* krf  = (float*)p;
    cudaGetSymbolAddress(&p, g_nx_hi);  bf16* nxh   = (bf16*)p;
    cudaGetSymbolAddress(&p, g_nx_lo);  bf16* nxl   = (bf16*)p;
    cudaGetSymbolAddress(&p, g_ql_hi);  bf16* qlh   = (bf16*)p;
    cudaGetSymbolAddress(&p, g_ql_lo);  bf16* qll   = (bf16*)p;
    cudaGetSymbolAddress(&p, g_ckv_hi); bf16* ckvh  = (bf16*)p;
    cudaGetSymbolAddress(&p, g_ckv_lo); bf16* ckvl  = (bf16*)p;
    cudaGetSymbolAddress(&p, g_att_hi); bf16* atth  = (bf16*)p;
    cudaGetSymbolAddress(&p, g_att_lo); bf16* attl  = (bf16*)p;
    cudaGetSymbolAddress(&p, g_tmp_hi); bf16* tmph  = (bf16*)p;
    cudaGetSymbolAddress(&p, g_tmp_lo); bf16* tmpl  = (bf16*)p;
    cudaGetSymbolAddress(&p, g_x_hi);   bf16* xh    = (bf16*)p;
    cudaGetSymbolAddress(&p, g_x_lo);   bf16* xl    = (bf16*)p;
    cudaGetSymbolAddress(&p, g_whi);    bf16* whi   = (bf16*)p;
    cudaGetSymbolAddress(&p, g_wlo);    bf16* wlo   = (bf16*)p;

    size_t off = 0;
    bf16* w_hi[11]; bf16* w_lo[11];
    for (int i = 0; i < 11; i++) {
        w_hi[i] = whi + off; w_lo[i] = wlo + off;
        cvt_split<<<1024, 256>>>(w_f32[i], w_hi[i], w_lo[i], (int)w_sz[i]);
        off += w_sz[i];
    }
    const bf16 *wqd_h = w_hi[0], *wqd_l = w_lo[0], *wqu_h = w_hi[1], *wqu_l = w_lo[1];
    const bf16 *wqr_h = w_hi[2], *wqr_l = w_lo[2], *wkd_h = w_hi[3], *wkd_l = w_lo[3];
    const bf16 *wku_h = w_hi[4], *wku_l = w_lo[4], *wvu_h = w_hi[5], *wvu_l = w_lo[5];
    const bf16 *wkr_h = w_hi[6], *wkr_l = w_lo[6], *wo_h  = w_hi[7], *wo_l  = w_lo[7];
    const bf16 *fc1_h = w_hi[8], *fc1_l = w_lo[8], *fc2_h = w_hi[9], *fc2_l = w_lo[9];
    const bf16 *lmh_h = w_hi[10], *lmh_l = w_lo[10];

    embed_kernel<<<TT, 256>>>(idx, wte, x);
    rmsnorm_kernel<<<TT, 256>>>(x, x, nullptr, nullptr);

    for (int l = 0; l < NL; l++) {
        size_t oD2 = (size_t)l * DD * DD, oLD = (size_t)l * LAT * DD;
        size_t oRD = (size_t)l * RDIM * DD, oF = (size_t)l * FF * DD;

        rmsnorm_kernel<<<TT, 256>>>(x, nullptr, nxh, nxl);

        gemm128(nxh, nxl, wqd_h + oLD, wqd_l + oLD, nullptr, nullptr, qlh, qll, TT, LAT, DD, 0);
        gemm128(qlh, qll, wqu_h + oLD, wqu_l + oLD, qf,  nullptr, nullptr, nullptr, TT, DD, LAT, 0);
        gemm128(qlh, qll, wqr_h + oLD, wqr_l + oLD, qrf, nullptr, nullptr, nullptr, TT, DD, LAT, 0);
        gemm128(nxh, nxl, wkd_h + oLD, wkd_l + oLD, nullptr, nullptr, ckvh, ckvl, TT, LAT, DD, 0);
        gemm128(ckvh, ckvl, wku_h + oLD, wku_l + oLD, kf, nullptr, nullptr, nullptr, TT, DD, LAT, 0);
        gemm128(ckvh, ckvl, wvu_h + oLD, wvu_l + oLD, vf, nullptr, nullptr, nullptr, TT, DD, LAT, 0);
        gemm64 (nxh, nxl, wkr_h + oRD, wkr_l + oRD, krf, TT, RDIM, DD);

        rope_kernel<<<dim3(TT, HN), 32>>>(qrf, HN);
        rope_kernel<<<dim3(TT, 1), 32>>>(krf, 1);

        attn_tc<<<dim3(8, 16), 256, SMEMATT>>>(qf, qrf, kf, vf, krf, atth, attl);

        gemm128(atth, attl, wo_h + oD2, wo_l + oD2, x, x, nullptr, nullptr, TT, DD, DD, 0);

        rmsnorm_kernel<<<TT, 256>>>(x, nullptr, nxh, nxl);
        gemm128(nxh, nxl, fc1_h + oF, fc1_l + oF, nullptr, nullptr, tmph, tmpl, TT, FF, DD, 1);
        bool last = (l == NL - 1);
        gemm128(tmph, tmpl, fc2_h + oF, fc2_l + oF, x, x,
                last ? xh : nullptr, last ? xl : nullptr, TT, DD, FF, 0);
    }

    gemm128(xh, xl, lmh_h, lmh_l, out, nullptr, nullptr, nullptr, TT, VV, DD, 0);
}

// round 7
// speedup vs baseline: 6.9069x; 1.2004x over previous
#include <cuda_runtime.h>
#include <cuda_bf16.h>
#include <cstdint>
#include <math.h>

#define TT 1024
#define DD 1024
#define HN 16
#define HD 64
#define LAT 512
#define RDIM 64
#define NL 8
#define VV 32000
#define FF 4096

typedef __nv_bfloat16 bf16;

// ---- device scratch --------------------------------------------------------
__device__ __align__(256) float g_x [TT*DD];
__device__ __align__(256) float g_q [TT*DD];
__device__ __align__(256) float g_qr[TT*DD];
__device__ __align__(256) float g_k [TT*DD];
__device__ __align__(256) float g_v [TT*DD];
__device__ __align__(256) float g_kr[TT*RDIM];

__device__ __align__(256) bf16 g_nx_hi [TT*DD],  g_nx_lo [TT*DD];
__device__ __align__(256) bf16 g_ql_hi [TT*LAT], g_ql_lo [TT*LAT];
__device__ __align__(256) bf16 g_ckv_hi[TT*LAT], g_ckv_lo[TT*LAT];
__device__ __align__(256) bf16 g_att_hi[TT*DD],  g_att_lo[TT*DD];
__device__ __align__(256) bf16 g_tmp_hi[TT*FF],  g_tmp_lo[TT*FF];
__device__ __align__(256) bf16 g_x_hi  [TT*DD],  g_x_lo  [TT*DD];

#define TOTAL_W (NL*(6*LAT*DD + RDIM*DD + DD*DD + 2*FF*DD) + VV*DD)
__device__ __align__(256) bf16 g_whi[TOTAL_W];
__device__ __align__(256) bf16 g_wlo[TOTAL_W];

// ---- helpers -----------------------------------------------------------------
__device__ __forceinline__ void split2(float x, bf16& h, bf16& l) {
    h = __float2bfloat16_rn(x);
    l = __float2bfloat16_rn(x - __bfloat162float(h));
}
__device__ __forceinline__ uint32_t packbf(bf16 a, bf16 b) {
    __nv_bfloat162 t = __halves2bfloat162(a, b);
    return *reinterpret_cast<uint32_t*>(&t);
}
__device__ __forceinline__ uint32_t splitpack(float x, float y, uint32_t& lo) {
    bf16 hx, lx, hy, ly;
    split2(x, hx, lx); split2(y, hy, ly);
    lo = packbf(lx, ly);
    return packbf(hx, hy);
}

__device__ __forceinline__ void cp16(uint32_t dst, const void* src) {
    asm volatile("cp.async.cg.shared.global [%0], [%1], 16;" :: "r"(dst), "l"(src));
}
#define CP_COMMIT() asm volatile("cp.async.commit_group;" ::: "memory")
#define CP_WAIT1()  asm volatile("cp.async.wait_group 1;" ::: "memory")
#define CP_WAIT0()  asm volatile("cp.async.wait_group 0;" ::: "memory")

__device__ __forceinline__ void mma16816(float* c, const uint32_t* a, const uint32_t* b) {
    asm volatile(
        "mma.sync.aligned.m16n8k16.row.col.f32.bf16.bf16.f32 "
        "{%0,%1,%2,%3}, {%4,%5,%6,%7}, {%8,%9}, {%0,%1,%2,%3};"
        : "+f"(c[0]), "+f"(c[1]), "+f"(c[2]), "+f"(c[3])
        : "r"(a[0]), "r"(a[1]), "r"(a[2]), "r"(a[3]), "r"(b[0]), "r"(b[1]));
}

__device__ __forceinline__ int sadr(int row, int w) {
    return row * 16 + (((w >> 2) ^ (row & 3)) << 2) + (w & 3);
}

// ---- weight conversion (8 elems/thread, uint4 stores) -------------------------
__global__ void cvt_split(const float* __restrict__ in, bf16* __restrict__ hi,
                          bf16* __restrict__ lo, int n) {
    int i = (blockIdx.x * blockDim.x + threadIdx.x) * 8;
    int stride = gridDim.x * blockDim.x * 8;
    for (; i < n; i += stride) {
        float4 a = *(const float4*)(in + i);
        float4 b = *(const float4*)(in + i + 4);
        uint32_t h0,h1,h2,h3,l0,l1,l2,l3;
        h0 = splitpack(a.x, a.y, l0); h1 = splitpack(a.z, a.w, l1);
        h2 = splitpack(b.x, b.y, l2); h3 = splitpack(b.z, b.w, l3);
        *(uint4*)(hi + i) = make_uint4(h0, h1, h2, h3);
        *(uint4*)(lo + i) = make_uint4(l0, l1, l2, l3);
    }
}

// ---- embedding --------------------------------------------------------------
__global__ void embed_kernel(const int* __restrict__ idx, const float* __restrict__ wte,
                             float* __restrict__ x) {
    int t = blockIdx.x;
    int row = idx[t];
    float4 v = *(const float4*)(wte + (size_t)row * DD + threadIdx.x * 4);
    *(float4*)(x + (size_t)t * DD + threadIdx.x * 4) = v;
}

// ---- rmsnorm ----------------------------------------------------------------
__global__ void rmsnorm_kernel(const float* __restrict__ in, float* __restrict__ out,
                               bf16* __restrict__ ohi, bf16* __restrict__ olo) {
    __shared__ float red[8];
    int row = blockIdx.x, tid = threadIdx.x;
    float4 v = *(const float4*)(in + (size_t)row * DD + tid * 4);
    float s = v.x*v.x + v.y*v.y + v.z*v.z + v.w*v.w;
    #pragma unroll
    for (int o = 16; o > 0; o >>= 1) s += __shfl_xor_sync(0xffffffff, s, o);
    if ((tid & 31) == 0) red[tid >> 5] = s;
    __syncthreads();
    if (tid < 8) {
        float t2 = red[tid];
        #pragma unroll
        for (int o = 4; o > 0; o >>= 1) t2 += __shfl_xor_sync(0xff, t2, o);
        if (tid == 0) red[0] = t2;
    }
    __syncthreads();
    float r = rsqrtf(red[0] / (float)DD + 1e-5f);
    float4 o4 = make_float4(v.x*r, v.y*r, v.z*r, v.w*r);
    if (out) *(float4*)(out + (size_t)row * DD + tid * 4) = o4;
    if (ohi) {
        size_t b = (size_t)row * DD + tid * 4;
        uint32_t lo0, lo1;
        uint32_t hi0 = splitpack(o4.x, o4.y, lo0);
        uint32_t hi1 = splitpack(o4.z, o4.w, lo1);
        *(uint2*)(ohi + b) = make_uint2(hi0, hi1);
        *(uint2*)(olo + b) = make_uint2(lo0, lo1);
    }
}

// ---- RoPE -------------------------------------------------------------------
__global__ void rope_kernel(float* __restrict__ x, int nh) {
    int t = blockIdx.x, h = blockIdx.y, j = threadIdx.x;
    float f = powf(10000.f, -(float)j / 32.f);
    float sv, cv;
    sincosf((float)t * f, &sv, &cv);
    float* p = x + ((size_t)t * nh + h) * RDIM;
    float x0 = p[j], x1 = p[j + 32];
    p[j]      = x0 * cv - x1 * sv;
    p[j + 32] = x1 * cv + x0 * sv;
}

// ---- split-bf16 NT GEMM via mma.sync (unchanged, verified) --------------------
template<int BN>
__global__ void __launch_bounds__(256) gemm_mma(
    const bf16* __restrict__ Ahi, const bf16* __restrict__ Alo,
    const bf16* __restrict__ Bhi, const bf16* __restrict__ Blo,
    float* __restrict__ C, const float* __restrict__ Rres,
    bf16* __restrict__ Chi, bf16* __restrict__ Clo,
    int M, int N, int K, int relu)
{
    extern __shared__ uint32_t smw[];
    constexpr int AT  = 128 * 16;
    constexpr int BT  = BN * 16;
    constexpr int STG = 2 * AT + 2 * BT;
    constexpr int NT  = BN / 16;

    int tid = threadIdx.x, lane = tid & 31, w = tid >> 5;
    int wm = w & 3, wn = w >> 2;
    int bm = blockIdx.y * 128, bn = blockIdx.x * BN;

    uint32_t sbase = (uint32_t)__cvta_generic_to_shared(smw);

    auto load_stage = [&](int i, int st) {
        int k0 = i * 32;
        uint32_t so = sbase + (uint32_t)(st * STG) * 4;
        for (int e = tid; e < 512; e += 256) {
            int r = e >> 2, kq = e & 3;
            size_t g = (size_t)(bm + r) * K + k0 + kq * 8;
            uint32_t d = so + (uint32_t)(r * 16 + ((kq ^ (r & 3)) << 2)) * 4;
            cp16(d, Ahi + g);
            cp16(d + AT * 4, Alo + g);
        }
        for (int e = tid; e < BN * 4; e += 256) {
            int r = e >> 2, kq = e & 3;
            size_t g = (size_t)(bn + r) * K + k0 + kq * 8;
            uint32_t d = so + (uint32_t)(2 * AT + r * 16 + ((kq ^ (r & 3)) << 2)) * 4;
            cp16(d, Bhi + g);
            cp16(d + BT * 4, Blo + g);
        }
        CP_COMMIT();
    };

    float acc[2][NT][4];
    #pragma unroll
    for (int mt = 0; mt < 2; mt++)
        #pragma unroll
        for (int nt = 0; nt < NT; nt++)
            #pragma unroll
            for (int c = 0; c < 4; c++) acc[mt][nt][c] = 0.f;

    int nk = K >> 5;
    load_stage(0, 0);
    for (int i = 0; i < nk; i++) {
        if (i + 1 < nk) { load_stage(i + 1, (i + 1) & 1); CP_WAIT1(); }
        else            { CP_WAIT0(); }
        __syncthreads();

        const uint32_t* Sa = smw + (i & 1) * STG;
        const uint32_t* Sb = Sa + 2 * AT;
        #pragma unroll
        for (int ks = 0; ks < 2; ks++) {
            int w0 = ks * 8 + (lane & 3);
            uint32_t ah[2][4], al[2][4];
            #pragma unroll
            for (int mt = 0; mt < 2; mt++) {
                int r0 = wm * 32 + mt * 16 + (lane >> 2);
                int i00 = sadr(r0, w0),     i10 = sadr(r0 + 8, w0);
                int i01 = sadr(r0, w0 + 4), i11 = sadr(r0 + 8, w0 + 4);
                ah[mt][0] = Sa[i00]; ah[mt][1] = Sa[i10];
                ah[mt][2] = Sa[i01]; ah[mt][3] = Sa[i11];
                al[mt][0] = Sa[AT + i00]; al[mt][1] = Sa[AT + i10];
                al[mt][2] = Sa[AT + i01]; al[mt][3] = Sa[AT + i11];
            }
            #pragma unroll
            for (int nt = 0; nt < NT; nt++) {
                int n0 = wn * (BN / 2) + nt * 8 + (lane >> 2);
                int j0 = sadr(n0, w0), j1 = sadr(n0, w0 + 4);
                uint32_t bh[2] = { Sb[j0], Sb[j1] };
                uint32_t bl[2] = { Sb[BT + j0], Sb[BT + j1] };
                #pragma unroll
                for (int mt = 0; mt < 2; mt++) {
                    mma16816(acc[mt][nt], ah[mt], bh);
                    mma16816(acc[mt][nt], ah[mt], bl);
                    mma16816(acc[mt][nt], al[mt], bh);
                }
            }
        }
        __syncthreads();
    }

    #pragma unroll
    for (int mt = 0; mt < 2; mt++) {
        #pragma unroll
        for (int nt = 0; nt < NT; nt++) {
            int col = bn + wn * (BN / 2) + nt * 8 + (lane & 3) * 2;
            #pragma unroll
            for (int half = 0; half < 2; half++) {
                int row = bm + wm * 32 + mt * 16 + (lane >> 2) + half * 8;
                float v0 = acc[mt][nt][half * 2 + 0];
                float v1 = acc[mt][nt][half * 2 + 1];
                size_t base = (size_t)row * N + col;
                if (Rres) {
                    float2 rr = *(const float2*)(Rres + base);
                    v0 += rr.x; v1 += rr.y;
                }
                if (relu) { v0 = fmaxf(v0, 0.f); v1 = fmaxf(v1, 0.f); }
                if (C) *(float2*)(C + base) = make_float2(v0, v1);
                if (Chi) {
                    uint32_t lo;
                    uint32_t hi = splitpack(v0, v1, lo);
                    *(uint32_t*)(Chi + base) = hi;
                    *(uint32_t*)(Clo + base) = lo;
                }
            }
        }
    }
}

// ---- flash attention via mma.sync, split-bf16 ----------------------------------
// grid (8 pairs, 16 heads), 256 threads (8 warps: 4 m-warps x 2 n-warps).
// Per (qt,h): S = QK^T (64x64, d=128) 3-pass split MMA; softmax in fragments;
// P repacked in-register as A-operand; O += P V (3-pass split).
#define AQ 68   // word stride for Q/K tiles (64 + 4 pad -> conflict-free frags)
#define AV 36   // word stride for V^T tile (32 + 4 pad)
#define ATTSM ((4*64*AQ + 2*64*AV) * 4 + 64*65*4 + (64+64+128+128) * 4)

__global__ void __launch_bounds__(256, 1) attn_mma(
    const float* __restrict__ q,  const float* __restrict__ qr,
    const float* __restrict__ k,  const float* __restrict__ v,
    const float* __restrict__ kr,
    bf16* __restrict__ atthi, bf16* __restrict__ attlo)
{
    extern __shared__ uint32_t sw[];
    uint32_t* Qh = sw;                 // [64][AQ]
    uint32_t* Ql = Qh + 64 * AQ;
    uint32_t* Kh = Ql + 64 * AQ;
    uint32_t* Kl = Kh + 64 * AQ;
    uint32_t* Vh = Kl + 64 * AQ;       // [64 d][AV], keys packed 2/word
    uint32_t* Vl = Vh + 64 * AV;
    float* Ob   = (float*)(Vl + 64 * AV);  // [64][65]
    float* rowM = Ob + 64 * 65;
    float* rowL = rowM + 64;
    float* pm   = rowL + 64;           // [2][64]
    float* ps   = pm + 128;            // [2][64]

    int hh = blockIdx.y, tid = threadIdx.x;
    int lane = tid & 31, w = tid >> 5;
    int wm = w & 3, wn = w >> 2;
    int la = lane & 3, lr = lane >> 2;
    const float scale = rsqrtf(128.f);

    for (int half = 0; half < 2; half++) {
        int qt = half ? (15 - (int)blockIdx.x) : (int)blockIdx.x;

        // load Q tile -> split words
        for (int e = tid; e < 64 * 64; e += 256) {
            int r = e >> 6, wq = e & 63;
            int t = qt * 64 + r, d = wq * 2;
            const float* src = (d < 64) ? (q + (size_t)t * DD + hh * 64 + d)
                                        : (qr + (size_t)t * DD + hh * 64 + (d - 64));
            float2 f = *(const float2*)src;
            uint32_t lo;
            uint32_t hi = splitpack(f.x, f.y, lo);
            Qh[r * AQ + wq] = hi; Ql[r * AQ + wq] = lo;
        }
        if (tid < 64) { rowM[tid] = -1e30f; rowL[tid] = 0.f; }

        float oacc[8][4];
        #pragma unroll
        for (int nt = 0; nt < 8; nt++)
            #pragma unroll
            for (int c = 0; c < 4; c++) oacc[nt][c] = 0.f;

        int rloc = wm * 16 + lr;       // local q row A; B = +8

        for (int kt = 0; kt <= qt; kt++) {
            __syncthreads();  // prev iter reads done before overwriting K/V

            for (int e = tid; e < 64 * 64; e += 256) {
                int r = e >> 6, wq = e & 63;
                int t = kt * 64 + r, d = wq * 2;
                const float* src = (d < 64) ? (k + (size_t)t * DD + hh * 64 + d)
                                            : (kr + (size_t)t * RDIM + (d - 64));
                float2 f = *(const float2*)src;
                uint32_t lo;
                uint32_t hi = splitpack(f.x, f.y, lo);
                Kh[r * AQ + wq] = hi; Kl[r * AQ + wq] = lo;
            }
            for (int e = tid; e < 64 * 32; e += 256) {
                int kp = e >> 6, d = e & 63;   // coalesced over d
                float v0 = v[(size_t)(kt * 64 + 2 * kp) * DD + hh * 64 + d];
                float v1 = v[(size_t)(kt * 64 + 2 * kp + 1) * DD + hh * 64 + d];
                uint32_t lo;
                uint32_t hi = splitpack(v0, v1, lo);
                Vh[d * AV + kp] = hi; Vl[d * AV + kp] = lo;
            }
            __syncthreads();

            // ---- S = Q K^T (3-pass split) ----
            float sacc[4][4];
            #pragma unroll
            for (int nt = 0; nt < 4; nt++)
                #pragma unroll
                for (int c = 0; c < 4; c++) sacc[nt][c] = 0.f;

            #pragma unroll
            for (int kk = 0; kk < 8; kk++) {
                int w0 = kk * 8 + la;
                uint32_t ah[4], al2[4];
                ah[0] = Qh[rloc * AQ + w0];        ah[1] = Qh[(rloc + 8) * AQ + w0];
                ah[2] = Qh[rloc * AQ + w0 + 4];    ah[3] = Qh[(rloc + 8) * AQ + w0 + 4];
                al2[0] = Ql[rloc * AQ + w0];       al2[1] = Ql[(rloc + 8) * AQ + w0];
                al2[2] = Ql[rloc * AQ + w0 + 4];   al2[3] = Ql[(rloc + 8) * AQ + w0 + 4];
                #pragma unroll
                for (int nt = 0; nt < 4; nt++) {
                    int n0 = wn * 32 + nt * 8 + lr;
                    uint32_t bh[2] = { Kh[n0 * AQ + w0], Kh[n0 * AQ + w0 + 4] };
                    uint32_t bl[2] = { Kl[n0 * AQ + w0], Kl[n0 * AQ + w0 + 4] };
                    mma16816(sacc[nt], ah, bh);
                    mma16816(sacc[nt], ah, bl);
                    mma16816(sacc[nt], al2, bh);
                }
            }

            // scale + causal mask
            int rgA = qt * 64 + rloc, rgB = rgA + 8;
            #pragma unroll
            for (int nt = 0; nt < 4; nt++) {
                int cg = kt * 64 + wn * 32 + nt * 8 + 2 * la;
                sacc[nt][0] = (cg     <= rgA) ? sacc[nt][0] * scale : -1e30f;
                sacc[nt][1] = (cg + 1 <= rgA) ? sacc[nt][1] * scale : -1e30f;
                sacc[nt][2] = (cg     <= rgB) ? sacc[nt][2] * scale : -1e30f;
                sacc[nt][3] = (cg + 1 <= rgB) ? sacc[nt][3] * scale : -1e30f;
            }

            // ---- partial row max ----
            float mA = -1e30f, mB = -1e30f;
            #pragma unroll
            for (int nt = 0; nt < 4; nt++) {
                mA = fmaxf(mA, fmaxf(sacc[nt][0], sacc[nt][1]));
                mB = fmaxf(mB, fmaxf(sacc[nt][2], sacc[nt][3]));
            }
            mA = fmaxf(mA, __shfl_xor_sync(0xffffffff, mA, 1));
            mA = fmaxf(mA, __shfl_xor_sync(0xffffffff, mA, 2));
            mB = fmaxf(mB, __shfl_xor_sync(0xffffffff, mB, 1));
            mB = fmaxf(mB, __shfl_xor_sync(0xffffffff, mB, 2));
            if (la == 0) { pm[wn * 64 + rloc] = mA; pm[wn * 64 + rloc + 8] = mB; }
            __syncthreads();

            float moA = rowM[rloc], moB = rowM[rloc + 8];
            float mnA = fmaxf(moA, fmaxf(pm[rloc], pm[64 + rloc]));
            float mnB = fmaxf(moB, fmaxf(pm[rloc + 8], pm[64 + rloc + 8]));
            float alA = __expf(moA - mnA), alB = __expf(moB - mnB);

            // p = exp(s - mn); rescale O; partial sums
            float sA = 0.f, sB = 0.f;
            #pragma unroll
            for (int nt = 0; nt < 4; nt++) {
                sacc[nt][0] = __expf(sacc[nt][0] - mnA);
                sacc[nt][1] = __expf(sacc[nt][1] - mnA);
                sacc[nt][2] = __expf(sacc[nt][2] - mnB);
                sacc[nt][3] = __expf(sacc[nt][3] - mnB);
                sA += sacc[nt][0] + sacc[nt][1];
                sB += sacc[nt][2] + sacc[nt][3];
            }
            #pragma unroll
            for (int nt = 0; nt < 8; nt++) {
                oacc[nt][0] *= alA; oacc[nt][1] *= alA;
                oacc[nt][2] *= alB; oacc[nt][3] *= alB;
            }
            sA += __shfl_xor_sync(0xffffffff, sA, 1);
            sA += __shfl_xor_sync(0xffffffff, sA, 2);
            sB += __shfl_xor_sync(0xffffffff, sB, 1);
            sB += __shfl_xor_sync(0xffffffff, sB, 2);
            __syncthreads();   // everyone done reading old rowM
            if (la == 0) { ps[wn * 64 + rloc] = sA; ps[wn * 64 + rloc + 8] = sB; }
            if (wn == 0 && la == 0) { rowM[rloc] = mnA; rowM[rloc + 8] = mnB; }
            __syncthreads();
            if (wn == 0 && la == 0) {
                rowL[rloc]     = rowL[rloc]     * alA + ps[rloc]     + ps[64 + rloc];
                rowL[rloc + 8] = rowL[rloc + 8] * alB + ps[rloc + 8] + ps[64 + rloc + 8];
            }

            // ---- O += P V (3-pass split); warp covers its 32 keys ----
            #pragma unroll
            for (int kc = 0; kc < 2; kc++) {
                uint32_t phi[4], plo[4];
                phi[0] = splitpack(sacc[2*kc][0],   sacc[2*kc][1],   plo[0]);
                phi[1] = splitpack(sacc[2*kc][2],   sacc[2*kc][3],   plo[1]);
                phi[2] = splitpack(sacc[2*kc+1][0], sacc[2*kc+1][1], plo[2]);
                phi[3] = splitpack(sacc[2*kc+1][2], sacc[2*kc+1][3], plo[3]);
                int kw = wn * 16 + kc * 8 + la;
                #pragma unroll
                for (int nt = 0; nt < 8; nt++) {
                    int d0 = nt * 8 + lr;
                    uint32_t bh[2] = { Vh[d0 * AV + kw], Vh[d0 * AV + kw + 4] };
                    uint32_t bl[2] = { Vl[d0 * AV + kw], Vl[d0 * AV + kw + 4] };
                    mma16816(oacc[nt], phi, bh);
                    mma16816(oacc[nt], phi, bl);
                    mma16816(oacc[nt], plo, bh);
                }
            }
        }

        // ---- combine the two wn halves, normalize, store ----
        __syncthreads();
        if (wn == 0) {
            #pragma unroll
            for (int nt = 0; nt < 8; nt++) {
                int c0 = nt * 8 + 2 * la;
                Ob[rloc * 65 + c0]       = oacc[nt][0];
                Ob[rloc * 65 + c0 + 1]   = oacc[nt][1];
                Ob[(rloc+8) * 65 + c0]     = oacc[nt][2];
                Ob[(rloc+8) * 65 + c0 + 1] = oacc[nt][3];
            }
        }
        __syncthreads();
        if (wn == 1) {
            #pragma unroll
            for (int nt = 0; nt < 8; nt++) {
                int c0 = nt * 8 + 2 * la;
                Ob[rloc * 65 + c0]       += oacc[nt][0];
                Ob[rloc * 65 + c0 + 1]   += oacc[nt][1];
                Ob[(rloc+8) * 65 + c0]     += oacc[nt][2];
                Ob[(rloc+8) * 65 + c0 + 1] += oacc[nt][3];
            }
        }
        __syncthreads();
        for (int e = tid; e < 64 * 64; e += 256) {
            int r = e >> 6, d = e & 63;
            float val = Ob[r * 65 + d] / rowL[r];
            bf16 vh, vl;
            split2(val, vh, vl);
            size_t o = (size_t)(qt * 64 + r) * DD + hh * 64 + d;
            atthi[o] = vh; attlo[o] = vl;
        }
        __syncthreads();
    }
}

// ---- host orchestration ---------------------------------------------------------
#define SMEM128 ((2 * (2*128*16 + 2*128*16)) * 4)
#define SMEM64G ((2 * (2*128*16 + 2*64*16)) * 4)

static void gemm128(const bf16* Ah, const bf16* Al, const bf16* Bh, const bf16* Bl,
                    float* C, const float* R, bf16* Ch, bf16* Cl,
                    int M, int N, int K, int relu) {
    dim3 grid(N / 128, M / 128);
    gemm_mma<128><<<grid, 256, SMEM128>>>(Ah, Al, Bh, Bl, C, R, Ch, Cl, M, N, K, relu);
}
static void gemm64(const bf16* Ah, const bf16* Al, const bf16* Bh, const bf16* Bl,
                   float* C, int M, int N, int K) {
    dim3 grid(N / 64, M / 128);
    gemm_mma<64><<<grid, 256, SMEM64G>>>(Ah, Al, Bh, Bl, C, nullptr, nullptr, nullptr, M, N, K, 0);
}

extern "C" void kernel_launch(void* const* d_in, const int* in_sizes, int n_in,
                              void* d_out, int out_size) {
    const int*   idx     = (const int*)  d_in[0];
    const float* wte     = (const float*)d_in[1];
    const float* w_f32[11] = {
        (const float*)d_in[2],  (const float*)d_in[3],  (const float*)d_in[4],
        (const float*)d_in[5],  (const float*)d_in[6],  (const float*)d_in[7],
        (const float*)d_in[8],  (const float*)d_in[9],  (const float*)d_in[10],
        (const float*)d_in[11], (const float*)d_in[12] };
    const size_t w_sz[11] = {
        (size_t)NL*LAT*DD, (size_t)NL*DD*LAT, (size_t)NL*DD*LAT,
        (size_t)NL*LAT*DD, (size_t)NL*DD*LAT, (size_t)NL*DD*LAT,
        (size_t)NL*RDIM*DD, (size_t)NL*DD*DD, (size_t)NL*FF*DD,
        (size_t)NL*DD*FF, (size_t)VV*DD };
    float* out = (float*)d_out;

    cudaFuncSetAttribute(gemm_mma<128>, cudaFuncAttributeMaxDynamicSharedMemorySize, SMEM128);
    cudaFuncSetAttribute(gemm_mma<64>,  cudaFuncAttributeMaxDynamicSharedMemorySize, SMEM64G);
    cudaFuncSetAttribute(attn_mma,      cudaFuncAttributeMaxDynamicSharedMemorySize, ATTSM);

    void* p;
    cudaGetSymbolAddress(&p, g_x);      float* x    = (float*)p;
    cudaGetSymbolAddress(&p, g_q);      float* qf   = (float*)p;
    cudaGetSymbolAddress(&p, g_qr);     float* qrf  = (float*)p;
    cudaGetSymbolAddress(&p, g_k);      float* kf   = (float*)p;
    cudaGetSymbolAddress(&p, g_v);      float* vf   = (float*)p;
    cudaGetSymbolAddress(&p, g_kr);     float* krf  = (float*)p;
    cudaGetSymbolAddress(&p, g_nx_hi);  bf16* nxh   = (bf16*)p;
    cudaGetSymbolAddress(&p, g_nx_lo);  bf16* nxl   = (bf16*)p;
    cudaGetSymbolAddress(&p, g_ql_hi);  bf16* qlh   = (bf16*)p;
    cudaGetSymbolAddress(&p, g_ql_lo);  bf16* qll   = (bf16*)p;
    cudaGetSymbolAddress(&p, g_ckv_hi); bf16* ckvh  = (bf16*)p;
    cudaGetSymbolAddress(&p, g_ckv_lo); bf16* ckvl  = (bf16*)p;
    cudaGetSymbolAddress(&p, g_att_hi); bf16* atth  = (bf16*)p;
    cudaGetSymbolAddress(&p, g_att_lo); bf16* attl  = (bf16*)p;
    cudaGetSymbolAddress(&p, g_tmp_hi); bf16* tmph  = (bf16*)p;
    cudaGetSymbolAddress(&p, g_tmp_lo); bf16* tmpl  = (bf16*)p;
    cudaGetSymbolAddress(&p, g_x_hi);   bf16* xh    = (bf16*)p;
    cudaGetSymbolAddress(&p, g_x_lo);   bf16* xl    = (bf16*)p;
    cudaGetSymbolAddress(&p, g_whi);    bf16* whi   = (bf16*)p;
    cudaGetSymbolAddress(&p, g_wlo);    bf16* wlo   = (bf16*)p;

    size_t off = 0;
    bf16* w_hi[11]; bf16* w_lo[11];
    for (int i = 0; i < 11; i++) {
        w_hi[i] = whi + off; w_lo[i] = wlo + off;
        cvt_split<<<2048, 256>>>(w_f32[i], w_hi[i], w_lo[i], (int)w_sz[i]);
        off += w_sz[i];
    }
    const bf16 *wqd_h = w_hi[0], *wqd_l = w_lo[0], *wqu_h = w_hi[1], *wqu_l = w_lo[1];
    const bf16 *wqr_h = w_hi[2], *wqr_l = w_lo[2], *wkd_h = w_hi[3], *wkd_l = w_lo[3];
    const bf16 *wku_h = w_hi[4], *wku_l = w_lo[4], *wvu_h = w_hi[5], *wvu_l = w_lo[5];
    const bf16 *wkr_h = w_hi[6], *wkr_l = w_lo[6], *wo_h  = w_hi[7], *wo_l  = w_lo[7];
    const bf16 *fc1_h = w_hi[8], *fc1_l = w_lo[8], *fc2_h = w_hi[9], *fc2_l = w_lo[9];
    const bf16 *lmh_h = w_hi[10], *lmh_l = w_lo[10];

    embed_kernel<<<TT, 256>>>(idx, wte, x);
    rmsnorm_kernel<<<TT, 256>>>(x, x, nullptr, nullptr);

    for (int l = 0; l < NL; l++) {
        size_t oD2 = (size_t)l * DD * DD, oLD = (size_t)l * LAT * DD;
        size_t oRD = (size_t)l * RDIM * DD, oF = (size_t)l * FF * DD;

        rmsnorm_kernel<<<TT, 256>>>(x, nullptr, nxh, nxl);

        gemm128(nxh, nxl, wqd_h + oLD, wqd_l + oLD, nullptr, nullptr, qlh, qll, TT, LAT, DD, 0);
        gemm128(qlh, qll, wqu_h + oLD, wqu_l + oLD, qf,  nullptr, nullptr, nullptr, TT, DD, LAT, 0);
        gemm128(qlh, qll, wqr_h + oLD, wqr_l + oLD, qrf, nullptr, nullptr, nullptr, TT, DD, LAT, 0);
        gemm128(nxh, nxl, wkd_h + oLD, wkd_l + oLD, nullptr, nullptr, ckvh, ckvl, TT, LAT, DD, 0);
        gemm128(ckvh, ckvl, wku_h + oLD, wku_l + oLD, kf, nullptr, nullptr, nullptr, TT, DD, LAT, 0);
        gemm128(ckvh, ckvl, wvu_h + oLD, wvu_l + oLD, vf, nullptr, nullptr, nullptr, TT, DD, LAT, 0);
        gemm64 (nxh, nxl, wkr_h + oRD, wkr_l + oRD, krf, TT, RDIM, DD);

        rope_kernel<<<dim3(TT, HN), 32>>>(qrf, HN);
        rope_kernel<<<dim3(TT, 1), 32>>>(krf, 1);

        attn_mma<<<dim3(8, 16), 256, ATTSM>>>(qf, qrf, kf, vf, krf, atth, attl);

        gemm128(atth, attl, wo_h + oD2, wo_l + oD2, x, x, nullptr, nullptr, TT, DD, DD, 0);

        rmsnorm_kernel<<<TT, 256>>>(x, nullptr, nxh, nxl);
        gemm128(nxh, nxl, fc1_h + oF, fc1_l + oF, nullptr, nullptr, tmph, tmpl, TT, FF, DD, 1);
        bool last = (l == NL - 1);
        gemm128(tmph, tmpl, fc2_h + oF, fc2_l + oF, x, x,
                last ? xh : nullptr, last ? xl : nullptr, TT, DD, FF, 0);
    }

    gemm128(xh, xl, lmh_h, lmh_l, out, nullptr, nullptr, nullptr, TT, VV, DD, 0);
}

// round 8
// speedup vs baseline: 9.3983x; 1.3607x over previous
#include <cuda_runtime.h>
#include <cuda_bf16.h>
#include <cstdint>
#include <math.h>

#define TT 1024
#define DD 1024
#define HN 16
#define HD 64
#define LAT 512
#define RDIM 64
#define NL 8
#define VV 32000
#define FF 4096

typedef __nv_bfloat16 bf16;

// ---- fused weight layout (bf16 hi/lo pair buffers) ---------------------------
// W1 [1088,1024]/layer: rows 0-511 wqdown, 512-1023 wkvdown, 1024-1087 wkr
// W2a [2048,512]/layer: rows 0-1023 wqup, 1024-2047 wqr
// W2b [2048,512]/layer: rows 0-1023 wkup, 1024-2047 wvup
#define W1SZ   (1088*1024)
#define W2SZ   (2048*512)
#define OFF_W1  0
#define OFF_W2A (OFF_W1  + NL*W1SZ)
#define OFF_W2B (OFF_W2A + NL*W2SZ)
#define OFF_WO  (OFF_W2B + NL*W2SZ)
#define OFF_FC1 (OFF_WO  + NL*DD*DD)
#define OFF_FC2 (OFF_FC1 + NL*FF*DD)
#define OFF_LMH (OFF_FC2 + NL*DD*FF)
#define TOTAL_W (OFF_LMH + VV*DD)

__device__ __align__(256) bf16 g_whi[TOTAL_W];
__device__ __align__(256) bf16 g_wlo[TOTAL_W];

// ---- activation scratch -------------------------------------------------------
__device__ __align__(256) float g_x  [TT*DD];
__device__ __align__(256) float g_c1 [TT*1088];     // ql | ckv | kr (float)
__device__ __align__(256) float g_qqr[TT*2048];     // q | qr
__device__ __align__(256) float g_kv [TT*2048];     // k | v
__device__ __align__(256) bf16 g_c1h[TT*1088], g_c1l[TT*1088];
__device__ __align__(256) bf16 g_nx_hi [TT*DD],  g_nx_lo [TT*DD];
__device__ __align__(256) bf16 g_att_hi[TT*DD],  g_att_lo[TT*DD];
__device__ __align__(256) bf16 g_tmp_hi[TT*FF],  g_tmp_lo[TT*FF];
__device__ __align__(256) bf16 g_x_hi  [TT*DD],  g_x_lo  [TT*DD];

// ---- helpers -----------------------------------------------------------------
__device__ __forceinline__ void split2(float x, bf16& h, bf16& l) {
    h = __float2bfloat16_rn(x);
    l = __float2bfloat16_rn(x - __bfloat162float(h));
}
__device__ __forceinline__ uint32_t packbf(bf16 a, bf16 b) {
    __nv_bfloat162 t = __halves2bfloat162(a, b);
    return *reinterpret_cast<uint32_t*>(&t);
}
__device__ __forceinline__ uint32_t splitpack(float x, float y, uint32_t& lo) {
    bf16 hx, lx, hy, ly;
    split2(x, hx, lx); split2(y, hy, ly);
    lo = packbf(lx, ly);
    return packbf(hx, hy);
}

__device__ __forceinline__ void cp16(uint32_t dst, const void* src) {
    asm volatile("cp.async.cg.shared.global [%0], [%1], 16;" :: "r"(dst), "l"(src));
}
#define CP_COMMIT() asm volatile("cp.async.commit_group;" ::: "memory")
#define CP_WAIT1()  asm volatile("cp.async.wait_group 1;" ::: "memory")
#define CP_WAIT0()  asm volatile("cp.async.wait_group 0;" ::: "memory")

__device__ __forceinline__ void mma16816(float* c, const uint32_t* a, const uint32_t* b) {
    asm volatile(
        "mma.sync.aligned.m16n8k16.row.col.f32.bf16.bf16.f32 "
        "{%0,%1,%2,%3}, {%4,%5,%6,%7}, {%8,%9}, {%0,%1,%2,%3};"
        : "+f"(c[0]), "+f"(c[1]), "+f"(c[2]), "+f"(c[3])
        : "r"(a[0]), "r"(a[1]), "r"(a[2]), "r"(a[3]), "r"(b[0]), "r"(b[1]));
}

__device__ __forceinline__ int sadr(int row, int w) {
    return row * 16 + (((w >> 2) ^ (row & 3)) << 2) + (w & 3);
}

// ---- strided split conversion (chunk = power of 2) ----------------------------
__global__ void cvt_split_s(const float* __restrict__ in, bf16* __restrict__ hi,
                            bf16* __restrict__ lo, int n, int cshift,
                            int dstride, int doff) {
    int i = (blockIdx.x * blockDim.x + threadIdx.x) * 8;
    int stride = gridDim.x * blockDim.x * 8;
    int cmask = (1 << cshift) - 1;
    for (; i < n; i += stride) {
        size_t di = (size_t)(i >> cshift) * dstride + doff + (i & cmask);
        float4 a = *(const float4*)(in + i);
        float4 b = *(const float4*)(in + i + 4);
        uint32_t h0,h1,h2,h3,l0,l1,l2,l3;
        h0 = splitpack(a.x, a.y, l0); h1 = splitpack(a.z, a.w, l1);
        h2 = splitpack(b.x, b.y, l2); h3 = splitpack(b.z, b.w, l3);
        *(uint4*)(hi + di) = make_uint4(h0, h1, h2, h3);
        *(uint4*)(lo + di) = make_uint4(l0, l1, l2, l3);
    }
}

// ---- embedding ----------------------------------------------------------------
__global__ void embed_kernel(const int* __restrict__ idx, const float* __restrict__ wte,
                             float* __restrict__ x) {
    int t = blockIdx.x;
    int row = idx[t];
    float4 v = *(const float4*)(wte + (size_t)row * DD + threadIdx.x * 4);
    *(float4*)(x + (size_t)t * DD + threadIdx.x * 4) = v;
}

// ---- rmsnorm ------------------------------------------------------------------
__global__ void rmsnorm_kernel(const float* __restrict__ in, float* __restrict__ out,
                               bf16* __restrict__ ohi, bf16* __restrict__ olo) {
    __shared__ float red[8];
    int row = blockIdx.x, tid = threadIdx.x;
    float4 v = *(const float4*)(in + (size_t)row * DD + tid * 4);
    float s = v.x*v.x + v.y*v.y + v.z*v.z + v.w*v.w;
    #pragma unroll
    for (int o = 16; o > 0; o >>= 1) s += __shfl_xor_sync(0xffffffff, s, o);
    if ((tid & 31) == 0) red[tid >> 5] = s;
    __syncthreads();
    if (tid < 8) {
        float t2 = red[tid];
        #pragma unroll
        for (int o = 4; o > 0; o >>= 1) t2 += __shfl_xor_sync(0xff, t2, o);
        if (tid == 0) red[0] = t2;
    }
    __syncthreads();
    float r = rsqrtf(red[0] / (float)DD + 1e-5f);
    float4 o4 = make_float4(v.x*r, v.y*r, v.z*r, v.w*r);
    if (out) *(float4*)(out + (size_t)row * DD + tid * 4) = o4;
    if (ohi) {
        size_t b = (size_t)row * DD + tid * 4;
        uint32_t lo0, lo1;
        uint32_t hi0 = splitpack(o4.x, o4.y, lo0);
        uint32_t hi1 = splitpack(o4.z, o4.w, lo1);
        *(uint2*)(ohi + b) = make_uint2(hi0, hi1);
        *(uint2*)(olo + b) = make_uint2(lo0, lo1);
    }
}

// ---- RoPE (row stride ld) -------------------------------------------------------
__global__ void rope_kernel(float* __restrict__ x, int ld, int nh) {
    int t = blockIdx.x, h = blockIdx.y, j = threadIdx.x;
    float f = powf(10000.f, -(float)j / 32.f);
    float sv, cv;
    sincosf((float)t * f, &sv, &cv);
    float* p = x + (size_t)t * ld + h * RDIM;
    float x0 = p[j], x1 = p[j + 32];
    p[j]      = x0 * cv - x1 * sv;
    p[j + 32] = x1 * cv + x0 * sv;
}

// ---- split-bf16 NT GEMM via mma.sync, templated BM/BN, strided A/C -------------
template<int BM, int BN>
__global__ void __launch_bounds__(256) gemm_mma(
    const bf16* __restrict__ Ahi, const bf16* __restrict__ Alo, int lda,
    const bf16* __restrict__ Bhi, const bf16* __restrict__ Blo,
    float* __restrict__ C, int ldc, const float* __restrict__ Rres,
    bf16* __restrict__ Chi, bf16* __restrict__ Clo,
    int K, int relu)
{
    extern __shared__ uint32_t smw[];
    constexpr int AT  = BM * 16;
    constexpr int BT  = BN * 16;
    constexpr int STG = 2 * AT + 2 * BT;
    constexpr int NT  = BN / 16;
    constexpr int MT  = BM / 64;

    int tid = threadIdx.x, lane = tid & 31, w = tid >> 5;
    int wm = w & 3, wn = w >> 2;
    int bm = blockIdx.y * BM, bn = blockIdx.x * BN;
    int la = lane & 3, lr = lane >> 2;

    uint32_t sbase = (uint32_t)__cvta_generic_to_shared(smw);

    auto load_stage = [&](int i, int st) {
        int k0 = i * 32;
        uint32_t so = sbase + (uint32_t)(st * STG) * 4;
        #pragma unroll
        for (int e0 = 0; e0 < BM * 4; e0 += 256) {
            int e = e0 + tid;
            int r = e >> 2, kq = e & 3;
            size_t g = (size_t)(bm + r) * lda + k0 + kq * 8;
            uint32_t d = so + (uint32_t)(r * 16 + ((kq ^ (r & 3)) << 2)) * 4;
            cp16(d, Ahi + g);
            cp16(d + AT * 4, Alo + g);
        }
        #pragma unroll
        for (int e0 = 0; e0 < BN * 4; e0 += 256) {
            int e = e0 + tid;
            int r = e >> 2, kq = e & 3;
            size_t g = (size_t)(bn + r) * K + k0 + kq * 8;
            uint32_t d = so + (uint32_t)(2 * AT + r * 16 + ((kq ^ (r & 3)) << 2)) * 4;
            cp16(d, Bhi + g);
            cp16(d + BT * 4, Blo + g);
        }
        CP_COMMIT();
    };

    float acc[MT][NT][4];
    #pragma unroll
    for (int mt = 0; mt < MT; mt++)
        #pragma unroll
        for (int nt = 0; nt < NT; nt++)
            #pragma unroll
            for (int c = 0; c < 4; c++) acc[mt][nt][c] = 0.f;

    int nk = K >> 5;
    load_stage(0, 0);
    for (int i = 0; i < nk; i++) {
        if (i + 1 < nk) { load_stage(i + 1, (i + 1) & 1); CP_WAIT1(); }
        else            { CP_WAIT0(); }
        __syncthreads();

        const uint32_t* Sa = smw + (i & 1) * STG;
        const uint32_t* Sb = Sa + 2 * AT;
        #pragma unroll
        for (int ks = 0; ks < 2; ks++) {
            int w0 = ks * 8 + la;
            uint32_t ah[MT][4], al[MT][4];
            #pragma unroll
            for (int mt = 0; mt < MT; mt++) {
                int r0 = wm * (BM / 4) + mt * 16 + lr;
                int i00 = sadr(r0, w0),     i10 = sadr(r0 + 8, w0);
                int i01 = sadr(r0, w0 + 4), i11 = sadr(r0 + 8, w0 + 4);
                ah[mt][0] = Sa[i00]; ah[mt][1] = Sa[i10];
                ah[mt][2] = Sa[i01]; ah[mt][3] = Sa[i11];
                al[mt][0] = Sa[AT + i00]; al[mt][1] = Sa[AT + i10];
                al[mt][2] = Sa[AT + i01]; al[mt][3] = Sa[AT + i11];
            }
            #pragma unroll
            for (int nt = 0; nt < NT; nt++) {
                int n0 = wn * (BN / 2) + nt * 8 + lr;
                int j0 = sadr(n0, w0), j1 = sadr(n0, w0 + 4);
                uint32_t bh[2] = { Sb[j0], Sb[j1] };
                uint32_t bl[2] = { Sb[BT + j0], Sb[BT + j1] };
                #pragma unroll
                for (int mt = 0; mt < MT; mt++) {
                    mma16816(acc[mt][nt], ah[mt], bh);
                    mma16816(acc[mt][nt], ah[mt], bl);
                    mma16816(acc[mt][nt], al[mt], bh);
                }
            }
        }
        __syncthreads();
    }

    #pragma unroll
    for (int mt = 0; mt < MT; mt++) {
        #pragma unroll
        for (int nt = 0; nt < NT; nt++) {
            int col = bn + wn * (BN / 2) + nt * 8 + la * 2;
            #pragma unroll
            for (int half = 0; half < 2; half++) {
                int row = bm + wm * (BM / 4) + mt * 16 + lr + half * 8;
                float v0 = acc[mt][nt][half * 2 + 0];
                float v1 = acc[mt][nt][half * 2 + 1];
                size_t base = (size_t)row * ldc + col;
                if (Rres) {
                    float2 rr = *(const float2*)(Rres + base);
                    v0 += rr.x; v1 += rr.y;
                }
                if (relu) { v0 = fmaxf(v0, 0.f); v1 = fmaxf(v1, 0.f); }
                if (C) *(float2*)(C + base) = make_float2(v0, v1);
                if (Chi) {
                    uint32_t lo;
                    uint32_t hi = splitpack(v0, v1, lo);
                    *(uint32_t*)(Chi + base) = hi;
                    *(uint32_t*)(Clo + base) = lo;
                }
            }
        }
    }
}

// ---- flash attention via mma.sync (strides for fused buffers) -------------------
#define QLD 2048
#define KRLD 1088
#define AQ 68
#define AV 36
#define ATTSM ((4*64*AQ + 2*64*AV) * 4 + 64*65*4 + (64+64+128+128) * 4)

__global__ void __launch_bounds__(256, 1) attn_mma(
    const float* __restrict__ q,  const float* __restrict__ qr,
    const float* __restrict__ k,  const float* __restrict__ v,
    const float* __restrict__ kr,
    bf16* __restrict__ atthi, bf16* __restrict__ attlo)
{
    extern __shared__ uint32_t sw[];
    uint32_t* Qh = sw;
    uint32_t* Ql = Qh + 64 * AQ;
    uint32_t* Kh = Ql + 64 * AQ;
    uint32_t* Kl = Kh + 64 * AQ;
    uint32_t* Vh = Kl + 64 * AQ;
    uint32_t* Vl = Vh + 64 * AV;
    float* Ob   = (float*)(Vl + 64 * AV);
    float* rowM = Ob + 64 * 65;
    float* rowL = rowM + 64;
    float* pm   = rowL + 64;
    float* ps   = pm + 128;

    int hh = blockIdx.y, tid = threadIdx.x;
    int lane = tid & 31, w = tid >> 5;
    int wm = w & 3, wn = w >> 2;
    int la = lane & 3, lr = lane >> 2;
    const float scale = rsqrtf(128.f);

    for (int half = 0; half < 2; half++) {
        int qt = half ? (15 - (int)blockIdx.x) : (int)blockIdx.x;

        for (int e = tid; e < 64 * 64; e += 256) {
            int r = e >> 6, wq = e & 63;
            int t = qt * 64 + r, d = wq * 2;
            const float* src = (d < 64) ? (q + (size_t)t * QLD + hh * 64 + d)
                                        : (qr + (size_t)t * QLD + hh * 64 + (d - 64));
            float2 f = *(const float2*)src;
            uint32_t lo;
            uint32_t hi = splitpack(f.x, f.y, lo);
            Qh[r * AQ + wq] = hi; Ql[r * AQ + wq] = lo;
        }
        if (tid < 64) { rowM[tid] = -1e30f; rowL[tid] = 0.f; }

        float oacc[8][4];
        #pragma unroll
        for (int nt = 0; nt < 8; nt++)
            #pragma unroll
            for (int c = 0; c < 4; c++) oacc[nt][c] = 0.f;

        int rloc = wm * 16 + lr;

        for (int kt = 0; kt <= qt; kt++) {
            __syncthreads();

            for (int e = tid; e < 64 * 64; e += 256) {
                int r = e >> 6, wq = e & 63;
                int t = kt * 64 + r, d = wq * 2;
                const float* src = (d < 64) ? (k + (size_t)t * QLD + hh * 64 + d)
                                            : (kr + (size_t)t * KRLD + (d - 64));
                float2 f = *(const float2*)src;
                uint32_t lo;
                uint32_t hi = splitpack(f.x, f.y, lo);
                Kh[r * AQ + wq] = hi; Kl[r * AQ + wq] = lo;
            }
            for (int e = tid; e < 64 * 32; e += 256) {
                int kp = e >> 6, d = e & 63;
                float v0 = v[(size_t)(kt * 64 + 2 * kp) * QLD + hh * 64 + d];
                float v1 = v[(size_t)(kt * 64 + 2 * kp + 1) * QLD + hh * 64 + d];
                uint32_t lo;
                uint32_t hi = splitpack(v0, v1, lo);
                Vh[d * AV + kp] = hi; Vl[d * AV + kp] = lo;
            }
            __syncthreads();

            float sacc[4][4];
            #pragma unroll
            for (int nt = 0; nt < 4; nt++)
                #pragma unroll
                for (int c = 0; c < 4; c++) sacc[nt][c] = 0.f;

            #pragma unroll
            for (int kk = 0; kk < 8; kk++) {
                int w0 = kk * 8 + la;
                uint32_t ah[4], al2[4];
                ah[0] = Qh[rloc * AQ + w0];        ah[1] = Qh[(rloc + 8) * AQ + w0];
                ah[2] = Qh[rloc * AQ + w0 + 4];    ah[3] = Qh[(rloc + 8) * AQ + w0 + 4];
                al2[0] = Ql[rloc * AQ + w0];       al2[1] = Ql[(rloc + 8) * AQ + w0];
                al2[2] = Ql[rloc * AQ + w0 + 4];   al2[3] = Ql[(rloc + 8) * AQ + w0 + 4];
                #pragma unroll
                for (int nt = 0; nt < 4; nt++) {
                    int n0 = wn * 32 + nt * 8 + lr;
                    uint32_t bh[2] = { Kh[n0 * AQ + w0], Kh[n0 * AQ + w0 + 4] };
                    uint32_t bl[2] = { Kl[n0 * AQ + w0], Kl[n0 * AQ + w0 + 4] };
                    mma16816(sacc[nt], ah, bh);
                    mma16816(sacc[nt], ah, bl);
                    mma16816(sacc[nt], al2, bh);
                }
            }

            int rgA = qt * 64 + rloc, rgB = rgA + 8;
            #pragma unroll
            for (int nt = 0; nt < 4; nt++) {
                int cg = kt * 64 + wn * 32 + nt * 8 + 2 * la;
                sacc[nt][0] = (cg     <= rgA) ? sacc[nt][0] * scale : -1e30f;
                sacc[nt][1] = (cg + 1 <= rgA) ? sacc[nt][1] * scale : -1e30f;
                sacc[nt][2] = (cg     <= rgB) ? sacc[nt][2] * scale : -1e30f;
                sacc[nt][3] = (cg + 1 <= rgB) ? sacc[nt][3] * scale : -1e30f;
            }

            float mA = -1e30f, mB = -1e30f;
            #pragma unroll
            for (int nt = 0; nt < 4; nt++) {
                mA = fmaxf(mA, fmaxf(sacc[nt][0], sacc[nt][1]));
                mB = fmaxf(mB, fmaxf(sacc[nt][2], sacc[nt][3]));
            }
            mA = fmaxf(mA, __shfl_xor_sync(0xffffffff, mA, 1));
            mA = fmaxf(mA, __shfl_xor_sync(0xffffffff, mA, 2));
            mB = fmaxf(mB, __shfl_xor_sync(0xffffffff, mB, 1));
            mB = fmaxf(mB, __shfl_xor_sync(0xffffffff, mB, 2));
            if (la == 0) { pm[wn * 64 + rloc] = mA; pm[wn * 64 + rloc + 8] = mB; }
            __syncthreads();

            float moA = rowM[rloc], moB = rowM[rloc + 8];
            float mnA = fmaxf(moA, fmaxf(pm[rloc], pm[64 + rloc]));
            float mnB = fmaxf(moB, fmaxf(pm[rloc + 8], pm[64 + rloc + 8]));
            float alA = __expf(moA - mnA), alB = __expf(moB - mnB);

            float sA = 0.f, sB = 0.f;
            #pragma unroll
            for (int nt = 0; nt < 4; nt++) {
                sacc[nt][0] = __expf(sacc[nt][0] - mnA);
                sacc[nt][1] = __expf(sacc[nt][1] - mnA);
                sacc[nt][2] = __expf(sacc[nt][2] - mnB);
                sacc[nt][3] = __expf(sacc[nt][3] - mnB);
                sA += sacc[nt][0] + sacc[nt][1];
                sB += sacc[nt][2] + sacc[nt][3];
            }
            #pragma unroll
            for (int nt = 0; nt < 8; nt++) {
                oacc[nt][0] *= alA; oacc[nt][1] *= alA;
                oacc[nt][2] *= alB; oacc[nt][3] *= alB;
            }
            sA += __shfl_xor_sync(0xffffffff, sA, 1);
            sA += __shfl_xor_sync(0xffffffff, sA, 2);
            sB += __shfl_xor_sync(0xffffffff, sB, 1);
            sB += __shfl_xor_sync(0xffffffff, sB, 2);
            __syncthreads();
            if (la == 0) { ps[wn * 64 + rloc] = sA; ps[wn * 64 + rloc + 8] = sB; }
            if (wn == 0 && la == 0) { rowM[rloc] = mnA; rowM[rloc + 8] = mnB; }
            __syncthreads();
            if (wn == 0 && la == 0) {
                rowL[rloc]     = rowL[rloc]     * alA + ps[rloc]     + ps[64 + rloc];
                rowL[rloc + 8] = rowL[rloc + 8] * alB + ps[rloc + 8] + ps[64 + rloc + 8];
            }

            #pragma unroll
            for (int kc = 0; kc < 2; kc++) {
                uint32_t phi[4], plo[4];
                phi[0] = splitpack(sacc[2*kc][0],   sacc[2*kc][1],   plo[0]);
                phi[1] = splitpack(sacc[2*kc][2],   sacc[2*kc][3],   plo[1]);
                phi[2] = splitpack(sacc[2*kc+1][0], sacc[2*kc+1][1], plo[2]);
                phi[3] = splitpack(sacc[2*kc+1][2], sacc[2*kc+1][3], plo[3]);
                int kw = wn * 16 + kc * 8 + la;
                #pragma unroll
                for (int nt = 0; nt < 8; nt++) {
                    int d0 = nt * 8 + lr;
                    uint32_t bh[2] = { Vh[d0 * AV + kw], Vh[d0 * AV + kw + 4] };
                    uint32_t bl[2] = { Vl[d0 * AV + kw], Vl[d0 * AV + kw + 4] };
                    mma16816(oacc[nt], phi, bh);
                    mma16816(oacc[nt], phi, bl);
                    mma16816(oacc[nt], plo, bh);
                }
            }
        }

        __syncthreads();
        if (wn == 0) {
            #pragma unroll
            for (int nt = 0; nt < 8; nt++) {
                int c0 = nt * 8 + 2 * la;
                Ob[rloc * 65 + c0]         = oacc[nt][0];
                Ob[rloc * 65 + c0 + 1]     = oacc[nt][1];
                Ob[(rloc+8) * 65 + c0]     = oacc[nt][2];
                Ob[(rloc+8) * 65 + c0 + 1] = oacc[nt][3];
            }
        }
        __syncthreads();
        if (wn == 1) {
            #pragma unroll
            for (int nt = 0; nt < 8; nt++) {
                int c0 = nt * 8 + 2 * la;
                Ob[rloc * 65 + c0]         += oacc[nt][0];
                Ob[rloc * 65 + c0 + 1]     += oacc[nt][1];
                Ob[(rloc+8) * 65 + c0]     += oacc[nt][2];
                Ob[(rloc+8) * 65 + c0 + 1] += oacc[nt][3];
            }
        }
        __syncthreads();
        for (int e = tid; e < 64 * 64; e += 256) {
            int r = e >> 6, d = e & 63;
            float val = Ob[r * 65 + d] / rowL[r];
            bf16 vh, vl;
            split2(val, vh, vl);
            size_t o = (size_t)(qt * 64 + r) * DD + hh * 64 + d;
            atthi[o] = vh; attlo[o] = vl;
        }
        __syncthreads();
    }
}

// ---- host orchestration ----------------------------------------------------------
#define SMEMSZ(BM,BN) ((BM + BN) * 256)

template<int BM, int BN>
static void gemmT(const bf16* Ah, const bf16* Al, int lda,
                  const bf16* Bh, const bf16* Bl,
                  float* C, int ldc, const float* R, bf16* Ch, bf16* Cl,
                  int M, int N, int K, int relu) {
    dim3 grid(N / BN, M / BM);
    gemm_mma<BM, BN><<<grid, 256, SMEMSZ(BM, BN)>>>(Ah, Al, lda, Bh, Bl, C, ldc, R, Ch, Cl, K, relu);
}

extern "C" void kernel_launch(void* const* d_in, const int* in_sizes, int n_in,
                              void* d_out, int out_size) {
    const int*   idx     = (const int*)  d_in[0];
    const float* wte     = (const float*)d_in[1];
    const float* wqdown  = (const float*)d_in[2];
    const float* wqup    = (const float*)d_in[3];
    const float* wqr     = (const float*)d_in[4];
    const float* wkvdown = (const float*)d_in[5];
    const float* wkup    = (const float*)d_in[6];
    const float* wvup    = (const float*)d_in[7];
    const float* wkr     = (const float*)d_in[8];
    const float* wo      = (const float*)d_in[9];
    const float* fc1     = (const float*)d_in[10];
    const float* fc2     = (const float*)d_in[11];
    const float* lm_head = (const float*)d_in[12];
    float* out = (float*)d_out;

    cudaFuncSetAttribute((void*)gemm_mma<128,128>, cudaFuncAttributeMaxDynamicSharedMemorySize, SMEMSZ(128,128));
    cudaFuncSetAttribute((void*)gemm_mma<128,64>,  cudaFuncAttributeMaxDynamicSharedMemorySize, SMEMSZ(128,64));
    cudaFuncSetAttribute((void*)gemm_mma<64,128>,  cudaFuncAttributeMaxDynamicSharedMemorySize, SMEMSZ(64,128));
    cudaFuncSetAttribute((void*)attn_mma,          cudaFuncAttributeMaxDynamicSharedMemorySize, ATTSM);

    void* p;
    cudaGetSymbolAddress(&p, g_x);      float* x    = (float*)p;
    cudaGetSymbolAddress(&p, g_c1);     float* c1f  = (float*)p;
    cudaGetSymbolAddress(&p, g_qqr);    float* qqr  = (float*)p;
    cudaGetSymbolAddress(&p, g_kv);     float* kv   = (float*)p;
    cudaGetSymbolAddress(&p, g_c1h);    bf16* c1h   = (bf16*)p;
    cudaGetSymbolAddress(&p, g_c1l);    bf16* c1l   = (bf16*)p;
    cudaGetSymbolAddress(&p, g_nx_hi);  bf16* nxh   = (bf16*)p;
    cudaGetSymbolAddress(&p, g_nx_lo);  bf16* nxl   = (bf16*)p;
    cudaGetSymbolAddress(&p, g_att_hi); bf16* atth  = (bf16*)p;
    cudaGetSymbolAddress(&p, g_att_lo); bf16* attl  = (bf16*)p;
    cudaGetSymbolAddress(&p, g_tmp_hi); bf16* tmph  = (bf16*)p;
    cudaGetSymbolAddress(&p, g_tmp_lo); bf16* tmpl  = (bf16*)p;
    cudaGetSymbolAddress(&p, g_x_hi);   bf16* xh    = (bf16*)p;
    cudaGetSymbolAddress(&p, g_x_lo);   bf16* xl    = (bf16*)p;
    cudaGetSymbolAddress(&p, g_whi);    bf16* whi   = (bf16*)p;
    cudaGetSymbolAddress(&p, g_wlo);    bf16* wlo   = (bf16*)p;

    // ---- build fused weight layout (strided split conversions) ----
    // W1: wqdown -> rows 0-511, wkvdown -> 512-1023, wkr -> 1024-1087 per layer
    cvt_split_s<<<2048,256>>>(wqdown,  whi+OFF_W1, wlo+OFF_W1, NL*512*1024, 19, W1SZ, 0);
    cvt_split_s<<<2048,256>>>(wkvdown, whi+OFF_W1, wlo+OFF_W1, NL*512*1024, 19, W1SZ, 512*1024);
    cvt_split_s<<<2048,256>>>(wkr,     whi+OFF_W1, wlo+OFF_W1, NL*64*1024,  16, W1SZ, 1024*1024);
    // W2a: wqup rows 0-1023, wqr rows 1024-2047 per layer (K=512)
    cvt_split_s<<<2048,256>>>(wqup, whi+OFF_W2A, wlo+OFF_W2A, NL*1024*512, 19, W2SZ, 0);
    cvt_split_s<<<2048,256>>>(wqr,  whi+OFF_W2A, wlo+OFF_W2A, NL*1024*512, 19, W2SZ, 1024*512);
    // W2b: wkup, wvup
    cvt_split_s<<<2048,256>>>(wkup, whi+OFF_W2B, wlo+OFF_W2B, NL*1024*512, 19, W2SZ, 0);
    cvt_split_s<<<2048,256>>>(wvup, whi+OFF_W2B, wlo+OFF_W2B, NL*1024*512, 19, W2SZ, 1024*512);
    // flat: wo, fc1, fc2, lm_head
    cvt_split_s<<<2048,256>>>(wo,      whi+OFF_WO,  wlo+OFF_WO,  NL*DD*DD, 20, DD*DD, 0);
    cvt_split_s<<<2048,256>>>(fc1,     whi+OFF_FC1, wlo+OFF_FC1, NL*FF*DD, 22, FF*DD, 0);
    cvt_split_s<<<2048,256>>>(fc2,     whi+OFF_FC2, wlo+OFF_FC2, NL*DD*FF, 22, DD*FF, 0);
    cvt_split_s<<<2048,256>>>(lm_head, whi+OFF_LMH, wlo+OFF_LMH, VV*DD,    30, VV*DD, 0);

    embed_kernel<<<TT, 256>>>(idx, wte, x);
    rmsnorm_kernel<<<TT, 256>>>(x, x, nullptr, nullptr);

    for (int l = 0; l < NL; l++) {
        const bf16* w1h  = whi + OFF_W1  + (size_t)l * W1SZ;
        const bf16* w1l  = wlo + OFF_W1  + (size_t)l * W1SZ;
        const bf16* w2ah = whi + OFF_W2A + (size_t)l * W2SZ;
        const bf16* w2al = wlo + OFF_W2A + (size_t)l * W2SZ;
        const bf16* w2bh = whi + OFF_W2B + (size_t)l * W2SZ;
        const bf16* w2bl = wlo + OFF_W2B + (size_t)l * W2SZ;
        const bf16* woh  = whi + OFF_WO  + (size_t)l * DD*DD;
        const bf16* wol  = wlo + OFF_WO  + (size_t)l * DD*DD;
        const bf16* f1h  = whi + OFF_FC1 + (size_t)l * FF*DD;
        const bf16* f1l  = wlo + OFF_FC1 + (size_t)l * FF*DD;
        const bf16* f2h  = whi + OFF_FC2 + (size_t)l * DD*FF;
        const bf16* f2l  = wlo + OFF_FC2 + (size_t)l * DD*FF;

        rmsnorm_kernel<<<TT, 256>>>(x, nullptr, nxh, nxl);

        // C1 = nx @ W1^T : [1024,1088] (ql | ckv | kr)
        gemmT<128,64>(nxh, nxl, DD, w1h, w1l, c1f, 1088, nullptr, c1h, c1l, TT, 1088, DD, 0);
        // QQR = ql @ [wqup;wqr]^T : [1024,2048]
        gemmT<128,128>(c1h, c1l, 1088, w2ah, w2al, qqr, 2048, nullptr, nullptr, nullptr, TT, 2048, LAT, 0);
        // KV = ckv @ [wkup;wvup]^T
        gemmT<128,128>(c1h + 512, c1l + 512, 1088, w2bh, w2bl, kv, 2048, nullptr, nullptr, nullptr, TT, 2048, LAT, 0);

        rope_kernel<<<dim3(TT, HN), 32>>>(qqr + 1024, 2048, HN);
        rope_kernel<<<dim3(TT, 1), 32>>>(c1f + 1024, 1088, 1);

        attn_mma<<<dim3(8, 16), 256, ATTSM>>>(qqr, qqr + 1024, kv, kv + 1024, c1f + 1024, atth, attl);

        gemmT<64,128>(atth, attl, DD, woh, wol, x, DD, x, nullptr, nullptr, TT, DD, DD, 0);

        rmsnorm_kernel<<<TT, 256>>>(x, nullptr, nxh, nxl);
        gemmT<128,128>(nxh, nxl, DD, f1h, f1l, nullptr, FF, nullptr, tmph, tmpl, TT, FF, DD, 1);
        bool last = (l == NL - 1);
        gemmT<64,128>(tmph, tmpl, FF, f2h, f2l, x, DD, x,
                      last ? xh : nullptr, last ? xl : nullptr, TT, DD, FF, 0);
    }

    gemmT<128,128>(xh, xl, DD, whi + OFF_LMH, wlo + OFF_LMH, out, VV, nullptr, nullptr, nullptr, TT, VV, DD, 0);
}

// round 9
// speedup vs baseline: 12.6497x; 1.3459x over previous
#include <cuda_runtime.h>
#include <cuda_fp16.h>
#include <cstdint>
#include <math.h>

#define TT 1024
#define DD 1024
#define HN 16
#define HD 64
#define LAT 512
#define RDIM 64
#define NL 8
#define VV 32000
#define FF 4096

typedef __half h16;

// ---- fused weight layout (single fp16 buffer; weights are always B operand) ---
#define W1SZ   (1088*1024)
#define W2SZ   (2048*512)
#define OFF_W1  0
#define OFF_W2A (OFF_W1  + NL*W1SZ)
#define OFF_W2B (OFF_W2A + NL*W2SZ)
#define OFF_WO  (OFF_W2B + NL*W2SZ)
#define OFF_FC1 (OFF_WO  + NL*DD*DD)
#define OFF_FC2 (OFF_FC1 + NL*FF*DD)
#define OFF_LMH (OFF_FC2 + NL*DD*FF)
#define TOTAL_W (OFF_LMH + VV*DD)

__device__ __align__(256) h16 g_wh[TOTAL_W];

// ---- activation scratch (A-side operands carry hi/lo fp16 split) --------------
__device__ __align__(256) float g_x  [TT*DD];
__device__ __align__(256) float g_c1 [TT*1088];     // ql | ckv | kr (float)
__device__ __align__(256) float g_qqr[TT*2048];     // q | qr
__device__ __align__(256) float g_kv [TT*2048];     // k | v
__device__ __align__(256) h16 g_c1h[TT*1088], g_c1l[TT*1088];
__device__ __align__(256) h16 g_nx_hi [TT*DD],  g_nx_lo [TT*DD];
__device__ __align__(256) h16 g_att_hi[TT*DD],  g_att_lo[TT*DD];
__device__ __align__(256) h16 g_tmp_hi[TT*FF],  g_tmp_lo[TT*FF];
__device__ __align__(256) h16 g_x_hi  [TT*DD],  g_x_lo  [TT*DD];

// ---- helpers -----------------------------------------------------------------
__device__ __forceinline__ uint32_t packh(h16 a, h16 b) {
    __half2 t = __halves2half2(a, b);
    return *reinterpret_cast<uint32_t*>(&t);
}
__device__ __forceinline__ uint32_t pack2h(float x, float y) {
    __half2 t = __floats2half2_rn(x, y);
    return *reinterpret_cast<uint32_t*>(&t);
}
__device__ __forceinline__ uint32_t splitpackh(float x, float y, uint32_t& lo) {
    h16 hx = __float2half_rn(x), hy = __float2half_rn(y);
    h16 lx = __float2half_rn(x - __half2float(hx));
    h16 ly = __float2half_rn(y - __half2float(hy));
    lo = packh(lx, ly);
    return packh(hx, hy);
}

__device__ __forceinline__ void cp16(uint32_t dst, const void* src) {
    asm volatile("cp.async.cg.shared.global [%0], [%1], 16;" :: "r"(dst), "l"(src));
}
#define CP_COMMIT() asm volatile("cp.async.commit_group;" ::: "memory")
#define CP_WAIT1()  asm volatile("cp.async.wait_group 1;" ::: "memory")
#define CP_WAIT0()  asm volatile("cp.async.wait_group 0;" ::: "memory")

__device__ __forceinline__ void mma16816(float* c, const uint32_t* a, const uint32_t* b) {
    asm volatile(
        "mma.sync.aligned.m16n8k16.row.col.f32.f16.f16.f32 "
        "{%0,%1,%2,%3}, {%4,%5,%6,%7}, {%8,%9}, {%0,%1,%2,%3};"
        : "+f"(c[0]), "+f"(c[1]), "+f"(c[2]), "+f"(c[3])
        : "r"(a[0]), "r"(a[1]), "r"(a[2]), "r"(a[3]), "r"(b[0]), "r"(b[1]));
}

__device__ __forceinline__ int sadr(int row, int w) {
    return row * 16 + (((w >> 2) ^ (row & 3)) << 2) + (w & 3);
}

// ---- strided weight conversion (single fp16 output) ----------------------------
__global__ void cvt_h_s(const float* __restrict__ in, h16* __restrict__ hi,
                        int n, int cshift, int dstride, int doff) {
    int i = (blockIdx.x * blockDim.x + threadIdx.x) * 8;
    int stride = gridDim.x * blockDim.x * 8;
    int cmask = (1 << cshift) - 1;
    for (; i < n; i += stride) {
        size_t di = (size_t)(i >> cshift) * dstride + doff + (i & cmask);
        float4 a = *(const float4*)(in + i);
        float4 b = *(const float4*)(in + i + 4);
        *(uint4*)(hi + di) = make_uint4(pack2h(a.x, a.y), pack2h(a.z, a.w),
                                        pack2h(b.x, b.y), pack2h(b.z, b.w));
    }
}

// ---- embedding ------------------------------------------------------------------
__global__ void embed_kernel(const int* __restrict__ idx, const float* __restrict__ wte,
                             float* __restrict__ x) {
    int t = blockIdx.x;
    int row = idx[t];
    float4 v = *(const float4*)(wte + (size_t)row * DD + threadIdx.x * 4);
    *(float4*)(x + (size_t)t * DD + threadIdx.x * 4) = v;
}

// ---- rmsnorm ----------------------------------------------------------------------
__global__ void rmsnorm_kernel(const float* __restrict__ in, float* __restrict__ out,
                               h16* __restrict__ ohi, h16* __restrict__ olo) {
    __shared__ float red[8];
    int row = blockIdx.x, tid = threadIdx.x;
    float4 v = *(const float4*)(in + (size_t)row * DD + tid * 4);
    float s = v.x*v.x + v.y*v.y + v.z*v.z + v.w*v.w;
    #pragma unroll
    for (int o = 16; o > 0; o >>= 1) s += __shfl_xor_sync(0xffffffff, s, o);
    if ((tid & 31) == 0) red[tid >> 5] = s;
    __syncthreads();
    if (tid < 8) {
        float t2 = red[tid];
        #pragma unroll
        for (int o = 4; o > 0; o >>= 1) t2 += __shfl_xor_sync(0xff, t2, o);
        if (tid == 0) red[0] = t2;
    }
    __syncthreads();
    float r = rsqrtf(red[0] / (float)DD + 1e-5f);
    float4 o4 = make_float4(v.x*r, v.y*r, v.z*r, v.w*r);
    if (out) *(float4*)(out + (size_t)row * DD + tid * 4) = o4;
    if (ohi) {
        size_t b = (size_t)row * DD + tid * 4;
        uint32_t lo0, lo1;
        uint32_t hi0 = splitpackh(o4.x, o4.y, lo0);
        uint32_t hi1 = splitpackh(o4.z, o4.w, lo1);
        *(uint2*)(ohi + b) = make_uint2(hi0, hi1);
        *(uint2*)(olo + b) = make_uint2(lo0, lo1);
    }
}

// ---- RoPE (fused qr + kr: blockIdx.y==16 -> kr) --------------------------------------
__global__ void rope_kernel(float* __restrict__ qqr, float* __restrict__ c1) {
    int t = blockIdx.x, h = blockIdx.y, j = threadIdx.x;
    float f = powf(10000.f, -(float)j / 32.f);
    float sv, cv;
    sincosf((float)t * f, &sv, &cv);
    float* p = (h < 16) ? (qqr + (size_t)t * 2048 + 1024 + h * RDIM)
                        : (c1 + (size_t)t * 1088 + 1024);
    float x0 = p[j], x1 = p[j + 32];
    p[j]      = x0 * cv - x1 * sv;
    p[j + 32] = x1 * cv + x0 * sv;
}

// ---- fp16 2-pass NT GEMM via mma.sync: C = (Ahi+Alo) * B^T ---------------------------
template<int BM, int BN>
__global__ void __launch_bounds__(256) gemm_mma(
    const h16* __restrict__ Ahi, const h16* __restrict__ Alo, int lda,
    const h16* __restrict__ Bh,
    float* __restrict__ C, int ldc, const float* __restrict__ Rres,
    h16* __restrict__ Chi, h16* __restrict__ Clo,
    int K, int relu)
{
    extern __shared__ uint32_t smw[];
    constexpr int AT  = BM * 16;
    constexpr int BT  = BN * 16;
    constexpr int STG = 2 * AT + BT;
    constexpr int NT  = BN / 16;
    constexpr int MT  = BM / 64;

    int tid = threadIdx.x, lane = tid & 31, w = tid >> 5;
    int wm = w & 3, wn = w >> 2;
    int bm = blockIdx.y * BM, bn = blockIdx.x * BN;
    int la = lane & 3, lr = lane >> 2;

    uint32_t sbase = (uint32_t)__cvta_generic_to_shared(smw);

    auto load_stage = [&](int i, int st) {
        int k0 = i * 32;
        uint32_t so = sbase + (uint32_t)(st * STG) * 4;
        #pragma unroll
        for (int e0 = 0; e0 < BM * 4; e0 += 256) {
            int e = e0 + tid;
            int r = e >> 2, kq = e & 3;
            size_t g = (size_t)(bm + r) * lda + k0 + kq * 8;
            uint32_t d = so + (uint32_t)(r * 16 + ((kq ^ (r & 3)) << 2)) * 4;
            cp16(d, Ahi + g);
            cp16(d + AT * 4, Alo + g);
        }
        #pragma unroll
        for (int e0 = 0; e0 < BN * 4; e0 += 256) {
            int e = e0 + tid;
            int r = e >> 2, kq = e & 3;
            size_t g = (size_t)(bn + r) * K + k0 + kq * 8;
            uint32_t d = so + (uint32_t)(2 * AT + r * 16 + ((kq ^ (r & 3)) << 2)) * 4;
            cp16(d, Bh + g);
        }
        CP_COMMIT();
    };

    float acc[MT][NT][4];
    #pragma unroll
    for (int mt = 0; mt < MT; mt++)
        #pragma unroll
        for (int nt = 0; nt < NT; nt++)
            #pragma unroll
            for (int c = 0; c < 4; c++) acc[mt][nt][c] = 0.f;

    int nk = K >> 5;
    load_stage(0, 0);
    for (int i = 0; i < nk; i++) {
        if (i + 1 < nk) { load_stage(i + 1, (i + 1) & 1); CP_WAIT1(); }
        else            { CP_WAIT0(); }
        __syncthreads();

        const uint32_t* Sa = smw + (i & 1) * STG;
        const uint32_t* Sb = Sa + 2 * AT;
        #pragma unroll
        for (int ks = 0; ks < 2; ks++) {
            int w0 = ks * 8 + la;
            uint32_t ah[MT][4], al[MT][4];
            #pragma unroll
            for (int mt = 0; mt < MT; mt++) {
                int r0 = wm * (BM / 4) + mt * 16 + lr;
                int i00 = sadr(r0, w0),     i10 = sadr(r0 + 8, w0);
                int i01 = sadr(r0, w0 + 4), i11 = sadr(r0 + 8, w0 + 4);
                ah[mt][0] = Sa[i00]; ah[mt][1] = Sa[i10];
                ah[mt][2] = Sa[i01]; ah[mt][3] = Sa[i11];
                al[mt][0] = Sa[AT + i00]; al[mt][1] = Sa[AT + i10];
                al[mt][2] = Sa[AT + i01]; al[mt][3] = Sa[AT + i11];
            }
            #pragma unroll
            for (int nt = 0; nt < NT; nt++) {
                int n0 = wn * (BN / 2) + nt * 8 + lr;
                int j0 = sadr(n0, w0), j1 = sadr(n0, w0 + 4);
                uint32_t bh[2] = { Sb[j0], Sb[j1] };
                #pragma unroll
                for (int mt = 0; mt < MT; mt++) {
                    mma16816(acc[mt][nt], ah[mt], bh);
                    mma16816(acc[mt][nt], al[mt], bh);
                }
            }
        }
        __syncthreads();
    }

    #pragma unroll
    for (int mt = 0; mt < MT; mt++) {
        #pragma unroll
        for (int nt = 0; nt < NT; nt++) {
            int col = bn + wn * (BN / 2) + nt * 8 + la * 2;
            #pragma unroll
            for (int half = 0; half < 2; half++) {
                int row = bm + wm * (BM / 4) + mt * 16 + lr + half * 8;
                float v0 = acc[mt][nt][half * 2 + 0];
                float v1 = acc[mt][nt][half * 2 + 1];
                size_t base = (size_t)row * ldc + col;
                if (Rres) {
                    float2 rr = *(const float2*)(Rres + base);
                    v0 += rr.x; v1 += rr.y;
                }
                if (relu) { v0 = fmaxf(v0, 0.f); v1 = fmaxf(v1, 0.f); }
                if (C) *(float2*)(C + base) = make_float2(v0, v1);
                if (Chi) {
                    uint32_t lo;
                    uint32_t hi = splitpackh(v0, v1, lo);
                    *(uint32_t*)(Chi + base) = hi;
                    *(uint32_t*)(Clo + base) = lo;
                }
            }
        }
    }
}

// ---- flash attention, fp16 2-pass (Q split, K/V/P plain) -----------------------------
#define QLD 2048
#define KRLD 1088
#define AQ 68
#define AV 36
#define ATTSM ((3*64*AQ + 64*AV) * 4 + 64*65*4 + (64+64+128+128) * 4)

__global__ void __launch_bounds__(256, 1) attn_mma(
    const float* __restrict__ q,  const float* __restrict__ qr,
    const float* __restrict__ k,  const float* __restrict__ v,
    const float* __restrict__ kr,
    h16* __restrict__ atthi, h16* __restrict__ attlo)
{
    extern __shared__ uint32_t sw[];
    uint32_t* Qh = sw;
    uint32_t* Ql = Qh + 64 * AQ;
    uint32_t* Kh = Ql + 64 * AQ;
    uint32_t* Vh = Kh + 64 * AQ;
    float* Ob   = (float*)(Vh + 64 * AV);
    float* rowM = Ob + 64 * 65;
    float* rowL = rowM + 64;
    float* pm   = rowL + 64;
    float* ps   = pm + 128;

    int hh = blockIdx.y, tid = threadIdx.x;
    int lane = tid & 31, w = tid >> 5;
    int wm = w & 3, wn = w >> 2;
    int la = lane & 3, lr = lane >> 2;
    const float scale = rsqrtf(128.f);

    for (int half = 0; half < 2; half++) {
        int qt = half ? (15 - (int)blockIdx.x) : (int)blockIdx.x;

        for (int e = tid; e < 64 * 64; e += 256) {
            int r = e >> 6, wq = e & 63;
            int t = qt * 64 + r, d = wq * 2;
            const float* src = (d < 64) ? (q + (size_t)t * QLD + hh * 64 + d)
                                        : (qr + (size_t)t * QLD + hh * 64 + (d - 64));
            float2 f = *(const float2*)src;
            uint32_t lo;
            uint32_t hi = splitpackh(f.x, f.y, lo);
            Qh[r * AQ + wq] = hi; Ql[r * AQ + wq] = lo;
        }
        if (tid < 64) { rowM[tid] = -1e30f; rowL[tid] = 0.f; }

        float oacc[8][4];
        #pragma unroll
        for (int nt = 0; nt < 8; nt++)
            #pragma unroll
            for (int c = 0; c < 4; c++) oacc[nt][c] = 0.f;

        int rloc = wm * 16 + lr;

        for (int kt = 0; kt <= qt; kt++) {
            __syncthreads();

            for (int e = tid; e < 64 * 64; e += 256) {
                int r = e >> 6, wq = e & 63;
                int t = kt * 64 + r, d = wq * 2;
                const float* src = (d < 64) ? (k + (size_t)t * QLD + hh * 64 + d)
                                            : (kr + (size_t)t * KRLD + (d - 64));
                float2 f = *(const float2*)src;
                Kh[r * AQ + wq] = pack2h(f.x, f.y);
            }
            for (int e = tid; e < 64 * 32; e += 256) {
                int kp = e >> 6, d = e & 63;
                float v0 = v[(size_t)(kt * 64 + 2 * kp) * QLD + hh * 64 + d];
                float v1 = v[(size_t)(kt * 64 + 2 * kp + 1) * QLD + hh * 64 + d];
                Vh[d * AV + kp] = pack2h(v0, v1);
            }
            __syncthreads();

            float sacc[4][4];
            #pragma unroll
            for (int nt = 0; nt < 4; nt++)
                #pragma unroll
                for (int c = 0; c < 4; c++) sacc[nt][c] = 0.f;

            #pragma unroll
            for (int kk = 0; kk < 8; kk++) {
                int w0 = kk * 8 + la;
                uint32_t ah[4], al2[4];
                ah[0] = Qh[rloc * AQ + w0];        ah[1] = Qh[(rloc + 8) * AQ + w0];
                ah[2] = Qh[rloc * AQ + w0 + 4];    ah[3] = Qh[(rloc + 8) * AQ + w0 + 4];
                al2[0] = Ql[rloc * AQ + w0];       al2[1] = Ql[(rloc + 8) * AQ + w0];
                al2[2] = Ql[rloc * AQ + w0 + 4];   al2[3] = Ql[(rloc + 8) * AQ + w0 + 4];
                #pragma unroll
                for (int nt = 0; nt < 4; nt++) {
                    int n0 = wn * 32 + nt * 8 + lr;
                    uint32_t bh[2] = { Kh[n0 * AQ + w0], Kh[n0 * AQ + w0 + 4] };
                    mma16816(sacc[nt], ah, bh);
                    mma16816(sacc[nt], al2, bh);
                }
            }

            int rgA = qt * 64 + rloc, rgB = rgA + 8;
            #pragma unroll
            for (int nt = 0; nt < 4; nt++) {
                int cg = kt * 64 + wn * 32 + nt * 8 + 2 * la;
                sacc[nt][0] = (cg     <= rgA) ? sacc[nt][0] * scale : -1e30f;
                sacc[nt][1] = (cg + 1 <= rgA) ? sacc[nt][1] * scale : -1e30f;
                sacc[nt][2] = (cg     <= rgB) ? sacc[nt][2] * scale : -1e30f;
                sacc[nt][3] = (cg + 1 <= rgB) ? sacc[nt][3] * scale : -1e30f;
            }

            float mA = -1e30f, mB = -1e30f;
            #pragma unroll
            for (int nt = 0; nt < 4; nt++) {
                mA = fmaxf(mA, fmaxf(sacc[nt][0], sacc[nt][1]));
                mB = fmaxf(mB, fmaxf(sacc[nt][2], sacc[nt][3]));
            }
            mA = fmaxf(mA, __shfl_xor_sync(0xffffffff, mA, 1));
            mA = fmaxf(mA, __shfl_xor_sync(0xffffffff, mA, 2));
            mB = fmaxf(mB, __shfl_xor_sync(0xffffffff, mB, 1));
            mB = fmaxf(mB, __shfl_xor_sync(0xffffffff, mB, 2));
            if (la == 0) { pm[wn * 64 + rloc] = mA; pm[wn * 64 + rloc + 8] = mB; }
            __syncthreads();

            float moA = rowM[rloc], moB = rowM[rloc + 8];
            float mnA = fmaxf(moA, fmaxf(pm[rloc], pm[64 + rloc]));
            float mnB = fmaxf(moB, fmaxf(pm[rloc + 8], pm[64 + rloc + 8]));
            float alA = __expf(moA - mnA), alB = __expf(moB - mnB);

            float sA = 0.f, sB = 0.f;
            #pragma unroll
            for (int nt = 0; nt < 4; nt++) {
                sacc[nt][0] = __expf(sacc[nt][0] - mnA);
                sacc[nt][1] = __expf(sacc[nt][1] - mnA);
                sacc[nt][2] = __expf(sacc[nt][2] - mnB);
                sacc[nt][3] = __expf(sacc[nt][3] - mnB);
                sA += sacc[nt][0] + sacc[nt][1];
                sB += sacc[nt][2] + sacc[nt][3];
            }
            #pragma unroll
            for (int nt = 0; nt < 8; nt++) {
                oacc[nt][0] *= alA; oacc[nt][1] *= alA;
                oacc[nt][2] *= alB; oacc[nt][3] *= alB;
            }
            sA += __shfl_xor_sync(0xffffffff, sA, 1);
            sA += __shfl_xor_sync(0xffffffff, sA, 2);
            sB += __shfl_xor_sync(0xffffffff, sB, 1);
            sB += __shfl_xor_sync(0xffffffff, sB, 2);
            __syncthreads();
            if (la == 0) { ps[wn * 64 + rloc] = sA; ps[wn * 64 + rloc + 8] = sB; }
            if (wn == 0 && la == 0) { rowM[rloc] = mnA; rowM[rloc + 8] = mnB; }
            __syncthreads();
            if (wn == 0 && la == 0) {
                rowL[rloc]     = rowL[rloc]     * alA + ps[rloc]     + ps[64 + rloc];
                rowL[rloc + 8] = rowL[rloc + 8] * alB + ps[rloc + 8] + ps[64 + rloc + 8];
            }

            #pragma unroll
            for (int kc = 0; kc < 2; kc++) {
                uint32_t phi[4];
                phi[0] = pack2h(sacc[2*kc][0],   sacc[2*kc][1]);
                phi[1] = pack2h(sacc[2*kc][2],   sacc[2*kc][3]);
                phi[2] = pack2h(sacc[2*kc+1][0], sacc[2*kc+1][1]);
                phi[3] = pack2h(sacc[2*kc+1][2], sacc[2*kc+1][3]);
                int kw = wn * 16 + kc * 8 + la;
                #pragma unroll
                for (int nt = 0; nt < 8; nt++) {
                    int d0 = nt * 8 + lr;
                    uint32_t bh[2] = { Vh[d0 * AV + kw], Vh[d0 * AV + kw + 4] };
                    mma16816(oacc[nt], phi, bh);
                }
            }
        }

        __syncthreads();
        if (wn == 0) {
            #pragma unroll
            for (int nt = 0; nt < 8; nt++) {
                int c0 = nt * 8 + 2 * la;
                Ob[rloc * 65 + c0]         = oacc[nt][0];
                Ob[rloc * 65 + c0 + 1]     = oacc[nt][1];
                Ob[(rloc+8) * 65 + c0]     = oacc[nt][2];
                Ob[(rloc+8) * 65 + c0 + 1] = oacc[nt][3];
            }
        }
        __syncthreads();
        if (wn == 1) {
            #pragma unroll
            for (int nt = 0; nt < 8; nt++) {
                int c0 = nt * 8 + 2 * la;
                Ob[rloc * 65 + c0]         += oacc[nt][0];
                Ob[rloc * 65 + c0 + 1]     += oacc[nt][1];
                Ob[(rloc+8) * 65 + c0]     += oacc[nt][2];
                Ob[(rloc+8) * 65 + c0 + 1] += oacc[nt][3];
            }
        }
        __syncthreads();
        for (int e = tid; e < 64 * 32; e += 256) {
            int r = e >> 5, d2 = (e & 31) * 2;
            float v0 = Ob[r * 65 + d2]     / rowL[r];
            float v1 = Ob[r * 65 + d2 + 1] / rowL[r];
            uint32_t lo;
            uint32_t hi = splitpackh(v0, v1, lo);
            size_t o = (size_t)(qt * 64 + r) * DD + hh * 64 + d2;
            *(uint32_t*)(atthi + o) = hi;
            *(uint32_t*)(attlo + o) = lo;
        }
        __syncthreads();
    }
}

// ---- host orchestration -------------------------------------------------------------
#define SMEMSZ(BM,BN) ((2*(BM) + (BN)) * 128)

template<int BM, int BN>
static void gemmT(const h16* Ah, const h16* Al, int lda, const h16* Bh,
                  float* C, int ldc, const float* R, h16* Ch, h16* Cl,
                  int M, int N, int K, int relu) {
    dim3 grid(N / BN, M / BM);
    gemm_mma<BM, BN><<<grid, 256, SMEMSZ(BM, BN)>>>(Ah, Al, lda, Bh, C, ldc, R, Ch, Cl, K, relu);
}

extern "C" void kernel_launch(void* const* d_in, const int* in_sizes, int n_in,
                              void* d_out, int out_size) {
    const int*   idx     = (const int*)  d_in[0];
    const float* wte     = (const float*)d_in[1];
    const float* wqdown  = (const float*)d_in[2];
    const float* wqup    = (const float*)d_in[3];
    const float* wqr     = (const float*)d_in[4];
    const float* wkvdown = (const float*)d_in[5];
    const float* wkup    = (const float*)d_in[6];
    const float* wvup    = (const float*)d_in[7];
    const float* wkr     = (const float*)d_in[8];
    const float* wo      = (const float*)d_in[9];
    const float* fc1     = (const float*)d_in[10];
    const float* fc2     = (const float*)d_in[11];
    const float* lm_head = (const float*)d_in[12];
    float* out = (float*)d_out;

    cudaFuncSetAttribute((void*)gemm_mma<128,128>, cudaFuncAttributeMaxDynamicSharedMemorySize, SMEMSZ(128,128));
    cudaFuncSetAttribute((void*)gemm_mma<128,64>,  cudaFuncAttributeMaxDynamicSharedMemorySize, SMEMSZ(128,64));
    cudaFuncSetAttribute((void*)gemm_mma<64,128>,  cudaFuncAttributeMaxDynamicSharedMemorySize, SMEMSZ(64,128));
    cudaFuncSetAttribute((void*)attn_mma,          cudaFuncAttributeMaxDynamicSharedMemorySize, ATTSM);

    void* p;
    cudaGetSymbolAddress(&p, g_x);      float* x    = (float*)p;
    cudaGetSymbolAddress(&p, g_c1);     float* c1f  = (float*)p;
    cudaGetSymbolAddress(&p, g_qqr);    float* qqr  = (float*)p;
    cudaGetSymbolAddress(&p, g_kv);     float* kv   = (float*)p;
    cudaGetSymbolAddress(&p, g_c1h);    h16* c1h    = (h16*)p;
    cudaGetSymbolAddress(&p, g_c1l);    h16* c1l    = (h16*)p;
    cudaGetSymbolAddress(&p, g_nx_hi);  h16* nxh    = (h16*)p;
    cudaGetSymbolAddress(&p, g_nx_lo);  h16* nxl    = (h16*)p;
    cudaGetSymbolAddress(&p, g_att_hi); h16* atth   = (h16*)p;
    cudaGetSymbolAddress(&p, g_att_lo); h16* attl   = (h16*)p;
    cudaGetSymbolAddress(&p, g_tmp_hi); h16* tmph   = (h16*)p;
    cudaGetSymbolAddress(&p, g_tmp_lo); h16* tmpl   = (h16*)p;
    cudaGetSymbolAddress(&p, g_x_hi);   h16* xh     = (h16*)p;
    cudaGetSymbolAddress(&p, g_x_lo);   h16* xl     = (h16*)p;
    cudaGetSymbolAddress(&p, g_wh);     h16* wh     = (h16*)p;

    // ---- fused weight layout ----
    cvt_h_s<<<2048,256>>>(wqdown,  wh+OFF_W1, NL*512*1024, 19, W1SZ, 0);
    cvt_h_s<<<2048,256>>>(wkvdown, wh+OFF_W1, NL*512*1024, 19, W1SZ, 512*1024);
    cvt_h_s<<<2048,256>>>(wkr,     wh+OFF_W1, NL*64*1024,  16, W1SZ, 1024*1024);
    cvt_h_s<<<2048,256>>>(wqup, wh+OFF_W2A, NL*1024*512, 19, W2SZ, 0);
    cvt_h_s<<<2048,256>>>(wqr,  wh+OFF_W2A, NL*1024*512, 19, W2SZ, 1024*512);
    cvt_h_s<<<2048,256>>>(wkup, wh+OFF_W2B, NL*1024*512, 19, W2SZ, 0);
    cvt_h_s<<<2048,256>>>(wvup, wh+OFF_W2B, NL*1024*512, 19, W2SZ, 1024*512);
    cvt_h_s<<<2048,256>>>(wo,      wh+OFF_WO,  NL*DD*DD, 20, DD*DD, 0);
    cvt_h_s<<<2048,256>>>(fc1,     wh+OFF_FC1, NL*FF*DD, 22, FF*DD, 0);
    cvt_h_s<<<2048,256>>>(fc2,     wh+OFF_FC2, NL*DD*FF, 22, DD*FF, 0);
    cvt_h_s<<<2048,256>>>(lm_head, wh+OFF_LMH, VV*DD,    30, VV*DD, 0);

    embed_kernel<<<TT, 256>>>(idx, wte, x);
    rmsnorm_kernel<<<TT, 256>>>(x, x, nullptr, nullptr);

    for (int l = 0; l < NL; l++) {
        const h16* w1  = wh + OFF_W1  + (size_t)l * W1SZ;
        const h16* w2a = wh + OFF_W2A + (size_t)l * W2SZ;
        const h16* w2b = wh + OFF_W2B + (size_t)l * W2SZ;
        const h16* wol = wh + OFF_WO  + (size_t)l * DD*DD;
        const h16* f1  = wh + OFF_FC1 + (size_t)l * FF*DD;
        const h16* f2  = wh + OFF_FC2 + (size_t)l * DD*FF;

        rmsnorm_kernel<<<TT, 256>>>(x, nullptr, nxh, nxl);

        gemmT<128,64>(nxh, nxl, DD, w1, c1f, 1088, nullptr, c1h, c1l, TT, 1088, DD, 0);
        gemmT<128,128>(c1h, c1l, 1088, w2a, qqr, 2048, nullptr, nullptr, nullptr, TT, 2048, LAT, 0);
        gemmT<128,128>(c1h + 512, c1l + 512, 1088, w2b, kv, 2048, nullptr, nullptr, nullptr, TT, 2048, LAT, 0);

        rope_kernel<<<dim3(TT, 17), 32>>>(qqr, c1f);

        attn_mma<<<dim3(8, 16), 256, ATTSM>>>(qqr, qqr + 1024, kv, kv + 1024, c1f + 1024, atth, attl);

        gemmT<64,128>(atth, attl, DD, wol, x, DD, x, nullptr, nullptr, TT, DD, DD, 0);

        rmsnorm_kernel<<<TT, 256>>>(x, nullptr, nxh, nxl);
        gemmT<128,128>(nxh, nxl, DD, f1, nullptr, FF, nullptr, tmph, tmpl, TT, FF, DD, 1);
        bool last = (l == NL - 1);
        gemmT<64,128>(tmph, tmpl, FF, f2, x, DD, x,
                      last ? xh : nullptr, last ? xl : nullptr, TT, DD, FF, 0);
    }

    gemmT<128,128>(xh, xl, DD, wh + OFF_LMH, out, VV, nullptr, nullptr, nullptr, TT, VV, DD, 0);
}

// round 10
// speedup vs baseline: 13.1532x; 1.0398x over previous
#include <cuda_runtime.h>
#include <cuda_fp16.h>
#include <cstdint>
#include <math.h>

#define TT 1024
#define DD 1024
#define HN 16
#define HD 64
#define LAT 512
#define RDIM 64
#define NL 8
#define VV 32000
#define FF 4096

typedef __half h16;

// ---- fused weight layout (single fp16 buffer; weights are always B operand) ---
#define W1SZ   (1088*1024)
#define W2SZ   (2048*512)
#define OFF_W1  0
#define OFF_W2A (OFF_W1  + NL*W1SZ)
#define OFF_W2B (OFF_W2A + NL*W2SZ)
#define OFF_WO  (OFF_W2B + NL*W2SZ)
#define OFF_FC1 (OFF_WO  + NL*DD*DD)
#define OFF_FC2 (OFF_FC1 + NL*FF*DD)
#define OFF_LMH (OFF_FC2 + NL*DD*FF)
#define TOTAL_W (OFF_LMH + VV*DD)

__device__ __align__(256) h16 g_wh[TOTAL_W];

// ---- activation scratch (A-side operands carry hi/lo fp16 split) --------------
__device__ __align__(256) float g_x  [TT*DD];
__device__ __align__(256) float g_c1 [TT*1088];     // ql | ckv | kr (float)
__device__ __align__(256) float g_qqr[TT*2048];     // q | qr
__device__ __align__(256) float g_kv [TT*2048];     // k | v
__device__ __align__(256) h16 g_c1h[TT*1088], g_c1l[TT*1088];
__device__ __align__(256) h16 g_nx_hi [TT*DD],  g_nx_lo [TT*DD];
__device__ __align__(256) h16 g_att_hi[TT*DD],  g_att_lo[TT*DD];
__device__ __align__(256) h16 g_tmp_hi[TT*FF],  g_tmp_lo[TT*FF];
__device__ __align__(256) h16 g_x_hi  [TT*DD],  g_x_lo  [TT*DD];

// ---- helpers -----------------------------------------------------------------
__device__ __forceinline__ uint32_t packh(h16 a, h16 b) {
    __half2 t = __halves2half2(a, b);
    return *reinterpret_cast<uint32_t*>(&t);
}
__device__ __forceinline__ uint32_t pack2h(float x, float y) {
    __half2 t = __floats2half2_rn(x, y);
    return *reinterpret_cast<uint32_t*>(&t);
}
__device__ __forceinline__ uint32_t splitpackh(float x, float y, uint32_t& lo) {
    h16 hx = __float2half_rn(x), hy = __float2half_rn(y);
    h16 lx = __float2half_rn(x - __half2float(hx));
    h16 ly = __float2half_rn(y - __half2float(hy));
    lo = packh(lx, ly);
    return packh(hx, hy);
}

__device__ __forceinline__ void cp16(uint32_t dst, const void* src) {
    asm volatile("cp.async.cg.shared.global [%0], [%1], 16;" :: "r"(dst), "l"(src));
}
#define CP_COMMIT() asm volatile("cp.async.commit_group;" ::: "memory")
#define CP_WAIT1()  asm volatile("cp.async.wait_group 1;" ::: "memory")
#define CP_WAIT0()  asm volatile("cp.async.wait_group 0;" ::: "memory")

__device__ __forceinline__ void mma16816(float* c, const uint32_t* a, const uint32_t* b) {
    asm volatile(
        "mma.sync.aligned.m16n8k16.row.col.f32.f16.f16.f32 "
        "{%0,%1,%2,%3}, {%4,%5,%6,%7}, {%8,%9}, {%0,%1,%2,%3};"
        : "+f"(c[0]), "+f"(c[1]), "+f"(c[2]), "+f"(c[3])
        : "r"(a[0]), "r"(a[1]), "r"(a[2]), "r"(a[3]), "r"(b[0]), "r"(b[1]));
}

__device__ __forceinline__ void ldm4(uint32_t* r, uint32_t addr) {
    asm volatile("ldmatrix.sync.aligned.m8n8.x4.shared.b16 {%0,%1,%2,%3}, [%4];"
        : "=r"(r[0]), "=r"(r[1]), "=r"(r[2]), "=r"(r[3]) : "r"(addr));
}

__device__ __forceinline__ int sadr(int row, int w) {
    return row * 16 + (((w >> 2) ^ (row & 3)) << 2) + (w & 3);
}

// ---- strided weight conversion (single fp16 output) ----------------------------
__global__ void cvt_h_s(const float* __restrict__ in, h16* __restrict__ hi,
                        int n, int cshift, int dstride, int doff) {
    int i = (blockIdx.x * blockDim.x + threadIdx.x) * 8;
    int stride = gridDim.x * blockDim.x * 8;
    int cmask = (1 << cshift) - 1;
    for (; i < n; i += stride) {
        size_t di = (size_t)(i >> cshift) * dstride + doff + (i & cmask);
        float4 a = *(const float4*)(in + i);
        float4 b = *(const float4*)(in + i + 4);
        *(uint4*)(hi + di) = make_uint4(pack2h(a.x, a.y), pack2h(a.z, a.w),
                                        pack2h(b.x, b.y), pack2h(b.z, b.w));
    }
}

// ---- embedding ------------------------------------------------------------------
__global__ void embed_kernel(const int* __restrict__ idx, const float* __restrict__ wte,
                             float* __restrict__ x) {
    int t = blockIdx.x;
    int row = idx[t];
    float4 v = *(const float4*)(wte + (size_t)row * DD + threadIdx.x * 4);
    *(float4*)(x + (size_t)t * DD + threadIdx.x * 4) = v;
}

// ---- rmsnorm ----------------------------------------------------------------------
__global__ void rmsnorm_kernel(const float* __restrict__ in, float* __restrict__ out,
                               h16* __restrict__ ohi, h16* __restrict__ olo) {
    __shared__ float red[8];
    int row = blockIdx.x, tid = threadIdx.x;
    float4 v = *(const float4*)(in + (size_t)row * DD + tid * 4);
    float s = v.x*v.x + v.y*v.y + v.z*v.z + v.w*v.w;
    #pragma unroll
    for (int o = 16; o > 0; o >>= 1) s += __shfl_xor_sync(0xffffffff, s, o);
    if ((tid & 31) == 0) red[tid >> 5] = s;
    __syncthreads();
    if (tid < 8) {
        float t2 = red[tid];
        #pragma unroll
        for (int o = 4; o > 0; o >>= 1) t2 += __shfl_xor_sync(0xff, t2, o);
        if (tid == 0) red[0] = t2;
    }
    __syncthreads();
    float r = rsqrtf(red[0] / (float)DD + 1e-5f);
    float4 o4 = make_float4(v.x*r, v.y*r, v.z*r, v.w*r);
    if (out) *(float4*)(out + (size_t)row * DD + tid * 4) = o4;
    if (ohi) {
        size_t b = (size_t)row * DD + tid * 4;
        uint32_t lo0, lo1;
        uint32_t hi0 = splitpackh(o4.x, o4.y, lo0);
        uint32_t hi1 = splitpackh(o4.z, o4.w, lo1);
        *(uint2*)(ohi + b) = make_uint2(hi0, hi1);
        *(uint2*)(olo + b) = make_uint2(lo0, lo1);
    }
}

// ---- RoPE (fused qr + kr: blockIdx.y==16 -> kr) --------------------------------------
__global__ void rope_kernel(float* __restrict__ qqr, float* __restrict__ c1) {
    int t = blockIdx.x, h = blockIdx.y, j = threadIdx.x;
    float f = powf(10000.f, -(float)j / 32.f);
    float sv, cv;
    sincosf((float)t * f, &sv, &cv);
    float* p = (h < 16) ? (qqr + (size_t)t * 2048 + 1024 + h * RDIM)
                        : (c1 + (size_t)t * 1088 + 1024);
    float x0 = p[j], x1 = p[j + 32];
    p[j]      = x0 * cv - x1 * sv;
    p[j + 32] = x1 * cv + x0 * sv;
}

// ---- fp16 2-pass NT GEMM via mma.sync + ldmatrix: C = (Ahi+Alo) * B^T ----------------
template<int BM, int BN>
__global__ void __launch_bounds__(256) gemm_mma(
    const h16* __restrict__ Ahi, const h16* __restrict__ Alo, int lda,
    const h16* __restrict__ Bh,
    float* __restrict__ C, int ldc, const float* __restrict__ Rres,
    h16* __restrict__ Chi, h16* __restrict__ Clo,
    int K, int relu)
{
    extern __shared__ uint32_t smw[];
    constexpr int AT  = BM * 16;
    constexpr int BT  = BN * 16;
    constexpr int STG = 2 * AT + BT;
    constexpr int NT  = BN / 16;
    constexpr int MT  = BM / 64;

    int tid = threadIdx.x, lane = tid & 31, w = tid >> 5;
    int wm = w & 3, wn = w >> 2;
    int bm = blockIdx.y * BM, bn = blockIdx.x * BN;
    int la = lane & 3, lr = lane >> 2;

    // ldmatrix per-lane addressing: lanes 0-7 rows 0-7 @w0, 8-15 rows 8-15 @w0,
    // 16-23 rows 0-7 @w0+4, 24-31 rows 8-15 @w0+4
    int rowl = (lane & 7) | (((lane >> 3) & 1) << 3);
    int csel = (lane >> 4) << 2;

    uint32_t sbase = (uint32_t)__cvta_generic_to_shared(smw);

    auto load_stage = [&](int i, int st) {
        int k0 = i * 32;
        uint32_t so = sbase + (uint32_t)(st * STG) * 4;
        #pragma unroll
        for (int e0 = 0; e0 < BM * 4; e0 += 256) {
            int e = e0 + tid;
            int r = e >> 2, kq = e & 3;
            size_t g = (size_t)(bm + r) * lda + k0 + kq * 8;
            uint32_t d = so + (uint32_t)(r * 16 + ((kq ^ (r & 3)) << 2)) * 4;
            cp16(d, Ahi + g);
            cp16(d + AT * 4, Alo + g);
        }
        #pragma unroll
        for (int e0 = 0; e0 < BN * 4; e0 += 256) {
            int e = e0 + tid;
            int r = e >> 2, kq = e & 3;
            size_t g = (size_t)(bn + r) * K + k0 + kq * 8;
            uint32_t d = so + (uint32_t)(2 * AT + r * 16 + ((kq ^ (r & 3)) << 2)) * 4;
            cp16(d, Bh + g);
        }
        CP_COMMIT();
    };

    float acc[MT][NT][4];
    #pragma unroll
    for (int mt = 0; mt < MT; mt++)
        #pragma unroll
        for (int nt = 0; nt < NT; nt++)
            #pragma unroll
            for (int c = 0; c < 4; c++) acc[mt][nt][c] = 0.f;

    int nk = K >> 5;
    load_stage(0, 0);
    for (int i = 0; i < nk; i++) {
        if (i + 1 < nk) { load_stage(i + 1, (i + 1) & 1); CP_WAIT1(); }
        else            { CP_WAIT0(); }
        __syncthreads();

        uint32_t SaB = sbase + (uint32_t)((i & 1) * STG) * 4;
        uint32_t SbB = SaB + (uint32_t)(2 * AT) * 4;
        #pragma unroll
        for (int ks = 0; ks < 2; ks++) {
            int w0 = ks * 8 + csel;
            uint32_t ah[MT][4], al[MT][4];
            #pragma unroll
            for (int mt = 0; mt < MT; mt++) {
                uint32_t aaddr = SaB + (uint32_t)sadr(wm * (BM / 4) + mt * 16 + rowl, w0) * 4;
                ldm4(ah[mt], aaddr);
                ldm4(al[mt], aaddr + AT * 4);
            }
            #pragma unroll
            for (int nt2 = 0; nt2 < NT / 2; nt2++) {
                uint32_t baddr = SbB + (uint32_t)sadr(wn * (BN / 2) + nt2 * 16 + rowl, w0) * 4;
                uint32_t bb[4];
                ldm4(bb, baddr);
                uint32_t b0[2] = { bb[0], bb[2] };   // even n-subtile
                uint32_t b1[2] = { bb[1], bb[3] };   // odd n-subtile
                #pragma unroll
                for (int mt = 0; mt < MT; mt++) {
                    mma16816(acc[mt][2 * nt2],     ah[mt], b0);
                    mma16816(acc[mt][2 * nt2],     al[mt], b0);
                    mma16816(acc[mt][2 * nt2 + 1], ah[mt], b1);
                    mma16816(acc[mt][2 * nt2 + 1], al[mt], b1);
                }
            }
        }
        __syncthreads();
    }

    #pragma unroll
    for (int mt = 0; mt < MT; mt++) {
        #pragma unroll
        for (int nt = 0; nt < NT; nt++) {
            int col = bn + wn * (BN / 2) + nt * 8 + la * 2;
            #pragma unroll
            for (int half = 0; half < 2; half++) {
                int row = bm + wm * (BM / 4) + mt * 16 + lr + half * 8;
                float v0 = acc[mt][nt][half * 2 + 0];
                float v1 = acc[mt][nt][half * 2 + 1];
                size_t base = (size_t)row * ldc + col;
                if (Rres) {
                    float2 rr = *(const float2*)(Rres + base);
                    v0 += rr.x; v1 += rr.y;
                }
                if (relu) { v0 = fmaxf(v0, 0.f); v1 = fmaxf(v1, 0.f); }
                if (C) *(float2*)(C + base) = make_float2(v0, v1);
                if (Chi) {
                    uint32_t lo;
                    uint32_t hi = splitpackh(v0, v1, lo);
                    *(uint32_t*)(Chi + base) = hi;
                    *(uint32_t*)(Clo + base) = lo;
                }
            }
        }
    }
}

// ---- flash attention, fp16 2-pass (Q split, K/V/P plain) -----------------------------
#define QLD 2048
#define KRLD 1088
#define AQ 68
#define AV 36
#define ATTSM ((3*64*AQ + 64*AV) * 4 + 64*65*4 + (64+64+128+128) * 4)

__global__ void __launch_bounds__(256, 1) attn_mma(
    const float* __restrict__ q,  const float* __restrict__ qr,
    const float* __restrict__ k,  const float* __restrict__ v,
    const float* __restrict__ kr,
    h16* __restrict__ atthi, h16* __restrict__ attlo)
{
    extern __shared__ uint32_t sw[];
    uint32_t* Qh = sw;
    uint32_t* Ql = Qh + 64 * AQ;
    uint32_t* Kh = Ql + 64 * AQ;
    uint32_t* Vh = Kh + 64 * AQ;
    float* Ob   = (float*)(Vh + 64 * AV);
    float* rowM = Ob + 64 * 65;
    float* rowL = rowM + 64;
    float* pm   = rowL + 64;
    float* ps   = pm + 128;

    int hh = blockIdx.y, tid = threadIdx.x;
    int lane = tid & 31, w = tid >> 5;
    int wm = w & 3, wn = w >> 2;
    int la = lane & 3, lr = lane >> 2;
    const float scale = rsqrtf(128.f);

    for (int half = 0; half < 2; half++) {
        int qt = half ? (15 - (int)blockIdx.x) : (int)blockIdx.x;

        for (int e = tid; e < 64 * 64; e += 256) {
            int r = e >> 6, wq = e & 63;
            int t = qt * 64 + r, d = wq * 2;
            const float* src = (d < 64) ? (q + (size_t)t * QLD + hh * 64 + d)
                                        : (qr + (size_t)t * QLD + hh * 64 + (d - 64));
            float2 f = *(const float2*)src;
            uint32_t lo;
            uint32_t hi = splitpackh(f.x, f.y, lo);
            Qh[r * AQ + wq] = hi; Ql[r * AQ + wq] = lo;
        }
        if (tid < 64) { rowM[tid] = -1e30f; rowL[tid] = 0.f; }

        float oacc[8][4];
        #pragma unroll
        for (int nt = 0; nt < 8; nt++)
            #pragma unroll
            for (int c = 0; c < 4; c++) oacc[nt][c] = 0.f;

        int rloc = wm * 16 + lr;

        for (int kt = 0; kt <= qt; kt++) {
            __syncthreads();

            for (int e = tid; e < 64 * 64; e += 256) {
                int r = e >> 6, wq = e & 63;
                int t = kt * 64 + r, d = wq * 2;
                const float* src = (d < 64) ? (k + (size_t)t * QLD + hh * 64 + d)
                                            : (kr + (size_t)t * KRLD + (d - 64));
                float2 f = *(const float2*)src;
                Kh[r * AQ + wq] = pack2h(f.x, f.y);
            }
            for (int e = tid; e < 64 * 32; e += 256) {
                int kp = e >> 6, d = e & 63;
                float v0 = v[(size_t)(kt * 64 + 2 * kp) * QLD + hh * 64 + d];
                float v1 = v[(size_t)(kt * 64 + 2 * kp + 1) * QLD + hh * 64 + d];
                Vh[d * AV + kp] = pack2h(v0, v1);
            }
            __syncthreads();

            float sacc[4][4];
            #pragma unroll
            for (int nt = 0; nt < 4; nt++)
                #pragma unroll
                for (int c = 0; c < 4; c++) sacc[nt][c] = 0.f;

            #pragma unroll
            for (int kk = 0; kk < 8; kk++) {
                int w0 = kk * 8 + la;
                uint32_t ah[4], al2[4];
                ah[0] = Qh[rloc * AQ + w0];        ah[1] = Qh[(rloc + 8) * AQ + w0];
                ah[2] = Qh[rloc * AQ + w0 + 4];    ah[3] = Qh[(rloc + 8) * AQ + w0 + 4];
                al2[0] = Ql[rloc * AQ + w0];       al2[1] = Ql[(rloc + 8) * AQ + w0];
                al2[2] = Ql[rloc * AQ + w0 + 4];   al2[3] = Ql[(rloc + 8) * AQ + w0 + 4];
                #pragma unroll
                for (int nt = 0; nt < 4; nt++) {
                    int n0 = wn * 32 + nt * 8 + lr;
                    uint32_t bh[2] = { Kh[n0 * AQ + w0], Kh[n0 * AQ + w0 + 4] };
                    mma16816(sacc[nt], ah, bh);
                    mma16816(sacc[nt], al2, bh);
                }
            }

            int rgA = qt * 64 + rloc, rgB = rgA + 8;
            #pragma unroll
            for (int nt = 0; nt < 4; nt++) {
                int cg = kt * 64 + wn * 32 + nt * 8 + 2 * la;
                sacc[nt][0] = (cg     <= rgA) ? sacc[nt][0] * scale : -1e30f;
                sacc[nt][1] = (cg + 1 <= rgA) ? sacc[nt][1] * scale : -1e30f;
                sacc[nt][2] = (cg     <= rgB) ? sacc[nt][2] * scale : -1e30f;
                sacc[nt][3] = (cg + 1 <= rgB) ? sacc[nt][3] * scale : -1e30f;
            }

            float mA = -1e30f, mB = -1e30f;
            #pragma unroll
            for (int nt = 0; nt < 4; nt++) {
                mA = fmaxf(mA, fmaxf(sacc[nt][0], sacc[nt][1]));
                mB = fmaxf(mB, fmaxf(sacc[nt][2], sacc[nt][3]));
            }
            mA = fmaxf(mA, __shfl_xor_sync(0xffffffff, mA, 1));
            mA = fmaxf(mA, __shfl_xor_sync(0xffffffff, mA, 2));
            mB = fmaxf(mB, __shfl_xor_sync(0xffffffff, mB, 1));
            mB = fmaxf(mB, __shfl_xor_sync(0xffffffff, mB, 2));
            if (la == 0) { pm[wn * 64 + rloc] = mA; pm[wn * 64 + rloc + 8] = mB; }
            __syncthreads();

            float moA = rowM[rloc], moB = rowM[rloc + 8];
            float mnA = fmaxf(moA, fmaxf(pm[rloc], pm[64 + rloc]));
            float mnB = fmaxf(moB, fmaxf(pm[rloc + 8], pm[64 + rloc + 8]));
            float alA = __expf(moA - mnA), alB = __expf(moB - mnB);

            float sA = 0.f, sB = 0.f;
            #pragma unroll
            for (int nt = 0; nt < 4; nt++) {
                sacc[nt][0] = __expf(sacc[nt][0] - mnA);
                sacc[nt][1] = __expf(sacc[nt][1] - mnA);
                sacc[nt][2] = __expf(sacc[nt][2] - mnB);
                sacc[nt][3] = __expf(sacc[nt][3] - mnB);
                sA += sacc[nt][0] + sacc[nt][1];
                sB += sacc[nt][2] + sacc[nt][3];
            }
            #pragma unroll
            for (int nt = 0; nt < 8; nt++) {
                oacc[nt][0] *= alA; oacc[nt][1] *= alA;
                oacc[nt][2] *= alB; oacc[nt][3] *= alB;
            }
            sA += __shfl_xor_sync(0xffffffff, sA, 1);
            sA += __shfl_xor_sync(0xffffffff, sA, 2);
            sB += __shfl_xor_sync(0xffffffff, sB, 1);
            sB += __shfl_xor_sync(0xffffffff, sB, 2);
            __syncthreads();
            if (la == 0) { ps[wn * 64 + rloc] = sA; ps[wn * 64 + rloc + 8] = sB; }
            if (wn == 0 && la == 0) { rowM[rloc] = mnA; rowM[rloc + 8] = mnB; }
            __syncthreads();
            if (wn == 0 && la == 0) {
                rowL[rloc]     = rowL[rloc]     * alA + ps[rloc]     + ps[64 + rloc];
                rowL[rloc + 8] = rowL[rloc + 8] * alB + ps[rloc + 8] + ps[64 + rloc + 8];
            }

            #pragma unroll
            for (int kc = 0; kc < 2; kc++) {
                uint32_t phi[4];
                phi[0] = pack2h(sacc[2*kc][0],   sacc[2*kc][1]);
                phi[1] = pack2h(sacc[2*kc][2],   sacc[2*kc][3]);
                phi[2] = pack2h(sacc[2*kc+1][0], sacc[2*kc+1][1]);
                phi[3] = pack2h(sacc[2*kc+1][2], sacc[2*kc+1][3]);
                int kw = wn * 16 + kc * 8 + la;
                #pragma unroll
                for (int nt = 0; nt < 8; nt++) {
                    int d0 = nt * 8 + lr;
                    uint32_t bh[2] = { Vh[d0 * AV + kw], Vh[d0 * AV + kw + 4] };
                    mma16816(oacc[nt], phi, bh);
                }
            }
        }

        __syncthreads();
        if (wn == 0) {
            #pragma unroll
            for (int nt = 0; nt < 8; nt++) {
                int c0 = nt * 8 + 2 * la;
                Ob[rloc * 65 + c0]         = oacc[nt][0];
                Ob[rloc * 65 + c0 + 1]     = oacc[nt][1];
                Ob[(rloc+8) * 65 + c0]     = oacc[nt][2];
                Ob[(rloc+8) * 65 + c0 + 1] = oacc[nt][3];
            }
        }
        __syncthreads();
        if (wn == 1) {
            #pragma unroll
            for (int nt = 0; nt < 8; nt++) {
                int c0 = nt * 8 + 2 * la;
                Ob[rloc * 65 + c0]         += oacc[nt][0];
                Ob[rloc * 65 + c0 + 1]     += oacc[nt][1];
                Ob[(rloc+8) * 65 + c0]     += oacc[nt][2];
                Ob[(rloc+8) * 65 + c0 + 1] += oacc[nt][3];
            }
        }
        __syncthreads();
        for (int e = tid; e < 64 * 32; e += 256) {
            int r = e >> 5, d2 = (e & 31) * 2;
            float v0 = Ob[r * 65 + d2]     / rowL[r];
            float v1 = Ob[r * 65 + d2 + 1] / rowL[r];
            uint32_t lo;
            uint32_t hi = splitpackh(v0, v1, lo);
            size_t o = (size_t)(qt * 64 + r) * DD + hh * 64 + d2;
            *(uint32_t*)(atthi + o) = hi;
            *(uint32_t*)(attlo + o) = lo;
        }
        __syncthreads();
    }
}

// ---- host orchestration -------------------------------------------------------------
#define SMEMSZ(BM,BN) ((2*(BM) + (BN)) * 128)

template<int BM, int BN>
static void gemmT(const h16* Ah, const h16* Al, int lda, const h16* Bh,
                  float* C, int ldc, const float* R, h16* Ch, h16* Cl,
                  int M, int N, int K, int relu) {
    dim3 grid(N / BN, M / BM);
    gemm_mma<BM, BN><<<grid, 256, SMEMSZ(BM, BN)>>>(Ah, Al, lda, Bh, C, ldc, R, Ch, Cl, K, relu);
}

extern "C" void kernel_launch(void* const* d_in, const int* in_sizes, int n_in,
                              void* d_out, int out_size) {
    const int*   idx     = (const int*)  d_in[0];
    const float* wte     = (const float*)d_in[1];
    const float* wqdown  = (const float*)d_in[2];
    const float* wqup    = (const float*)d_in[3];
    const float* wqr     = (const float*)d_in[4];
    const float* wkvdown = (const float*)d_in[5];
    const float* wkup    = (const float*)d_in[6];
    const float* wvup    = (const float*)d_in[7];
    const float* wkr     = (const float*)d_in[8];
    const float* wo      = (const float*)d_in[9];
    const float* fc1     = (const float*)d_in[10];
    const float* fc2     = (const float*)d_in[11];
    const float* lm_head = (const float*)d_in[12];
    float* out = (float*)d_out;

    cudaFuncSetAttribute((void*)gemm_mma<128,128>, cudaFuncAttributeMaxDynamicSharedMemorySize, SMEMSZ(128,128));
    cudaFuncSetAttribute((void*)gemm_mma<128,64>,  cudaFuncAttributeMaxDynamicSharedMemorySize, SMEMSZ(128,64));
    cudaFuncSetAttribute((void*)gemm_mma<64,128>,  cudaFuncAttributeMaxDynamicSharedMemorySize, SMEMSZ(64,128));
    cudaFuncSetAttribute((void*)attn_mma,          cudaFuncAttributeMaxDynamicSharedMemorySize, ATTSM);

    void* p;
    cudaGetSymbolAddress(&p, g_x);      float* x    = (float*)p;
    cudaGetSymbolAddress(&p, g_c1);     float* c1f  = (float*)p;
    cudaGetSymbolAddress(&p, g_qqr);    float* qqr  = (float*)p;
    cudaGetSymbolAddress(&p, g_kv);     float* kv   = (float*)p;
    cudaGetSymbolAddress(&p, g_c1h);    h16* c1h    = (h16*)p;
    cudaGetSymbolAddress(&p, g_c1l);    h16* c1l    = (h16*)p;
    cudaGetSymbolAddress(&p, g_nx_hi);  h16* nxh    = (h16*)p;
    cudaGetSymbolAddress(&p, g_nx_lo);  h16* nxl    = (h16*)p;
    cudaGetSymbolAddress(&p, g_att_hi); h16* atth   = (h16*)p;
    cudaGetSymbolAddress(&p, g_att_lo); h16* attl   = (h16*)p;
    cudaGetSymbolAddress(&p, g_tmp_hi); h16* tmph   = (h16*)p;
    cudaGetSymbolAddress(&p, g_tmp_lo); h16* tmpl   = (h16*)p;
    cudaGetSymbolAddress(&p, g_x_hi);   h16* xh     = (h16*)p;
    cudaGetSymbolAddress(&p, g_x_lo);   h16* xl     = (h16*)p;
    cudaGetSymbolAddress(&p, g_wh);     h16* wh     = (h16*)p;

    // ---- fused weight layout ----
    cvt_h_s<<<2048,256>>>(wqdown,  wh+OFF_W1, NL*512*1024, 19, W1SZ, 0);
    cvt_h_s<<<2048,256>>>(wkvdown, wh+OFF_W1, NL*512*1024, 19, W1SZ, 512*1024);
    cvt_h_s<<<2048,256>>>(wkr,     wh+OFF_W1, NL*64*1024,  16, W1SZ, 1024*1024);
    cvt_h_s<<<2048,256>>>(wqup, wh+OFF_W2A, NL*1024*512, 19, W2SZ, 0);
    cvt_h_s<<<2048,256>>>(wqr,  wh+OFF_W2A, NL*1024*512, 19, W2SZ, 1024*512);
    cvt_h_s<<<2048,256>>>(wkup, wh+OFF_W2B, NL*1024*512, 19, W2SZ, 0);
    cvt_h_s<<<2048,256>>>(wvup, wh+OFF_W2B, NL*1024*512, 19, W2SZ, 1024*512);
    cvt_h_s<<<2048,256>>>(wo,      wh+OFF_WO,  NL*DD*DD, 20, DD*DD, 0);
    cvt_h_s<<<2048,256>>>(fc1,     wh+OFF_FC1, NL*FF*DD, 22, FF*DD, 0);
    cvt_h_s<<<2048,256>>>(fc2,     wh+OFF_FC2, NL*DD*FF, 22, DD*FF, 0);
    cvt_h_s<<<2048,256>>>(lm_head, wh+OFF_LMH, VV*DD,    30, VV*DD, 0);

    embed_kernel<<<TT, 256>>>(idx, wte, x);
    rmsnorm_kernel<<<TT, 256>>>(x, x, nullptr, nullptr);

    for (int l = 0; l < NL; l++) {
        const h16* w1  = wh + OFF_W1  + (size_t)l * W1SZ;
        const h16* w2a = wh + OFF_W2A + (size_t)l * W2SZ;
        const h16* w2b = wh + OFF_W2B + (size_t)l * W2SZ;
        const h16* wol = wh + OFF_WO  + (size_t)l * DD*DD;
        const h16* f1  = wh + OFF_FC1 + (size_t)l * FF*DD;
        const h16* f2  = wh + OFF_FC2 + (size_t)l * DD*FF;

        rmsnorm_kernel<<<TT, 256>>>(x, nullptr, nxh, nxl);

        gemmT<128,64>(nxh, nxl, DD, w1, c1f, 1088, nullptr, c1h, c1l, TT, 1088, DD, 0);
        gemmT<128,128>(c1h, c1l, 1088, w2a, qqr, 2048, nullptr, nullptr, nullptr, TT, 2048, LAT, 0);
        gemmT<128,128>(c1h + 512, c1l + 512, 1088, w2b, kv, 2048, nullptr, nullptr, nullptr, TT, 2048, LAT, 0);

        rope_kernel<<<dim3(TT, 17), 32>>>(qqr, c1f);

        attn_mma<<<dim3(8, 16), 256, ATTSM>>>(qqr, qqr + 1024, kv, kv + 1024, c1f + 1024, atth, attl);

        gemmT<64,128>(atth, attl, DD, wol, x, DD, x, nullptr, nullptr, TT, DD, DD, 0);

        rmsnorm_kernel<<<TT, 256>>>(x, nullptr, nxh, nxl);
        gemmT<128,128>(nxh, nxl, DD, f1, nullptr, FF, nullptr, tmph, tmpl, TT, FF, DD, 1);
        bool last = (l == NL - 1);
        gemmT<64,128>(tmph, tmpl, FF, f2, x, DD, x,
                      last ? xh : nullptr, last ? xl : nullptr, TT, DD, FF, 0);
    }

    gemmT<128,128>(xh, xl, DD, wh + OFF_LMH, out, VV, nullptr, nullptr, nullptr, TT, VV, DD, 0);
}

// round 11
// speedup vs baseline: 13.3064x; 1.0116x over previous
#include <cuda_runtime.h>
#include <cuda_fp16.h>
#include <cstdint>
#include <math.h>

#define TT 1024
#define DD 1024
#define HN 16
#define HD 64
#define LAT 512
#define RDIM 64
#define NL 8
#define VV 32000
#define FF 4096

typedef __half h16;

// ---- fused weight layout (single fp16 buffer; weights are always B operand) ---
#define W1SZ   (1088*1024)
#define W2SZ   (2048*512)
#define OFF_W1  0
#define OFF_W2A (OFF_W1  + NL*W1SZ)
#define OFF_W2B (OFF_W2A + NL*W2SZ)
#define OFF_WO  (OFF_W2B + NL*W2SZ)
#define OFF_FC1 (OFF_WO  + NL*DD*DD)
#define OFF_FC2 (OFF_FC1 + NL*FF*DD)
#define OFF_LMH (OFF_FC2 + NL*DD*FF)
#define TOTAL_W (OFF_LMH + VV*DD)

__device__ __align__(256) h16 g_wh[TOTAL_W];

// ---- activation scratch (A-side operands carry hi/lo fp16 split) --------------
__device__ __align__(256) float g_x  [TT*DD];
__device__ __align__(256) float g_c1 [TT*1088];     // ql | ckv | kr (float)
__device__ __align__(256) float g_qqr[TT*2048];     // q | qr
__device__ __align__(256) float g_kv [TT*2048];     // k | v
__device__ __align__(256) h16 g_c1h[TT*1088], g_c1l[TT*1088];
__device__ __align__(256) h16 g_nx_hi [TT*DD],  g_nx_lo [TT*DD];
__device__ __align__(256) h16 g_att_hi[TT*DD],  g_att_lo[TT*DD];
__device__ __align__(256) h16 g_tmp_hi[TT*FF],  g_tmp_lo[TT*FF];
__device__ __align__(256) h16 g_x_hi  [TT*DD],  g_x_lo  [TT*DD];

// ---- helpers -----------------------------------------------------------------
__device__ __forceinline__ uint32_t packh(h16 a, h16 b) {
    __half2 t = __halves2half2(a, b);
    return *reinterpret_cast<uint32_t*>(&t);
}
__device__ __forceinline__ uint32_t pack2h(float x, float y) {
    __half2 t = __floats2half2_rn(x, y);
    return *reinterpret_cast<uint32_t*>(&t);
}
__device__ __forceinline__ uint32_t splitpackh(float x, float y, uint32_t& lo) {
    h16 hx = __float2half_rn(x), hy = __float2half_rn(y);
    h16 lx = __float2half_rn(x - __half2float(hx));
    h16 ly = __float2half_rn(y - __half2float(hy));
    lo = packh(lx, ly);
    return packh(hx, hy);
}

__device__ __forceinline__ void cp16(uint32_t dst, const void* src) {
    asm volatile("cp.async.cg.shared.global [%0], [%1], 16;" :: "r"(dst), "l"(src));
}
#define CP_COMMIT() asm volatile("cp.async.commit_group;" ::: "memory")
template<int N> __device__ __forceinline__ void cp_wait() {
    asm volatile("cp.async.wait_group %0;" :: "n"(N) : "memory");
}

__device__ __forceinline__ void mma16816(float* c, const uint32_t* a, const uint32_t* b) {
    asm volatile(
        "mma.sync.aligned.m16n8k16.row.col.f32.f16.f16.f32 "
        "{%0,%1,%2,%3}, {%4,%5,%6,%7}, {%8,%9}, {%0,%1,%2,%3};"
        : "+f"(c[0]), "+f"(c[1]), "+f"(c[2]), "+f"(c[3])
        : "r"(a[0]), "r"(a[1]), "r"(a[2]), "r"(a[3]), "r"(b[0]), "r"(b[1]));
}

__device__ __forceinline__ void ldm4(uint32_t* r, uint32_t addr) {
    asm volatile("ldmatrix.sync.aligned.m8n8.x4.shared.b16 {%0,%1,%2,%3}, [%4];"
        : "=r"(r[0]), "=r"(r[1]), "=r"(r[2]), "=r"(r[3]) : "r"(addr));
}

__device__ __forceinline__ int sadr(int row, int w) {
    return row * 16 + (((w >> 2) ^ (row & 3)) << 2) + (w & 3);
}

// ---- strided weight conversion (single fp16 output) ----------------------------
__global__ void cvt_h_s(const float* __restrict__ in, h16* __restrict__ hi,
                        int n, int cshift, int dstride, int doff) {
    int i = (blockIdx.x * blockDim.x + threadIdx.x) * 8;
    int stride = gridDim.x * blockDim.x * 8;
    int cmask = (1 << cshift) - 1;
    for (; i < n; i += stride) {
        size_t di = (size_t)(i >> cshift) * dstride + doff + (i & cmask);
        float4 a = *(const float4*)(in + i);
        float4 b = *(const float4*)(in + i + 4);
        *(uint4*)(hi + di) = make_uint4(pack2h(a.x, a.y), pack2h(a.z, a.w),
                                        pack2h(b.x, b.y), pack2h(b.z, b.w));
    }
}

// ---- embedding ------------------------------------------------------------------
__global__ void embed_kernel(const int* __restrict__ idx, const float* __restrict__ wte,
                             float* __restrict__ x) {
    int t = blockIdx.x;
    int row = idx[t];
    float4 v = *(const float4*)(wte + (size_t)row * DD + threadIdx.x * 4);
    *(float4*)(x + (size_t)t * DD + threadIdx.x * 4) = v;
}

// ---- rmsnorm ----------------------------------------------------------------------
__global__ void rmsnorm_kernel(const float* __restrict__ in, float* __restrict__ out,
                               h16* __restrict__ ohi, h16* __restrict__ olo) {
    __shared__ float red[8];
    int row = blockIdx.x, tid = threadIdx.x;
    float4 v = *(const float4*)(in + (size_t)row * DD + tid * 4);
    float s = v.x*v.x + v.y*v.y + v.z*v.z + v.w*v.w;
    #pragma unroll
    for (int o = 16; o > 0; o >>= 1) s += __shfl_xor_sync(0xffffffff, s, o);
    if ((tid & 31) == 0) red[tid >> 5] = s;
    __syncthreads();
    if (tid < 8) {
        float t2 = red[tid];
        #pragma unroll
        for (int o = 4; o > 0; o >>= 1) t2 += __shfl_xor_sync(0xff, t2, o);
        if (tid == 0) red[0] = t2;
    }
    __syncthreads();
    float r = rsqrtf(red[0] / (float)DD + 1e-5f);
    float4 o4 = make_float4(v.x*r, v.y*r, v.z*r, v.w*r);
    if (out) *(float4*)(out + (size_t)row * DD + tid * 4) = o4;
    if (ohi) {
        size_t b = (size_t)row * DD + tid * 4;
        uint32_t lo0, lo1;
        uint32_t hi0 = splitpackh(o4.x, o4.y, lo0);
        uint32_t hi1 = splitpackh(o4.z, o4.w, lo1);
        *(uint2*)(ohi + b) = make_uint2(hi0, hi1);
        *(uint2*)(olo + b) = make_uint2(lo0, lo1);
    }
}

// ---- RoPE (fused qr + kr: blockIdx.y==16 -> kr) --------------------------------------
__global__ void rope_kernel(float* __restrict__ qqr, float* __restrict__ c1) {
    int t = blockIdx.x, h = blockIdx.y, j = threadIdx.x;
    float f = powf(10000.f, -(float)j / 32.f);
    float sv, cv;
    sincosf((float)t * f, &sv, &cv);
    float* p = (h < 16) ? (qqr + (size_t)t * 2048 + 1024 + h * RDIM)
                        : (c1 + (size_t)t * 1088 + 1024);
    float x0 = p[j], x1 = p[j + 32];
    p[j]      = x0 * cv - x1 * sv;
    p[j + 32] = x1 * cv + x0 * sv;
}

// ---- fp16 2-pass NT GEMM, 4-stage cp.async pipeline + ldmatrix ----------------------
template<int BM, int BN>
__global__ void __launch_bounds__(256) gemm_mma(
    const h16* __restrict__ Ahi, const h16* __restrict__ Alo, int lda,
    const h16* __restrict__ Bh,
    float* __restrict__ C, int ldc, const float* __restrict__ Rres,
    h16* __restrict__ Chi, h16* __restrict__ Clo,
    int K, int relu)
{
    extern __shared__ uint32_t smw[];
    constexpr int AT  = BM * 16;
    constexpr int BT  = BN * 16;
    constexpr int STG = 2 * AT + BT;
    constexpr int NT  = BN / 16;
    constexpr int MT  = BM / 64;
    constexpr int D   = 4;              // pipeline depth

    int tid = threadIdx.x, lane = tid & 31, w = tid >> 5;
    int wm = w & 3, wn = w >> 2;
    int bm = blockIdx.y * BM, bn = blockIdx.x * BN;
    int la = lane & 3, lr = lane >> 2;

    int rowl = (lane & 7) | (((lane >> 3) & 1) << 3);
    int csel = (lane >> 4) << 2;

    uint32_t sbase = (uint32_t)__cvta_generic_to_shared(smw);

    auto load_stage = [&](int i, int st) {
        int k0 = i * 32;
        uint32_t so = sbase + (uint32_t)(st * STG) * 4;
        #pragma unroll
        for (int e0 = 0; e0 < BM * 4; e0 += 256) {
            int e = e0 + tid;
            int r = e >> 2, kq = e & 3;
            size_t g = (size_t)(bm + r) * lda + k0 + kq * 8;
            uint32_t d = so + (uint32_t)(r * 16 + ((kq ^ (r & 3)) << 2)) * 4;
            cp16(d, Ahi + g);
            cp16(d + AT * 4, Alo + g);
        }
        #pragma unroll
        for (int e0 = 0; e0 < BN * 4; e0 += 256) {
            int e = e0 + tid;
            int r = e >> 2, kq = e & 3;
            size_t g = (size_t)(bn + r) * K + k0 + kq * 8;
            uint32_t d = so + (uint32_t)(2 * AT + r * 16 + ((kq ^ (r & 3)) << 2)) * 4;
            cp16(d, Bh + g);
        }
        CP_COMMIT();
    };

    float acc[MT][NT][4];
    #pragma unroll
    for (int mt = 0; mt < MT; mt++)
        #pragma unroll
        for (int nt = 0; nt < NT; nt++)
            #pragma unroll
            for (int c = 0; c < 4; c++) acc[mt][nt][c] = 0.f;

    int nk = K >> 5;
    // preload D-1 stages (nk >= 16 always here)
    #pragma unroll
    for (int s = 0; s < D - 1; s++) load_stage(s, s);

    for (int i = 0; i < nk; i++) {
        cp_wait<D - 2>();          // group i complete
        __syncthreads();           // all warps done reading stage (i-1)%D
        if (i + D - 1 < nk) load_stage(i + D - 1, (i + D - 1) % D);
        else                CP_COMMIT();   // keep group count uniform

        uint32_t SaB = sbase + (uint32_t)((i % D) * STG) * 4;
        uint32_t SbB = SaB + (uint32_t)(2 * AT) * 4;
        #pragma unroll
        for (int ks = 0; ks < 2; ks++) {
            int w0 = ks * 8 + csel;
            uint32_t ah[MT][4], al[MT][4];
            #pragma unroll
            for (int mt = 0; mt < MT; mt++) {
                uint32_t aaddr = SaB + (uint32_t)sadr(wm * (BM / 4) + mt * 16 + rowl, w0) * 4;
                ldm4(ah[mt], aaddr);
                ldm4(al[mt], aaddr + AT * 4);
            }
            #pragma unroll
            for (int nt2 = 0; nt2 < NT / 2; nt2++) {
                uint32_t baddr = SbB + (uint32_t)sadr(wn * (BN / 2) + nt2 * 16 + rowl, w0) * 4;
                uint32_t bb[4];
                ldm4(bb, baddr);
                uint32_t b0[2] = { bb[0], bb[2] };
                uint32_t b1[2] = { bb[1], bb[3] };
                #pragma unroll
                for (int mt = 0; mt < MT; mt++) {
                    mma16816(acc[mt][2 * nt2],     ah[mt], b0);
                    mma16816(acc[mt][2 * nt2],     al[mt], b0);
                    mma16816(acc[mt][2 * nt2 + 1], ah[mt], b1);
                    mma16816(acc[mt][2 * nt2 + 1], al[mt], b1);
                }
            }
        }
    }

    #pragma unroll
    for (int mt = 0; mt < MT; mt++) {
        #pragma unroll
        for (int nt = 0; nt < NT; nt++) {
            int col = bn + wn * (BN / 2) + nt * 8 + la * 2;
            #pragma unroll
            for (int half = 0; half < 2; half++) {
                int row = bm + wm * (BM / 4) + mt * 16 + lr + half * 8;
                float v0 = acc[mt][nt][half * 2 + 0];
                float v1 = acc[mt][nt][half * 2 + 1];
                size_t base = (size_t)row * ldc + col;
                if (Rres) {
                    float2 rr = *(const float2*)(Rres + base);
                    v0 += rr.x; v1 += rr.y;
                }
                if (relu) { v0 = fmaxf(v0, 0.f); v1 = fmaxf(v1, 0.f); }
                if (C) *(float2*)(C + base) = make_float2(v0, v1);
                if (Chi) {
                    uint32_t lo;
                    uint32_t hi = splitpackh(v0, v1, lo);
                    *(uint32_t*)(Chi + base) = hi;
                    *(uint32_t*)(Clo + base) = lo;
                }
            }
        }
    }
}

// ---- flash attention, fp16 2-pass (Q split, K/V/P plain) -----------------------------
#define QLD 2048
#define KRLD 1088
#define AQ 68
#define AV 36
#define ATTSM ((3*64*AQ + 64*AV) * 4 + 64*65*4 + (64+64+128+128) * 4)

__global__ void __launch_bounds__(256, 1) attn_mma(
    const float* __restrict__ q,  const float* __restrict__ qr,
    const float* __restrict__ k,  const float* __restrict__ v,
    const float* __restrict__ kr,
    h16* __restrict__ atthi, h16* __restrict__ attlo)
{
    extern __shared__ uint32_t sw[];
    uint32_t* Qh = sw;
    uint32_t* Ql = Qh + 64 * AQ;
    uint32_t* Kh = Ql + 64 * AQ;
    uint32_t* Vh = Kh + 64 * AQ;
    float* Ob   = (float*)(Vh + 64 * AV);
    float* rowM = Ob + 64 * 65;
    float* rowL = rowM + 64;
    float* pm   = rowL + 64;
    float* ps   = pm + 128;

    int hh = blockIdx.y, tid = threadIdx.x;
    int lane = tid & 31, w = tid >> 5;
    int wm = w & 3, wn = w >> 2;
    int la = lane & 3, lr = lane >> 2;
    const float scale = rsqrtf(128.f);

    for (int half = 0; half < 2; half++) {
        int qt = half ? (15 - (int)blockIdx.x) : (int)blockIdx.x;

        for (int e = tid; e < 64 * 64; e += 256) {
            int r = e >> 6, wq = e & 63;
            int t = qt * 64 + r, d = wq * 2;
            const float* src = (d < 64) ? (q + (size_t)t * QLD + hh * 64 + d)
                                        : (qr + (size_t)t * QLD + hh * 64 + (d - 64));
            float2 f = *(const float2*)src;
            uint32_t lo;
            uint32_t hi = splitpackh(f.x, f.y, lo);
            Qh[r * AQ + wq] = hi; Ql[r * AQ + wq] = lo;
        }
        if (tid < 64) { rowM[tid] = -1e30f; rowL[tid] = 0.f; }

        float oacc[8][4];
        #pragma unroll
        for (int nt = 0; nt < 8; nt++)
            #pragma unroll
            for (int c = 0; c < 4; c++) oacc[nt][c] = 0.f;

        int rloc = wm * 16 + lr;

        for (int kt = 0; kt <= qt; kt++) {
            __syncthreads();

            for (int e = tid; e < 64 * 64; e += 256) {
                int r = e >> 6, wq = e & 63;
                int t = kt * 64 + r, d = wq * 2;
                const float* src = (d < 64) ? (k + (size_t)t * QLD + hh * 64 + d)
                                            : (kr + (size_t)t * KRLD + (d - 64));
                float2 f = *(const float2*)src;
                Kh[r * AQ + wq] = pack2h(f.x, f.y);
            }
            for (int e = tid; e < 64 * 32; e += 256) {
                int kp = e >> 6, d = e & 63;
                float v0 = v[(size_t)(kt * 64 + 2 * kp) * QLD + hh * 64 + d];
                float v1 = v[(size_t)(kt * 64 + 2 * kp + 1) * QLD + hh * 64 + d];
                Vh[d * AV + kp] = pack2h(v0, v1);
            }
            __syncthreads();

            float sacc[4][4];
            #pragma unroll
            for (int nt = 0; nt < 4; nt++)
                #pragma unroll
                for (int c = 0; c < 4; c++) sacc[nt][c] = 0.f;

            #pragma unroll
            for (int kk = 0; kk < 8; kk++) {
                int w0 = kk * 8 + la;
                uint32_t ah[4], al2[4];
                ah[0] = Qh[rloc * AQ + w0];        ah[1] = Qh[(rloc + 8) * AQ + w0];
                ah[2] = Qh[rloc * AQ + w0 + 4];    ah[3] = Qh[(rloc + 8) * AQ + w0 + 4];
                al2[0] = Ql[rloc * AQ + w0];       al2[1] = Ql[(rloc + 8) * AQ + w0];
                al2[2] = Ql[rloc * AQ + w0 + 4];   al2[3] = Ql[(rloc + 8) * AQ + w0 + 4];
                #pragma unroll
                for (int nt = 0; nt < 4; nt++) {
                    int n0 = wn * 32 + nt * 8 + lr;
                    uint32_t bh[2] = { Kh[n0 * AQ + w0], Kh[n0 * AQ + w0 + 4] };
                    mma16816(sacc[nt], ah, bh);
                    mma16816(sacc[nt], al2, bh);
                }
            }

            int rgA = qt * 64 + rloc, rgB = rgA + 8;
            #pragma unroll
            for (int nt = 0; nt < 4; nt++) {
                int cg = kt * 64 + wn * 32 + nt * 8 + 2 * la;
                sacc[nt][0] = (cg     <= rgA) ? sacc[nt][0] * scale : -1e30f;
                sacc[nt][1] = (cg + 1 <= rgA) ? sacc[nt][1] * scale : -1e30f;
                sacc[nt][2] = (cg     <= rgB) ? sacc[nt][2] * scale : -1e30f;
                sacc[nt][3] = (cg + 1 <= rgB) ? sacc[nt][3] * scale : -1e30f;
            }

            float mA = -1e30f, mB = -1e30f;
            #pragma unroll
            for (int nt = 0; nt < 4; nt++) {
                mA = fmaxf(mA, fmaxf(sacc[nt][0], sacc[nt][1]));
                mB = fmaxf(mB, fmaxf(sacc[nt][2], sacc[nt][3]));
            }
            mA = fmaxf(mA, __shfl_xor_sync(0xffffffff, mA, 1));
            mA = fmaxf(mA, __shfl_xor_sync(0xffffffff, mA, 2));
            mB = fmaxf(mB, __shfl_xor_sync(0xffffffff, mB, 1));
            mB = fmaxf(mB, __shfl_xor_sync(0xffffffff, mB, 2));
            if (la == 0) { pm[wn * 64 + rloc] = mA; pm[wn * 64 + rloc + 8] = mB; }
            __syncthreads();

            float moA = rowM[rloc], moB = rowM[rloc + 8];
            float mnA = fmaxf(moA, fmaxf(pm[rloc], pm[64 + rloc]));
            float mnB = fmaxf(moB, fmaxf(pm[rloc + 8], pm[64 + rloc + 8]));
            float alA = __expf(moA - mnA), alB = __expf(moB - mnB);

            float sA = 0.f, sB = 0.f;
            #pragma unroll
            for (int nt = 0; nt < 4; nt++) {
                sacc[nt][0] = __expf(sacc[nt][0] - mnA);
                sacc[nt][1] = __expf(sacc[nt][1] - mnA);
                sacc[nt][2] = __expf(sacc[nt][2] - mnB);
                sacc[nt][3] = __expf(sacc[nt][3] - mnB);
                sA += sacc[nt][0] + sacc[nt][1];
                sB += sacc[nt][2] + sacc[nt][3];
            }
            #pragma unroll
            for (int nt = 0; nt < 8; nt++) {
                oacc[nt][0] *= alA; oacc[nt][1] *= alA;
                oacc[nt][2] *= alB; oacc[nt][3] *= alB;
            }
            sA += __shfl_xor_sync(0xffffffff, sA, 1);
            sA += __shfl_xor_sync(0xffffffff, sA, 2);
            sB += __shfl_xor_sync(0xffffffff, sB, 1);
            sB += __shfl_xor_sync(0xffffffff, sB, 2);
            __syncthreads();
            if (la == 0) { ps[wn * 64 + rloc] = sA; ps[wn * 64 + rloc + 8] = sB; }
            if (wn == 0 && la == 0) { rowM[rloc] = mnA; rowM[rloc + 8] = mnB; }
            __syncthreads();
            if (wn == 0 && la == 0) {
                rowL[rloc]     = rowL[rloc]     * alA + ps[rloc]     + ps[64 + rloc];
                rowL[rloc + 8] = rowL[rloc + 8] * alB + ps[rloc + 8] + ps[64 + rloc + 8];
            }

            #pragma unroll
            for (int kc = 0; kc < 2; kc++) {
                uint32_t phi[4];
                phi[0] = pack2h(sacc[2*kc][0],   sacc[2*kc][1]);
                phi[1] = pack2h(sacc[2*kc][2],   sacc[2*kc][3]);
                phi[2] = pack2h(sacc[2*kc+1][0], sacc[2*kc+1][1]);
                phi[3] = pack2h(sacc[2*kc+1][2], sacc[2*kc+1][3]);
                int kw = wn * 16 + kc * 8 + la;
                #pragma unroll
                for (int nt = 0; nt < 8; nt++) {
                    int d0 = nt * 8 + lr;
                    uint32_t bh[2] = { Vh[d0 * AV + kw], Vh[d0 * AV + kw + 4] };
                    mma16816(oacc[nt], phi, bh);
                }
            }
        }

        __syncthreads();
        if (wn == 0) {
            #pragma unroll
            for (int nt = 0; nt < 8; nt++) {
                int c0 = nt * 8 + 2 * la;
                Ob[rloc * 65 + c0]         = oacc[nt][0];
                Ob[rloc * 65 + c0 + 1]     = oacc[nt][1];
                Ob[(rloc+8) * 65 + c0]     = oacc[nt][2];
                Ob[(rloc+8) * 65 + c0 + 1] = oacc[nt][3];
            }
        }
        __syncthreads();
        if (wn == 1) {
            #pragma unroll
            for (int nt = 0; nt < 8; nt++) {
                int c0 = nt * 8 + 2 * la;
                Ob[rloc * 65 + c0]         += oacc[nt][0];
                Ob[rloc * 65 + c0 + 1]     += oacc[nt][1];
                Ob[(rloc+8) * 65 + c0]     += oacc[nt][2];
                Ob[(rloc+8) * 65 + c0 + 1] += oacc[nt][3];
            }
        }
        __syncthreads();
        for (int e = tid; e < 64 * 32; e += 256) {
            int r = e >> 5, d2 = (e & 31) * 2;
            float v0 = Ob[r * 65 + d2]     / rowL[r];
            float v1 = Ob[r * 65 + d2 + 1] / rowL[r];
            uint32_t lo;
            uint32_t hi = splitpackh(v0, v1, lo);
            size_t o = (size_t)(qt * 64 + r) * DD + hh * 64 + d2;
            *(uint32_t*)(atthi + o) = hi;
            *(uint32_t*)(attlo + o) = lo;
        }
        __syncthreads();
    }
}

// ---- host orchestration -------------------------------------------------------------
#define SMEMSZ(BM,BN) (4 * (2*(BM) + (BN)) * 64)   // D=4 stages, stage=(2BM+BN)*32 halves

template<int BM, int BN>
static void gemmT(const h16* Ah, const h16* Al, int lda, const h16* Bh,
                  float* C, int ldc, const float* R, h16* Ch, h16* Cl,
                  int M, int N, int K, int relu) {
    dim3 grid(N / BN, M / BM);
    gemm_mma<BM, BN><<<grid, 256, SMEMSZ(BM, BN)>>>(Ah, Al, lda, Bh, C, ldc, R, Ch, Cl, K, relu);
}

extern "C" void kernel_launch(void* const* d_in, const int* in_sizes, int n_in,
                              void* d_out, int out_size) {
    const int*   idx     = (const int*)  d_in[0];
    const float* wte     = (const float*)d_in[1];
    const float* wqdown  = (const float*)d_in[2];
    const float* wqup    = (const float*)d_in[3];
    const float* wqr     = (const float*)d_in[4];
    const float* wkvdown = (const float*)d_in[5];
    const float* wkup    = (const float*)d_in[6];
    const float* wvup    = (const float*)d_in[7];
    const float* wkr     = (const float*)d_in[8];
    const float* wo      = (const float*)d_in[9];
    const float* fc1     = (const float*)d_in[10];
    const float* fc2     = (const float*)d_in[11];
    const float* lm_head = (const float*)d_in[12];
    float* out = (float*)d_out;

    cudaFuncSetAttribute((void*)gemm_mma<128,128>, cudaFuncAttributeMaxDynamicSharedMemorySize, SMEMSZ(128,128));
    cudaFuncSetAttribute((void*)gemm_mma<128,64>,  cudaFuncAttributeMaxDynamicSharedMemorySize, SMEMSZ(128,64));
    cudaFuncSetAttribute((void*)gemm_mma<64,128>,  cudaFuncAttributeMaxDynamicSharedMemorySize, SMEMSZ(64,128));
    cudaFuncSetAttribute((void*)attn_mma,          cudaFuncAttributeMaxDynamicSharedMemorySize, ATTSM);

    void* p;
    cudaGetSymbolAddress(&p, g_x);      float* x    = (float*)p;
    cudaGetSymbolAddress(&p, g_c1);     float* c1f  = (float*)p;
    cudaGetSymbolAddress(&p, g_qqr);    float* qqr  = (float*)p;
    cudaGetSymbolAddress(&p, g_kv);     float* kv   = (float*)p;
    cudaGetSymbolAddress(&p, g_c1h);    h16* c1h    = (h16*)p;
    cudaGetSymbolAddress(&p, g_c1l);    h16* c1l    = (h16*)p;
    cudaGetSymbolAddress(&p, g_nx_hi);  h16* nxh    = (h16*)p;
    cudaGetSymbolAddress(&p, g_nx_lo);  h16* nxl    = (h16*)p;
    cudaGetSymbolAddress(&p, g_att_hi); h16* atth   = (h16*)p;
    cudaGetSymbolAddress(&p, g_att_lo); h16* attl   = (h16*)p;
    cudaGetSymbolAddress(&p, g_tmp_hi); h16* tmph   = (h16*)p;
    cudaGetSymbolAddress(&p, g_tmp_lo); h16* tmpl   = (h16*)p;
    cudaGetSymbolAddress(&p, g_x_hi);   h16* xh     = (h16*)p;
    cudaGetSymbolAddress(&p, g_x_lo);   h16* xl     = (h16*)p;
    cudaGetSymbolAddress(&p, g_wh);     h16* wh     = (h16*)p;

    // ---- fused weight layout ----
    cvt_h_s<<<2048,256>>>(wqdown,  wh+OFF_W1, NL*512*1024, 19, W1SZ, 0);
    cvt_h_s<<<2048,256>>>(wkvdown, wh+OFF_W1, NL*512*1024, 19, W1SZ, 512*1024);
    cvt_h_s<<<2048,256>>>(wkr,     wh+OFF_W1, NL*64*1024,  16, W1SZ, 1024*1024);
    cvt_h_s<<<2048,256>>>(wqup, wh+OFF_W2A, NL*1024*512, 19, W2SZ, 0);
    cvt_h_s<<<2048,256>>>(wqr,  wh+OFF_W2A, NL*1024*512, 19, W2SZ, 1024*512);
    cvt_h_s<<<2048,256>>>(wkup, wh+OFF_W2B, NL*1024*512, 19, W2SZ, 0);
    cvt_h_s<<<2048,256>>>(wvup, wh+OFF_W2B, NL*1024*512, 19, W2SZ, 1024*512);
    cvt_h_s<<<2048,256>>>(wo,      wh+OFF_WO,  NL*DD*DD, 20, DD*DD, 0);
    cvt_h_s<<<2048,256>>>(fc1,     wh+OFF_FC1, NL*FF*DD, 22, FF*DD, 0);
    cvt_h_s<<<2048,256>>>(fc2,     wh+OFF_FC2, NL*DD*FF, 22, DD*FF, 0);
    cvt_h_s<<<2048,256>>>(lm_head, wh+OFF_LMH, VV*DD,    30, VV*DD, 0);

    embed_kernel<<<TT, 256>>>(idx, wte, x);
    rmsnorm_kernel<<<TT, 256>>>(x, x, nullptr, nullptr);

    for (int l = 0; l < NL; l++) {
        const h16* w1  = wh + OFF_W1  + (size_t)l * W1SZ;
        const h16* w2a = wh + OFF_W2A + (size_t)l * W2SZ;
        const h16* w2b = wh + OFF_W2B + (size_t)l * W2SZ;
        const h16* wol = wh + OFF_WO  + (size_t)l * DD*DD;
        const h16* f1  = wh + OFF_FC1 + (size_t)l * FF*DD;
        const h16* f2  = wh + OFF_FC2 + (size_t)l * DD*FF;

        rmsnorm_kernel<<<TT, 256>>>(x, nullptr, nxh, nxl);

        gemmT<128,64>(nxh, nxl, DD, w1, c1f, 1088, nullptr, c1h, c1l, TT, 1088, DD, 0);
        gemmT<128,128>(c1h, c1l, 1088, w2a, qqr, 2048, nullptr, nullptr, nullptr, TT, 2048, LAT, 0);
        gemmT<128,128>(c1h + 512, c1l + 512, 1088, w2b, kv, 2048, nullptr, nullptr, nullptr, TT, 2048, LAT, 0);

        rope_kernel<<<dim3(TT, 17), 32>>>(qqr, c1f);

        attn_mma<<<dim3(8, 16), 256, ATTSM>>>(qqr, qqr + 1024, kv, kv + 1024, c1f + 1024, atth, attl);

        gemmT<64,128>(atth, attl, DD, wol, x, DD, x, nullptr, nullptr, TT, DD, DD, 0);

        rmsnorm_kernel<<<TT, 256>>>(x, nullptr, nxh, nxl);
        gemmT<128,128>(nxh, nxl, DD, f1, nullptr, FF, nullptr, tmph, tmpl, TT, FF, DD, 1);
        bool last = (l == NL - 1);
        gemmT<64,128>(tmph, tmpl, FF, f2, x, DD, x,
                      last ? xh : nullptr, last ? xl : nullptr, TT, DD, FF, 0);
    }

    gemmT<128,128>(xh, xl, DD, wh + OFF_LMH, out, VV, nullptr, nullptr, nullptr, TT, VV, DD, 0);
}

// round 12
// speedup vs baseline: 17.1683x; 1.2902x over previous
#include <cuda_runtime.h>
#include <cuda_fp16.h>
#include <cstdint>
#include <math.h>

#define TT 1024
#define DD 1024
#define HN 16
#define HD 64
#define LAT 512
#define RDIM 64
#define NL 8
#define VV 32000
#define FF 4096

typedef __half h16;

// ---- fused weight layout (single fp16 buffer; weights are always B operand) ---
#define W1SZ   (1088*1024)
#define W2SZ   (2048*512)
#define OFF_W1  0
#define OFF_W2A (OFF_W1  + NL*W1SZ)
#define OFF_W2B (OFF_W2A + NL*W2SZ)
#define OFF_WO  (OFF_W2B + NL*W2SZ)
#define OFF_FC1 (OFF_WO  + NL*DD*DD)
#define OFF_FC2 (OFF_FC1 + NL*FF*DD)
#define OFF_LMH (OFF_FC2 + NL*DD*FF)
#define TOTAL_W (OFF_LMH + VV*DD)

__device__ __align__(256) h16 g_wh[TOTAL_W];

// ---- activation scratch (plain fp16 A operands) --------------------------------
__device__ __align__(256) float g_x  [TT*DD];
__device__ __align__(256) float g_c1 [TT*1088];     // ql | ckv | kr (float)
__device__ __align__(256) float g_qqr[TT*2048];     // q | qr
__device__ __align__(256) float g_kv [TT*2048];     // k | v
__device__ __align__(256) h16 g_c1h[TT*1088];
__device__ __align__(256) h16 g_nxh[TT*DD];
__device__ __align__(256) h16 g_atth[TT*DD];
__device__ __align__(256) h16 g_tmph[TT*FF];
__device__ __align__(256) h16 g_xh [TT*DD];

// ---- helpers -----------------------------------------------------------------
__device__ __forceinline__ uint32_t packh(h16 a, h16 b) {
    __half2 t = __halves2half2(a, b);
    return *reinterpret_cast<uint32_t*>(&t);
}
__device__ __forceinline__ uint32_t pack2h(float x, float y) {
    __half2 t = __floats2half2_rn(x, y);
    return *reinterpret_cast<uint32_t*>(&t);
}
__device__ __forceinline__ uint32_t splitpackh(float x, float y, uint32_t& lo) {
    h16 hx = __float2half_rn(x), hy = __float2half_rn(y);
    h16 lx = __float2half_rn(x - __half2float(hx));
    h16 ly = __float2half_rn(y - __half2float(hy));
    lo = packh(lx, ly);
    return packh(hx, hy);
}

__device__ __forceinline__ void cp16(uint32_t dst, const void* src) {
    asm volatile("cp.async.cg.shared.global [%0], [%1], 16;" :: "r"(dst), "l"(src));
}
#define CP_COMMIT() asm volatile("cp.async.commit_group;" ::: "memory")
template<int N> __device__ __forceinline__ void cp_wait() {
    asm volatile("cp.async.wait_group %0;" :: "n"(N) : "memory");
}

__device__ __forceinline__ void mma16816(float* c, const uint32_t* a, const uint32_t* b) {
    asm volatile(
        "mma.sync.aligned.m16n8k16.row.col.f32.f16.f16.f32 "
        "{%0,%1,%2,%3}, {%4,%5,%6,%7}, {%8,%9}, {%0,%1,%2,%3};"
        : "+f"(c[0]), "+f"(c[1]), "+f"(c[2]), "+f"(c[3])
        : "r"(a[0]), "r"(a[1]), "r"(a[2]), "r"(a[3]), "r"(b[0]), "r"(b[1]));
}

__device__ __forceinline__ void ldm4(uint32_t* r, uint32_t addr) {
    asm volatile("ldmatrix.sync.aligned.m8n8.x4.shared.b16 {%0,%1,%2,%3}, [%4];"
        : "=r"(r[0]), "=r"(r[1]), "=r"(r[2]), "=r"(r[3]) : "r"(addr));
}

__device__ __forceinline__ int sadr(int row, int w) {
    return row * 16 + (((w >> 2) ^ (row & 3)) << 2) + (w & 3);
}

// ---- strided weight conversion (single fp16 output) ----------------------------
__global__ void cvt_h_s(const float* __restrict__ in, h16* __restrict__ hi,
                        int n, int cshift, int dstride, int doff) {
    int i = (blockIdx.x * blockDim.x + threadIdx.x) * 8;
    int stride = gridDim.x * blockDim.x * 8;
    int cmask = (1 << cshift) - 1;
    for (; i < n; i += stride) {
        size_t di = (size_t)(i >> cshift) * dstride + doff + (i & cmask);
        float4 a = *(const float4*)(in + i);
        float4 b = *(const float4*)(in + i + 4);
        *(uint4*)(hi + di) = make_uint4(pack2h(a.x, a.y), pack2h(a.z, a.w),
                                        pack2h(b.x, b.y), pack2h(b.z, b.w));
    }
}

// ---- embedding ------------------------------------------------------------------
__global__ void embed_kernel(const int* __restrict__ idx, const float* __restrict__ wte,
                             float* __restrict__ x) {
    int t = blockIdx.x;
    int row = idx[t];
    float4 v = *(const float4*)(wte + (size_t)row * DD + threadIdx.x * 4);
    *(float4*)(x + (size_t)t * DD + threadIdx.x * 4) = v;
}

// ---- rmsnorm ----------------------------------------------------------------------
__global__ void rmsnorm_kernel(const float* __restrict__ in, float* __restrict__ out,
                               h16* __restrict__ ohi) {
    __shared__ float red[8];
    int row = blockIdx.x, tid = threadIdx.x;
    float4 v = *(const float4*)(in + (size_t)row * DD + tid * 4);
    float s = v.x*v.x + v.y*v.y + v.z*v.z + v.w*v.w;
    #pragma unroll
    for (int o = 16; o > 0; o >>= 1) s += __shfl_xor_sync(0xffffffff, s, o);
    if ((tid & 31) == 0) red[tid >> 5] = s;
    __syncthreads();
    if (tid < 8) {
        float t2 = red[tid];
        #pragma unroll
        for (int o = 4; o > 0; o >>= 1) t2 += __shfl_xor_sync(0xff, t2, o);
        if (tid == 0) red[0] = t2;
    }
    __syncthreads();
    float r = rsqrtf(red[0] / (float)DD + 1e-5f);
    float4 o4 = make_float4(v.x*r, v.y*r, v.z*r, v.w*r);
    if (out) *(float4*)(out + (size_t)row * DD + tid * 4) = o4;
    if (ohi) {
        size_t b = (size_t)row * DD + tid * 4;
        *(uint2*)(ohi + b) = make_uint2(pack2h(o4.x, o4.y), pack2h(o4.z, o4.w));
    }
}

// ---- RoPE (fused qr + kr: blockIdx.y==16 -> kr) --------------------------------------
__global__ void rope_kernel(float* __restrict__ qqr, float* __restrict__ c1) {
    int t = blockIdx.x, h = blockIdx.y, j = threadIdx.x;
    float f = powf(10000.f, -(float)j / 32.f);
    float sv, cv;
    sincosf((float)t * f, &sv, &cv);
    float* p = (h < 16) ? (qqr + (size_t)t * 2048 + 1024 + h * RDIM)
                        : (c1 + (size_t)t * 1088 + 1024);
    float x0 = p[j], x1 = p[j + 32];
    p[j]      = x0 * cv - x1 * sv;
    p[j + 32] = x1 * cv + x0 * sv;
}

// ---- fp16 1-pass NT GEMM, 4-stage cp.async pipeline + ldmatrix ----------------------
template<int BM, int BN>
__global__ void __launch_bounds__(256) gemm_mma(
    const h16* __restrict__ Ah, int lda,
    const h16* __restrict__ Bh,
    float* __restrict__ C, int ldc, const float* __restrict__ Rres,
    h16* __restrict__ Chi,
    int K, int relu)
{
    extern __shared__ uint32_t smw[];
    constexpr int AT  = BM * 16;
    constexpr int BT  = BN * 16;
    constexpr int STG = AT + BT;
    constexpr int NT  = BN / 16;
    constexpr int MT  = BM / 64;
    constexpr int D   = 4;

    int tid = threadIdx.x, lane = tid & 31, w = tid >> 5;
    int wm = w & 3, wn = w >> 2;
    int bm = blockIdx.y * BM, bn = blockIdx.x * BN;
    int la = lane & 3, lr = lane >> 2;

    int rowl = (lane & 7) | (((lane >> 3) & 1) << 3);
    int csel = (lane >> 4) << 2;

    uint32_t sbase = (uint32_t)__cvta_generic_to_shared(smw);

    auto load_stage = [&](int i, int st) {
        int k0 = i * 32;
        uint32_t so = sbase + (uint32_t)(st * STG) * 4;
        #pragma unroll
        for (int e0 = 0; e0 < BM * 4; e0 += 256) {
            int e = e0 + tid;
            int r = e >> 2, kq = e & 3;
            size_t g = (size_t)(bm + r) * lda + k0 + kq * 8;
            uint32_t d = so + (uint32_t)(r * 16 + ((kq ^ (r & 3)) << 2)) * 4;
            cp16(d, Ah + g);
        }
        #pragma unroll
        for (int e0 = 0; e0 < BN * 4; e0 += 256) {
            int e = e0 + tid;
            int r = e >> 2, kq = e & 3;
            size_t g = (size_t)(bn + r) * K + k0 + kq * 8;
            uint32_t d = so + (uint32_t)(AT + r * 16 + ((kq ^ (r & 3)) << 2)) * 4;
            cp16(d, Bh + g);
        }
        CP_COMMIT();
    };

    float acc[MT][NT][4];
    #pragma unroll
    for (int mt = 0; mt < MT; mt++)
        #pragma unroll
        for (int nt = 0; nt < NT; nt++)
            #pragma unroll
            for (int c = 0; c < 4; c++) acc[mt][nt][c] = 0.f;

    int nk = K >> 5;
    #pragma unroll
    for (int s = 0; s < D - 1; s++) load_stage(s, s);

    for (int i = 0; i < nk; i++) {
        cp_wait<D - 2>();
        __syncthreads();
        if (i + D - 1 < nk) load_stage(i + D - 1, (i + D - 1) % D);
        else                CP_COMMIT();

        uint32_t SaB = sbase + (uint32_t)((i % D) * STG) * 4;
        uint32_t SbB = SaB + (uint32_t)AT * 4;
        #pragma unroll
        for (int ks = 0; ks < 2; ks++) {
            int w0 = ks * 8 + csel;
            uint32_t ah[MT][4];
            #pragma unroll
            for (int mt = 0; mt < MT; mt++) {
                uint32_t aaddr = SaB + (uint32_t)sadr(wm * (BM / 4) + mt * 16 + rowl, w0) * 4;
                ldm4(ah[mt], aaddr);
            }
            #pragma unroll
            for (int nt2 = 0; nt2 < NT / 2; nt2++) {
                uint32_t baddr = SbB + (uint32_t)sadr(wn * (BN / 2) + nt2 * 16 + rowl, w0) * 4;
                uint32_t bb[4];
                ldm4(bb, baddr);
                uint32_t b0[2] = { bb[0], bb[2] };
                uint32_t b1[2] = { bb[1], bb[3] };
                #pragma unroll
                for (int mt = 0; mt < MT; mt++) {
                    mma16816(acc[mt][2 * nt2],     ah[mt], b0);
                    mma16816(acc[mt][2 * nt2 + 1], ah[mt], b1);
                }
            }
        }
    }

    #pragma unroll
    for (int mt = 0; mt < MT; mt++) {
        #pragma unroll
        for (int nt = 0; nt < NT; nt++) {
            int col = bn + wn * (BN / 2) + nt * 8 + la * 2;
            #pragma unroll
            for (int half = 0; half < 2; half++) {
                int row = bm + wm * (BM / 4) + mt * 16 + lr + half * 8;
                float v0 = acc[mt][nt][half * 2 + 0];
                float v1 = acc[mt][nt][half * 2 + 1];
                size_t base = (size_t)row * ldc + col;
                if (Rres) {
                    float2 rr = *(const float2*)(Rres + base);
                    v0 += rr.x; v1 += rr.y;
                }
                if (relu) { v0 = fmaxf(v0, 0.f); v1 = fmaxf(v1, 0.f); }
                if (C) *(float2*)(C + base) = make_float2(v0, v1);
                if (Chi) *(uint32_t*)(Chi + base) = pack2h(v0, v1);
            }
        }
    }
}

// ---- flash attention, fp16 (Q split 2-pass, K/V/P plain) -----------------------------
#define QLD 2048
#define KRLD 1088
#define AQ 68
#define AV 36
#define ATTSM ((3*64*AQ + 64*AV) * 4 + 64*65*4 + (64+64+128+128) * 4)

__global__ void __launch_bounds__(256, 1) attn_mma(
    const float* __restrict__ q,  const float* __restrict__ qr,
    const float* __restrict__ k,  const float* __restrict__ v,
    const float* __restrict__ kr,
    h16* __restrict__ atth)
{
    extern __shared__ uint32_t sw[];
    uint32_t* Qh = sw;
    uint32_t* Ql = Qh + 64 * AQ;
    uint32_t* Kh = Ql + 64 * AQ;
    uint32_t* Vh = Kh + 64 * AQ;
    float* Ob   = (float*)(Vh + 64 * AV);
    float* rowM = Ob + 64 * 65;
    float* rowL = rowM + 64;
    float* pm   = rowL + 64;
    float* ps   = pm + 128;

    int hh = blockIdx.y, tid = threadIdx.x;
    int lane = tid & 31, w = tid >> 5;
    int wm = w & 3, wn = w >> 2;
    int la = lane & 3, lr = lane >> 2;
    const float scale = rsqrtf(128.f);

    for (int half = 0; half < 2; half++) {
        int qt = half ? (15 - (int)blockIdx.x) : (int)blockIdx.x;

        for (int e = tid; e < 64 * 64; e += 256) {
            int r = e >> 6, wq = e & 63;
            int t = qt * 64 + r, d = wq * 2;
            const float* src = (d < 64) ? (q + (size_t)t * QLD + hh * 64 + d)
                                        : (qr + (size_t)t * QLD + hh * 64 + (d - 64));
            float2 f = *(const float2*)src;
            uint32_t lo;
            uint32_t hi = splitpackh(f.x, f.y, lo);
            Qh[r * AQ + wq] = hi; Ql[r * AQ + wq] = lo;
        }
        if (tid < 64) { rowM[tid] = -1e30f; rowL[tid] = 0.f; }

        float oacc[8][4];
        #pragma unroll
        for (int nt = 0; nt < 8; nt++)
            #pragma unroll
            for (int c = 0; c < 4; c++) oacc[nt][c] = 0.f;

        int rloc = wm * 16 + lr;

        for (int kt = 0; kt <= qt; kt++) {
            __syncthreads();

            for (int e = tid; e < 64 * 64; e += 256) {
                int r = e >> 6, wq = e & 63;
                int t = kt * 64 + r, d = wq * 2;
                const float* src = (d < 64) ? (k + (size_t)t * QLD + hh * 64 + d)
                                            : (kr + (size_t)t * KRLD + (d - 64));
                float2 f = *(const float2*)src;
                Kh[r * AQ + wq] = pack2h(f.x, f.y);
            }
            for (int e = tid; e < 64 * 32; e += 256) {
                int kp = e >> 6, d = e & 63;
                float v0 = v[(size_t)(kt * 64 + 2 * kp) * QLD + hh * 64 + d];
                float v1 = v[(size_t)(kt * 64 + 2 * kp + 1) * QLD + hh * 64 + d];
                Vh[d * AV + kp] = pack2h(v0, v1);
            }
            __syncthreads();

            float sacc[4][4];
            #pragma unroll
            for (int nt = 0; nt < 4; nt++)
                #pragma unroll
                for (int c = 0; c < 4; c++) sacc[nt][c] = 0.f;

            #pragma unroll
            for (int kk = 0; kk < 8; kk++) {
                int w0 = kk * 8 + la;
                uint32_t ah[4], al2[4];
                ah[0] = Qh[rloc * AQ + w0];        ah[1] = Qh[(rloc + 8) * AQ + w0];
                ah[2] = Qh[rloc * AQ + w0 + 4];    ah[3] = Qh[(rloc + 8) * AQ + w0 + 4];
                al2[0] = Ql[rloc * AQ + w0];       al2[1] = Ql[(rloc + 8) * AQ + w0];
                al2[2] = Ql[rloc * AQ + w0 + 4];   al2[3] = Ql[(rloc + 8) * AQ + w0 + 4];
                #pragma unroll
                for (int nt = 0; nt < 4; nt++) {
                    int n0 = wn * 32 + nt * 8 + lr;
                    uint32_t bh[2] = { Kh[n0 * AQ + w0], Kh[n0 * AQ + w0 + 4] };
                    mma16816(sacc[nt], ah, bh);
                    mma16816(sacc[nt], al2, bh);
                }
            }

            int rgA = qt * 64 + rloc, rgB = rgA + 8;
            #pragma unroll
            for (int nt = 0; nt < 4; nt++) {
                int cg = kt * 64 + wn * 32 + nt * 8 + 2 * la;
                sacc[nt][0] = (cg     <= rgA) ? sacc[nt][0] * scale : -1e30f;
                sacc[nt][1] = (cg + 1 <= rgA) ? sacc[nt][1] * scale : -1e30f;
                sacc[nt][2] = (cg     <= rgB) ? sacc[nt][2] * scale : -1e30f;
                sacc[nt][3] = (cg + 1 <= rgB) ? sacc[nt][3] * scale : -1e30f;
            }

            float mA = -1e30f, mB = -1e30f;
            #pragma unroll
            for (int nt = 0; nt < 4; nt++) {
                mA = fmaxf(mA, fmaxf(sacc[nt][0], sacc[nt][1]));
                mB = fmaxf(mB, fmaxf(sacc[nt][2], sacc[nt][3]));
            }
            mA = fmaxf(mA, __shfl_xor_sync(0xffffffff, mA, 1));
            mA = fmaxf(mA, __shfl_xor_sync(0xffffffff, mA, 2));
            mB = fmaxf(mB, __shfl_xor_sync(0xffffffff, mB, 1));
            mB = fmaxf(mB, __shfl_xor_sync(0xffffffff, mB, 2));
            if (la == 0) { pm[wn * 64 + rloc] = mA; pm[wn * 64 + rloc + 8] = mB; }
            __syncthreads();

            float moA = rowM[rloc], moB = rowM[rloc + 8];
            float mnA = fmaxf(moA, fmaxf(pm[rloc], pm[64 + rloc]));
            float mnB = fmaxf(moB, fmaxf(pm[rloc + 8], pm[64 + rloc + 8]));
            float alA = __expf(moA - mnA), alB = __expf(moB - mnB);

            float sA = 0.f, sB = 0.f;
            #pragma unroll
            for (int nt = 0; nt < 4; nt++) {
                sacc[nt][0] = __expf(sacc[nt][0] - mnA);
                sacc[nt][1] = __expf(sacc[nt][1] - mnA);
                sacc[nt][2] = __expf(sacc[nt][2] - mnB);
                sacc[nt][3] = __expf(sacc[nt][3] - mnB);
                sA += sacc[nt][0] + sacc[nt][1];
                sB += sacc[nt][2] + sacc[nt][3];
            }
            #pragma unroll
            for (int nt = 0; nt < 8; nt++) {
                oacc[nt][0] *= alA; oacc[nt][1] *= alA;
                oacc[nt][2] *= alB; oacc[nt][3] *= alB;
            }
            sA += __shfl_xor_sync(0xffffffff, sA, 1);
            sA += __shfl_xor_sync(0xffffffff, sA, 2);
            sB += __shfl_xor_sync(0xffffffff, sB, 1);
            sB += __shfl_xor_sync(0xffffffff, sB, 2);
            __syncthreads();
            if (la == 0) { ps[wn * 64 + rloc] = sA; ps[wn * 64 + rloc + 8] = sB; }
            if (wn == 0 && la == 0) { rowM[rloc] = mnA; rowM[rloc + 8] = mnB; }
            __syncthreads();
            if (wn == 0 && la == 0) {
                rowL[rloc]     = rowL[rloc]     * alA + ps[rloc]     + ps[64 + rloc];
                rowL[rloc + 8] = rowL[rloc + 8] * alB + ps[rloc + 8] + ps[64 + rloc + 8];
            }

            #pragma unroll
            for (int kc = 0; kc < 2; kc++) {
                uint32_t phi[4];
                phi[0] = pack2h(sacc[2*kc][0],   sacc[2*kc][1]);
                phi[1] = pack2h(sacc[2*kc][2],   sacc[2*kc][3]);
                phi[2] = pack2h(sacc[2*kc+1][0], sacc[2*kc+1][1]);
                phi[3] = pack2h(sacc[2*kc+1][2], sacc[2*kc+1][3]);
                int kw = wn * 16 + kc * 8 + la;
                #pragma unroll
                for (int nt = 0; nt < 8; nt++) {
                    int d0 = nt * 8 + lr;
                    uint32_t bh[2] = { Vh[d0 * AV + kw], Vh[d0 * AV + kw + 4] };
                    mma16816(oacc[nt], phi, bh);
                }
            }
        }

        __syncthreads();
        if (wn == 0) {
            #pragma unroll
            for (int nt = 0; nt < 8; nt++) {
                int c0 = nt * 8 + 2 * la;
                Ob[rloc * 65 + c0]         = oacc[nt][0];
                Ob[rloc * 65 + c0 + 1]     = oacc[nt][1];
                Ob[(rloc+8) * 65 + c0]     = oacc[nt][2];
                Ob[(rloc+8) * 65 + c0 + 1] = oacc[nt][3];
            }
        }
        __syncthreads();
        if (wn == 1) {
            #pragma unroll
            for (int nt = 0; nt < 8; nt++) {
                int c0 = nt * 8 + 2 * la;
                Ob[rloc * 65 + c0]         += oacc[nt][0];
                Ob[rloc * 65 + c0 + 1]     += oacc[nt][1];
                Ob[(rloc+8) * 65 + c0]     += oacc[nt][2];
                Ob[(rloc+8) * 65 + c0 + 1] += oacc[nt][3];
            }
        }
        __syncthreads();
        for (int e = tid; e < 64 * 32; e += 256) {
            int r = e >> 5, d2 = (e & 31) * 2;
            float v0 = Ob[r * 65 + d2]     / rowL[r];
            float v1 = Ob[r * 65 + d2 + 1] / rowL[r];
            size_t o = (size_t)(qt * 64 + r) * DD + hh * 64 + d2;
            *(uint32_t*)(atth + o) = pack2h(v0, v1);
        }
        __syncthreads();
    }
}

// ---- host orchestration -------------------------------------------------------------
#define SMEMSZ(BM,BN) (4 * ((BM) + (BN)) * 64)   // D=4 stages

template<int BM, int BN>
static void gemmT(const h16* Ah, int lda, const h16* Bh,
                  float* C, int ldc, const float* R, h16* Ch,
                  int M, int N, int K, int relu) {
    dim3 grid(N / BN, M / BM);
    gemm_mma<BM, BN><<<grid, 256, SMEMSZ(BM, BN)>>>(Ah, lda, Bh, C, ldc, R, Ch, K, relu);
}

extern "C" void kernel_launch(void* const* d_in, const int* in_sizes, int n_in,
                              void* d_out, int out_size) {
    const int*   idx     = (const int*)  d_in[0];
    const float* wte     = (const float*)d_in[1];
    const float* wqdown  = (const float*)d_in[2];
    const float* wqup    = (const float*)d_in[3];
    const float* wqr     = (const float*)d_in[4];
    const float* wkvdown = (const float*)d_in[5];
    const float* wkup    = (const float*)d_in[6];
    const float* wvup    = (const float*)d_in[7];
    const float* wkr     = (const float*)d_in[8];
    const float* wo      = (const float*)d_in[9];
    const float* fc1     = (const float*)d_in[10];
    const float* fc2     = (const float*)d_in[11];
    const float* lm_head = (const float*)d_in[12];
    float* out = (float*)d_out;

    cudaFuncSetAttribute((void*)gemm_mma<128,128>, cudaFuncAttributeMaxDynamicSharedMemorySize, SMEMSZ(128,128));
    cudaFuncSetAttribute((void*)gemm_mma<128,64>,  cudaFuncAttributeMaxDynamicSharedMemorySize, SMEMSZ(128,64));
    cudaFuncSetAttribute((void*)gemm_mma<64,128>,  cudaFuncAttributeMaxDynamicSharedMemorySize, SMEMSZ(64,128));
    cudaFuncSetAttribute((void*)attn_mma,          cudaFuncAttributeMaxDynamicSharedMemorySize, ATTSM);

    void* p;
    cudaGetSymbolAddress(&p, g_x);    float* x    = (float*)p;
    cudaGetSymbolAddress(&p, g_c1);   float* c1f  = (float*)p;
    cudaGetSymbolAddress(&p, g_qqr);  float* qqr  = (float*)p;
    cudaGetSymbolAddress(&p, g_kv);   float* kv   = (float*)p;
    cudaGetSymbolAddress(&p, g_c1h);  h16* c1h    = (h16*)p;
    cudaGetSymbolAddress(&p, g_nxh);  h16* nxh    = (h16*)p;
    cudaGetSymbolAddress(&p, g_atth); h16* atth   = (h16*)p;
    cudaGetSymbolAddress(&p, g_tmph); h16* tmph   = (h16*)p;
    cudaGetSymbolAddress(&p, g_xh);   h16* xh     = (h16*)p;
    cudaGetSymbolAddress(&p, g_wh);   h16* wh     = (h16*)p;

    // ---- fused weight layout ----
    cvt_h_s<<<2048,256>>>(wqdown,  wh+OFF_W1, NL*512*1024, 19, W1SZ, 0);
    cvt_h_s<<<2048,256>>>(wkvdown, wh+OFF_W1, NL*512*1024, 19, W1SZ, 512*1024);
    cvt_h_s<<<2048,256>>>(wkr,     wh+OFF_W1, NL*64*1024,  16, W1SZ, 1024*1024);
    cvt_h_s<<<2048,256>>>(wqup, wh+OFF_W2A, NL*1024*512, 19, W2SZ, 0);
    cvt_h_s<<<2048,256>>>(wqr,  wh+OFF_W2A, NL*1024*512, 19, W2SZ, 1024*512);
    cvt_h_s<<<2048,256>>>(wkup, wh+OFF_W2B, NL*1024*512, 19, W2SZ, 0);
    cvt_h_s<<<2048,256>>>(wvup, wh+OFF_W2B, NL*1024*512, 19, W2SZ, 1024*512);
    cvt_h_s<<<2048,256>>>(wo,      wh+OFF_WO,  NL*DD*DD, 20, DD*DD, 0);
    cvt_h_s<<<2048,256>>>(fc1,     wh+OFF_FC1, NL*FF*DD, 22, FF*DD, 0);
    cvt_h_s<<<2048,256>>>(fc2,     wh+OFF_FC2, NL*DD*FF, 22, DD*FF, 0);
    cvt_h_s<<<2048,256>>>(lm_head, wh+OFF_LMH, VV*DD,    30, VV*DD, 0);

    embed_kernel<<<TT, 256>>>(idx, wte, x);
    rmsnorm_kernel<<<TT, 256>>>(x, x, nullptr);

    for (int l = 0; l < NL; l++) {
        const h16* w1  = wh + OFF_W1  + (size_t)l * W1SZ;
        const h16* w2a = wh + OFF_W2A + (size_t)l * W2SZ;
        const h16* w2b = wh + OFF_W2B + (size_t)l * W2SZ;
        const h16* wol = wh + OFF_WO  + (size_t)l * DD*DD;
        const h16* f1  = wh + OFF_FC1 + (size_t)l * FF*DD;
        const h16* f2  = wh + OFF_FC2 + (size_t)l * DD*FF;

        rmsnorm_kernel<<<TT, 256>>>(x, nullptr, nxh);

        gemmT<128,64>(nxh, DD, w1, c1f, 1088, nullptr, c1h, TT, 1088, DD, 0);
        gemmT<128,128>(c1h, 1088, w2a, qqr, 2048, nullptr, nullptr, TT, 2048, LAT, 0);
        gemmT<128,128>(c1h + 512, 1088, w2b, kv, 2048, nullptr, nullptr, TT, 2048, LAT, 0);

        rope_kernel<<<dim3(TT, 17), 32>>>(qqr, c1f);

        attn_mma<<<dim3(8, 16), 256, ATTSM>>>(qqr, qqr + 1024, kv, kv + 1024, c1f + 1024, atth);

        gemmT<64,128>(atth, DD, wol, x, DD, x, nullptr, TT, DD, DD, 0);

        rmsnorm_kernel<<<TT, 256>>>(x, nullptr, nxh);
        gemmT<128,128>(nxh, DD, f1, nullptr, FF, nullptr, tmph, TT, FF, DD, 1);
        bool last = (l == NL - 1);
        gemmT<64,128>(tmph, FF, f2, x, DD, x, last ? xh : nullptr, TT, DD, FF, 0);
    }

    gemmT<128,128>(xh, DD, wh + OFF_LMH, out, VV, nullptr, nullptr, TT, VV, DD, 0);
}

// round 13
// speedup vs baseline: 18.2697x; 1.0642x over previous
#include <cuda_runtime.h>
#include <cuda_fp16.h>
#include <cstdint>
#include <math.h>

#define TT 1024
#define DD 1024
#define HN 16
#define HD 64
#define LAT 512
#define RDIM 64
#define NL 8
#define VV 32000
#define FF 4096

typedef __half h16;

// ---- fused weight layout ---------------------------------------------------
#define W1SZ   (1088*1024)
#define W2SZ   (2048*512)
#define OFF_W1  0
#define OFF_W2A (OFF_W1  + NL*W1SZ)
#define OFF_W2B (OFF_W2A + NL*W2SZ)
#define OFF_WO  (OFF_W2B + NL*W2SZ)
#define OFF_FC1 (OFF_WO  + NL*DD*DD)
#define OFF_FC2 (OFF_FC1 + NL*FF*DD)
#define OFF_LMH (OFF_FC2 + NL*DD*FF)
#define TOTAL_W (OFF_LMH + VV*DD)

__device__ __align__(256) h16 g_wh[TOTAL_W];

// ---- activation scratch (fp16 end-to-end through attention) ------------------
__device__ __align__(256) float g_x [TT*DD];
__device__ __align__(256) h16 g_c1h[TT*1088];      // ql | ckv | kr
__device__ __align__(256) h16 g_qqr[TT*2048];      // q | qr
__device__ __align__(256) h16 g_kv [TT*2048];      // k | v
__device__ __align__(256) h16 g_nxh[TT*DD];
__device__ __align__(256) h16 g_atth[TT*DD];
__device__ __align__(256) h16 g_tmph[TT*FF];
__device__ __align__(256) h16 g_xh [TT*DD];

// ---- helpers -----------------------------------------------------------------
__device__ __forceinline__ uint32_t packh(h16 a, h16 b) {
    __half2 t = __halves2half2(a, b);
    return *reinterpret_cast<uint32_t*>(&t);
}
__device__ __forceinline__ uint32_t pack2h(float x, float y) {
    __half2 t = __floats2half2_rn(x, y);
    return *reinterpret_cast<uint32_t*>(&t);
}

__device__ __forceinline__ void cp16(uint32_t dst, const void* src) {
    asm volatile("cp.async.cg.shared.global [%0], [%1], 16;" :: "r"(dst), "l"(src));
}
#define CP_COMMIT() asm volatile("cp.async.commit_group;" ::: "memory")
template<int N> __device__ __forceinline__ void cp_wait() {
    asm volatile("cp.async.wait_group %0;" :: "n"(N) : "memory");
}

__device__ __forceinline__ void mma16816(float* c, const uint32_t* a, const uint32_t* b) {
    asm volatile(
        "mma.sync.aligned.m16n8k16.row.col.f32.f16.f16.f32 "
        "{%0,%1,%2,%3}, {%4,%5,%6,%7}, {%8,%9}, {%0,%1,%2,%3};"
        : "+f"(c[0]), "+f"(c[1]), "+f"(c[2]), "+f"(c[3])
        : "r"(a[0]), "r"(a[1]), "r"(a[2]), "r"(a[3]), "r"(b[0]), "r"(b[1]));
}

__device__ __forceinline__ void ldm4(uint32_t* r, uint32_t addr) {
    asm volatile("ldmatrix.sync.aligned.m8n8.x4.shared.b16 {%0,%1,%2,%3}, [%4];"
        : "=r"(r[0]), "=r"(r[1]), "=r"(r[2]), "=r"(r[3]) : "r"(addr));
}

__device__ __forceinline__ int sadr(int row, int w) {
    return row * 16 + (((w >> 2) ^ (row & 3)) << 2) + (w & 3);
}

// ---- strided weight conversion ---------------------------------------------------
__global__ void cvt_h_s(const float* __restrict__ in, h16* __restrict__ hi,
                        int n, int cshift, int dstride, int doff) {
    int i = (blockIdx.x * blockDim.x + threadIdx.x) * 8;
    int stride = gridDim.x * blockDim.x * 8;
    int cmask = (1 << cshift) - 1;
    for (; i < n; i += stride) {
        size_t di = (size_t)(i >> cshift) * dstride + doff + (i & cmask);
        float4 a = *(const float4*)(in + i);
        float4 b = *(const float4*)(in + i + 4);
        *(uint4*)(hi + di) = make_uint4(pack2h(a.x, a.y), pack2h(a.z, a.w),
                                        pack2h(b.x, b.y), pack2h(b.z, b.w));
    }
}

// ---- embedding ---------------------------------------------------------------------
__global__ void embed_kernel(const int* __restrict__ idx, const float* __restrict__ wte,
                             float* __restrict__ x) {
    int t = blockIdx.x;
    int row = idx[t];
    float4 v = *(const float4*)(wte + (size_t)row * DD + threadIdx.x * 4);
    *(float4*)(x + (size_t)t * DD + threadIdx.x * 4) = v;
}

// ---- rmsnorm -------------------------------------------------------------------------
__global__ void rmsnorm_kernel(const float* __restrict__ in, float* __restrict__ out,
                               h16* __restrict__ ohi) {
    __shared__ float red[8];
    int row = blockIdx.x, tid = threadIdx.x;
    float4 v = *(const float4*)(in + (size_t)row * DD + tid * 4);
    float s = v.x*v.x + v.y*v.y + v.z*v.z + v.w*v.w;
    #pragma unroll
    for (int o = 16; o > 0; o >>= 1) s += __shfl_xor_sync(0xffffffff, s, o);
    if ((tid & 31) == 0) red[tid >> 5] = s;
    __syncthreads();
    if (tid < 8) {
        float t2 = red[tid];
        #pragma unroll
        for (int o = 4; o > 0; o >>= 1) t2 += __shfl_xor_sync(0xff, t2, o);
        if (tid == 0) red[0] = t2;
    }
    __syncthreads();
    float r = rsqrtf(red[0] / (float)DD + 1e-5f);
    float4 o4 = make_float4(v.x*r, v.y*r, v.z*r, v.w*r);
    if (out) *(float4*)(out + (size_t)row * DD + tid * 4) = o4;
    if (ohi) {
        size_t b = (size_t)row * DD + tid * 4;
        *(uint2*)(ohi + b) = make_uint2(pack2h(o4.x, o4.y), pack2h(o4.z, o4.w));
    }
}

// ---- RoPE on fp16 (h<16 -> qr in qqr; h==16 -> kr in c1h) -----------------------------
__global__ void rope_kernel(h16* __restrict__ qqr, h16* __restrict__ c1h) {
    int t = blockIdx.x, h = blockIdx.y, j = threadIdx.x;
    float f = powf(10000.f, -(float)j / 32.f);
    float sv, cv;
    sincosf((float)t * f, &sv, &cv);
    h16* p = (h < 16) ? (qqr + (size_t)t * 2048 + 1024 + h * RDIM)
                      : (c1h + (size_t)t * 1088 + 1024);
    float x0 = __half2float(p[j]), x1 = __half2float(p[j + 32]);
    p[j]      = __float2half_rn(x0 * cv - x1 * sv);
    p[j + 32] = __float2half_rn(x1 * cv + x0 * sv);
}

// ---- fp16 1-pass NT GEMM, 4-stage pipeline, optional z-fused second problem -----------
template<int BM, int BN>
__global__ void __launch_bounds__(256) gemm_mma(
    const h16* __restrict__ Ah_, const h16* __restrict__ Ah2_, int lda,
    const h16* __restrict__ Bh_, const h16* __restrict__ Bh2_,
    float* __restrict__ C, int ldc, const float* __restrict__ Rres,
    h16* __restrict__ Chi_, h16* __restrict__ Chi2_,
    int K, int relu)
{
    extern __shared__ uint32_t smw[];
    constexpr int AT  = BM * 16;
    constexpr int BT  = BN * 16;
    constexpr int STG = AT + BT;
    constexpr int NT  = BN / 16;
    constexpr int MT  = BM / 64;
    constexpr int D   = 4;

    const h16* Ah  = blockIdx.z ? Ah2_  : Ah_;
    const h16* Bh  = blockIdx.z ? Bh2_  : Bh_;
    h16*       Chi = blockIdx.z ? Chi2_ : Chi_;

    int tid = threadIdx.x, lane = tid & 31, w = tid >> 5;
    int wm = w & 3, wn = w >> 2;
    int bm = blockIdx.y * BM, bn = blockIdx.x * BN;
    int la = lane & 3, lr = lane >> 2;

    int rowl = (lane & 7) | (((lane >> 3) & 1) << 3);
    int csel = (lane >> 4) << 2;

    uint32_t sbase = (uint32_t)__cvta_generic_to_shared(smw);

    auto load_stage = [&](int i, int st) {
        int k0 = i * 32;
        uint32_t so = sbase + (uint32_t)(st * STG) * 4;
        #pragma unroll
        for (int e0 = 0; e0 < BM * 4; e0 += 256) {
            int e = e0 + tid;
            int r = e >> 2, kq = e & 3;
            size_t g = (size_t)(bm + r) * lda + k0 + kq * 8;
            uint32_t d = so + (uint32_t)(r * 16 + ((kq ^ (r & 3)) << 2)) * 4;
            cp16(d, Ah + g);
        }
        #pragma unroll
        for (int e0 = 0; e0 < BN * 4; e0 += 256) {
            int e = e0 + tid;
            int r = e >> 2, kq = e & 3;
            size_t g = (size_t)(bn + r) * K + k0 + kq * 8;
            uint32_t d = so + (uint32_t)(AT + r * 16 + ((kq ^ (r & 3)) << 2)) * 4;
            cp16(d, Bh + g);
        }
        CP_COMMIT();
    };

    float acc[MT][NT][4];
    #pragma unroll
    for (int mt = 0; mt < MT; mt++)
        #pragma unroll
        for (int nt = 0; nt < NT; nt++)
            #pragma unroll
            for (int c = 0; c < 4; c++) acc[mt][nt][c] = 0.f;

    int nk = K >> 5;
    #pragma unroll
    for (int s = 0; s < D - 1; s++) load_stage(s, s);

    for (int i = 0; i < nk; i++) {
        cp_wait<D - 2>();
        __syncthreads();
        if (i + D - 1 < nk) load_stage(i + D - 1, (i + D - 1) % D);
        else                CP_COMMIT();

        uint32_t SaB = sbase + (uint32_t)((i % D) * STG) * 4;
        uint32_t SbB = SaB + (uint32_t)AT * 4;
        #pragma unroll
        for (int ks = 0; ks < 2; ks++) {
            int w0 = ks * 8 + csel;
            uint32_t ah[MT][4];
            #pragma unroll
            for (int mt = 0; mt < MT; mt++) {
                uint32_t aaddr = SaB + (uint32_t)sadr(wm * (BM / 4) + mt * 16 + rowl, w0) * 4;
                ldm4(ah[mt], aaddr);
            }
            #pragma unroll
            for (int nt2 = 0; nt2 < NT / 2; nt2++) {
                uint32_t baddr = SbB + (uint32_t)sadr(wn * (BN / 2) + nt2 * 16 + rowl, w0) * 4;
                uint32_t bb[4];
                ldm4(bb, baddr);
                uint32_t b0[2] = { bb[0], bb[2] };
                uint32_t b1[2] = { bb[1], bb[3] };
                #pragma unroll
                for (int mt = 0; mt < MT; mt++) {
                    mma16816(acc[mt][2 * nt2],     ah[mt], b0);
                    mma16816(acc[mt][2 * nt2 + 1], ah[mt], b1);
                }
            }
        }
    }

    #pragma unroll
    for (int mt = 0; mt < MT; mt++) {
        #pragma unroll
        for (int nt = 0; nt < NT; nt++) {
            int col = bn + wn * (BN / 2) + nt * 8 + la * 2;
            #pragma unroll
            for (int half = 0; half < 2; half++) {
                int row = bm + wm * (BM / 4) + mt * 16 + lr + half * 8;
                float v0 = acc[mt][nt][half * 2 + 0];
                float v1 = acc[mt][nt][half * 2 + 1];
                size_t base = (size_t)row * ldc + col;
                if (Rres) {
                    float2 rr = *(const float2*)(Rres + base);
                    v0 += rr.x; v1 += rr.y;
                }
                if (relu) { v0 = fmaxf(v0, 0.f); v1 = fmaxf(v1, 0.f); }
                if (C) *(float2*)(C + base) = make_float2(v0, v1);
                if (Chi) *(uint32_t*)(Chi + base) = pack2h(v0, v1);
            }
        }
    }
}

// ---- flash attention, fp16 in/out, 1-pass MMA -------------------------------------------
#define QLD 2048
#define KRLD 1088
#define AQ 68
#define AV 36
#define ATTSM ((2*64*AQ + 64*AV) * 4 + 64*65*4 + (64+64+128+128) * 4)

__global__ void __launch_bounds__(256, 1) attn_mma(
    const h16* __restrict__ q,  const h16* __restrict__ qr,
    const h16* __restrict__ k,  const h16* __restrict__ v,
    const h16* __restrict__ kr,
    h16* __restrict__ atth)
{
    extern __shared__ uint32_t sw[];
    uint32_t* Qh = sw;
    uint32_t* Kh = Qh + 64 * AQ;
    uint32_t* Vh = Kh + 64 * AQ;
    float* Ob   = (float*)(Vh + 64 * AV);
    float* rowM = Ob + 64 * 65;
    float* rowL = rowM + 64;
    float* pm   = rowL + 64;
    float* ps   = pm + 128;

    int hh = blockIdx.y, tid = threadIdx.x;
    int lane = tid & 31, w = tid >> 5;
    int wm = w & 3, wn = w >> 2;
    int la = lane & 3, lr = lane >> 2;
    const float scale = rsqrtf(128.f);

    for (int half = 0; half < 2; half++) {
        int qt = half ? (15 - (int)blockIdx.x) : (int)blockIdx.x;

        for (int e = tid; e < 64 * 64; e += 256) {
            int r = e >> 6, wq = e & 63;
            int t = qt * 64 + r, d = wq * 2;
            const h16* src = (d < 64) ? (q + (size_t)t * QLD + hh * 64 + d)
                                      : (qr + (size_t)t * QLD + hh * 64 + (d - 64));
            Qh[r * AQ + wq] = *(const uint32_t*)src;
        }
        if (tid < 64) { rowM[tid] = -1e30f; rowL[tid] = 0.f; }

        float oacc[8][4];
        #pragma unroll
        for (int nt = 0; nt < 8; nt++)
            #pragma unroll
            for (int c = 0; c < 4; c++) oacc[nt][c] = 0.f;

        int rloc = wm * 16 + lr;

        for (int kt = 0; kt <= qt; kt++) {
            __syncthreads();

            for (int e = tid; e < 64 * 64; e += 256) {
                int r = e >> 6, wq = e & 63;
                int t = kt * 64 + r, d = wq * 2;
                const h16* src = (d < 64) ? (k + (size_t)t * QLD + hh * 64 + d)
                                          : (kr + (size_t)t * KRLD + (d - 64));
                Kh[r * AQ + wq] = *(const uint32_t*)src;
            }
            for (int e = tid; e < 64 * 32; e += 256) {
                int kp = e >> 6, d = e & 63;
                h16 v0 = v[(size_t)(kt * 64 + 2 * kp) * QLD + hh * 64 + d];
                h16 v1 = v[(size_t)(kt * 64 + 2 * kp + 1) * QLD + hh * 64 + d];
                Vh[d * AV + kp] = packh(v0, v1);
            }
            __syncthreads();

            float sacc[4][4];
            #pragma unroll
            for (int nt = 0; nt < 4; nt++)
                #pragma unroll
                for (int c = 0; c < 4; c++) sacc[nt][c] = 0.f;

            #pragma unroll
            for (int kk = 0; kk < 8; kk++) {
                int w0 = kk * 8 + la;
                uint32_t ah[4];
                ah[0] = Qh[rloc * AQ + w0];        ah[1] = Qh[(rloc + 8) * AQ + w0];
                ah[2] = Qh[rloc * AQ + w0 + 4];    ah[3] = Qh[(rloc + 8) * AQ + w0 + 4];
                #pragma unroll
                for (int nt = 0; nt < 4; nt++) {
                    int n0 = wn * 32 + nt * 8 + lr;
                    uint32_t bh[2] = { Kh[n0 * AQ + w0], Kh[n0 * AQ + w0 + 4] };
                    mma16816(sacc[nt], ah, bh);
                }
            }

            int rgA = qt * 64 + rloc, rgB = rgA + 8;
            #pragma unroll
            for (int nt = 0; nt < 4; nt++) {
                int cg = kt * 64 + wn * 32 + nt * 8 + 2 * la;
                sacc[nt][0] = (cg     <= rgA) ? sacc[nt][0] * scale : -1e30f;
                sacc[nt][1] = (cg + 1 <= rgA) ? sacc[nt][1] * scale : -1e30f;
                sacc[nt][2] = (cg     <= rgB) ? sacc[nt][2] * scale : -1e30f;
                sacc[nt][3] = (cg + 1 <= rgB) ? sacc[nt][3] * scale : -1e30f;
            }

            float mA = -1e30f, mB = -1e30f;
            #pragma unroll
            for (int nt = 0; nt < 4; nt++) {
                mA = fmaxf(mA, fmaxf(sacc[nt][0], sacc[nt][1]));
                mB = fmaxf(mB, fmaxf(sacc[nt][2], sacc[nt][3]));
            }
            mA = fmaxf(mA, __shfl_xor_sync(0xffffffff, mA, 1));
            mA = fmaxf(mA, __shfl_xor_sync(0xffffffff, mA, 2));
            mB = fmaxf(mB, __shfl_xor_sync(0xffffffff, mB, 1));
            mB = fmaxf(mB, __shfl_xor_sync(0xffffffff, mB, 2));
            if (la == 0) { pm[wn * 64 + rloc] = mA; pm[wn * 64 + rloc + 8] = mB; }
            __syncthreads();

            float moA = rowM[rloc], moB = rowM[rloc + 8];
            float mnA = fmaxf(moA, fmaxf(pm[rloc], pm[64 + rloc]));
            float mnB = fmaxf(moB, fmaxf(pm[rloc + 8], pm[64 + rloc + 8]));
            float alA = __expf(moA - mnA), alB = __expf(moB - mnB);

            float sA = 0.f, sB = 0.f;
            #pragma unroll
            for (int nt = 0; nt < 4; nt++) {
                sacc[nt][0] = __expf(sacc[nt][0] - mnA);
                sacc[nt][1] = __expf(sacc[nt][1] - mnA);
                sacc[nt][2] = __expf(sacc[nt][2] - mnB);
                sacc[nt][3] = __expf(sacc[nt][3] - mnB);
                sA += sacc[nt][0] + sacc[nt][1];
                sB += sacc[nt][2] + sacc[nt][3];
            }
            #pragma unroll
            for (int nt = 0; nt < 8; nt++) {
                oacc[nt][0] *= alA; oacc[nt][1] *= alA;
                oacc[nt][2] *= alB; oacc[nt][3] *= alB;
            }
            sA += __shfl_xor_sync(0xffffffff, sA, 1);
            sA += __shfl_xor_sync(0xffffffff, sA, 2);
            sB += __shfl_xor_sync(0xffffffff, sB, 1);
            sB += __shfl_xor_sync(0xffffffff, sB, 2);
            __syncthreads();
            if (la == 0) { ps[wn * 64 + rloc] = sA; ps[wn * 64 + rloc + 8] = sB; }
            if (wn == 0 && la == 0) { rowM[rloc] = mnA; rowM[rloc + 8] = mnB; }
            __syncthreads();
            if (wn == 0 && la == 0) {
                rowL[rloc]     = rowL[rloc]     * alA + ps[rloc]     + ps[64 + rloc];
                rowL[rloc + 8] = rowL[rloc + 8] * alB + ps[rloc + 8] + ps[64 + rloc + 8];
            }

            #pragma unroll
            for (int kc = 0; kc < 2; kc++) {
                uint32_t phi[4];
                phi[0] = pack2h(sacc[2*kc][0],   sacc[2*kc][1]);
                phi[1] = pack2h(sacc[2*kc][2],   sacc[2*kc][3]);
                phi[2] = pack2h(sacc[2*kc+1][0], sacc[2*kc+1][1]);
                phi[3] = pack2h(sacc[2*kc+1][2], sacc[2*kc+1][3]);
                int kw = wn * 16 + kc * 8 + la;
                #pragma unroll
                for (int nt = 0; nt < 8; nt++) {
                    int d0 = nt * 8 + lr;
                    uint32_t bh[2] = { Vh[d0 * AV + kw], Vh[d0 * AV + kw + 4] };
                    mma16816(oacc[nt], phi, bh);
                }
            }
        }

        __syncthreads();
        if (wn == 0) {
            #pragma unroll
            for (int nt = 0; nt < 8; nt++) {
                int c0 = nt * 8 + 2 * la;
                Ob[rloc * 65 + c0]         = oacc[nt][0];
                Ob[rloc * 65 + c0 + 1]     = oacc[nt][1];
                Ob[(rloc+8) * 65 + c0]     = oacc[nt][2];
                Ob[(rloc+8) * 65 + c0 + 1] = oacc[nt][3];
            }
        }
        __syncthreads();
        if (wn == 1) {
            #pragma unroll
            for (int nt = 0; nt < 8; nt++) {
                int c0 = nt * 8 + 2 * la;
                Ob[rloc * 65 + c0]         += oacc[nt][0];
                Ob[rloc * 65 + c0 + 1]     += oacc[nt][1];
                Ob[(rloc+8) * 65 + c0]     += oacc[nt][2];
                Ob[(rloc+8) * 65 + c0 + 1] += oacc[nt][3];
            }
        }
        __syncthreads();
        for (int e = tid; e < 64 * 32; e += 256) {
            int r = e >> 5, d2 = (e & 31) * 2;
            float v0 = Ob[r * 65 + d2]     / rowL[r];
            float v1 = Ob[r * 65 + d2 + 1] / rowL[r];
            size_t o = (size_t)(qt * 64 + r) * DD + hh * 64 + d2;
            *(uint32_t*)(atth + o) = pack2h(v0, v1);
        }
        __syncthreads();
    }
}

// ---- host orchestration -------------------------------------------------------------
#define SMEMSZ(BM,BN) (4 * ((BM) + (BN)) * 64)

template<int BM, int BN>
static void gemmT(const h16* Ah, int lda, const h16* Bh,
                  float* C, int ldc, const float* R, h16* Ch,
                  int M, int N, int K, int relu) {
    dim3 grid(N / BN, M / BM, 1);
    gemm_mma<BM, BN><<<grid, 256, SMEMSZ(BM, BN)>>>(Ah, Ah, lda, Bh, Bh, C, ldc, R, Ch, Ch, K, relu);
}
template<int BM, int BN>
static void gemmT2(const h16* Ah, const h16* Ah2, int lda,
                   const h16* Bh, const h16* Bh2,
                   h16* Ch, h16* Ch2, int ldc,
                   int M, int N, int K) {
    dim3 grid(N / BN, M / BM, 2);
    gemm_mma<BM, BN><<<grid, 256, SMEMSZ(BM, BN)>>>(Ah, Ah2, lda, Bh, Bh2,
                                                    nullptr, ldc, nullptr, Ch, Ch2, K, 0);
}

extern "C" void kernel_launch(void* const* d_in, const int* in_sizes, int n_in,
                              void* d_out, int out_size) {
    const int*   idx     = (const int*)  d_in[0];
    const float* wte     = (const float*)d_in[1];
    const float* wqdown  = (const float*)d_in[2];
    const float* wqup    = (const float*)d_in[3];
    const float* wqr     = (const float*)d_in[4];
    const float* wkvdown = (const float*)d_in[5];
    const float* wkup    = (const float*)d_in[6];
    const float* wvup    = (const float*)d_in[7];
    const float* wkr     = (const float*)d_in[8];
    const float* wo      = (const float*)d_in[9];
    const float* fc1     = (const float*)d_in[10];
    const float* fc2     = (const float*)d_in[11];
    const float* lm_head = (const float*)d_in[12];
    float* out = (float*)d_out;

    cudaFuncSetAttribute((void*)gemm_mma<128,128>, cudaFuncAttributeMaxDynamicSharedMemorySize, SMEMSZ(128,128));
    cudaFuncSetAttribute((void*)gemm_mma<128,64>,  cudaFuncAttributeMaxDynamicSharedMemorySize, SMEMSZ(128,64));
    cudaFuncSetAttribute((void*)gemm_mma<64,128>,  cudaFuncAttributeMaxDynamicSharedMemorySize, SMEMSZ(64,128));
    cudaFuncSetAttribute((void*)attn_mma,          cudaFuncAttributeMaxDynamicSharedMemorySize, ATTSM);

    void* p;
    cudaGetSymbolAddress(&p, g_x);    float* x   = (float*)p;
    cudaGetSymbolAddress(&p, g_c1h);  h16* c1h   = (h16*)p;
    cudaGetSymbolAddress(&p, g_qqr);  h16* qqr   = (h16*)p;
    cudaGetSymbolAddress(&p, g_kv);   h16* kv    = (h16*)p;
    cudaGetSymbolAddress(&p, g_nxh);  h16* nxh   = (h16*)p;
    cudaGetSymbolAddress(&p, g_atth); h16* atth  = (h16*)p;
    cudaGetSymbolAddress(&p, g_tmph); h16* tmph  = (h16*)p;
    cudaGetSymbolAddress(&p, g_xh);   h16* xh    = (h16*)p;
    cudaGetSymbolAddress(&p, g_wh);   h16* wh    = (h16*)p;

    // ---- fused weight layout ----
    cvt_h_s<<<2048,256>>>(wqdown,  wh+OFF_W1, NL*512*1024, 19, W1SZ, 0);
    cvt_h_s<<<2048,256>>>(wkvdown, wh+OFF_W1, NL*512*1024, 19, W1SZ, 512*1024);
    cvt_h_s<<<2048,256>>>(wkr,     wh+OFF_W1, NL*64*1024,  16, W1SZ, 1024*1024);
    cvt_h_s<<<2048,256>>>(wqup, wh+OFF_W2A, NL*1024*512, 19, W2SZ, 0);
    cvt_h_s<<<2048,256>>>(wqr,  wh+OFF_W2A, NL*1024*512, 19, W2SZ, 1024*512);
    cvt_h_s<<<2048,256>>>(wkup, wh+OFF_W2B, NL*1024*512, 19, W2SZ, 0);
    cvt_h_s<<<2048,256>>>(wvup, wh+OFF_W2B, NL*1024*512, 19, W2SZ, 1024*512);
    cvt_h_s<<<2048,256>>>(wo,      wh+OFF_WO,  NL*DD*DD, 20, DD*DD, 0);
    cvt_h_s<<<2048,256>>>(fc1,     wh+OFF_FC1, NL*FF*DD, 22, FF*DD, 0);
    cvt_h_s<<<2048,256>>>(fc2,     wh+OFF_FC2, NL*DD*FF, 22, DD*FF, 0);
    cvt_h_s<<<2048,256>>>(lm_head, wh+OFF_LMH, VV*DD,    30, VV*DD, 0);

    embed_kernel<<<TT, 256>>>(idx, wte, x);
    rmsnorm_kernel<<<TT, 256>>>(x, x, nullptr);

    for (int l = 0; l < NL; l++) {
        const h16* w1  = wh + OFF_W1  + (size_t)l * W1SZ;
        const h16* w2a = wh + OFF_W2A + (size_t)l * W2SZ;
        const h16* w2b = wh + OFF_W2B + (size_t)l * W2SZ;
        const h16* wol = wh + OFF_WO  + (size_t)l * DD*DD;
        const h16* f1  = wh + OFF_FC1 + (size_t)l * FF*DD;
        const h16* f2  = wh + OFF_FC2 + (size_t)l * DD*FF;

        rmsnorm_kernel<<<TT, 256>>>(x, nullptr, nxh);

        gemmT<128,64>(nxh, DD, w1, nullptr, 1088, nullptr, c1h, TT, 1088, DD, 0);
        gemmT2<128,128>(c1h, c1h + 512, 1088, w2a, w2b, qqr, kv, 2048, TT, 2048, LAT);

        rope_kernel<<<dim3(TT, 17), 32>>>(qqr, c1h);

        attn_mma<<<dim3(8, 16), 256, ATTSM>>>(qqr, qqr + 1024, kv, kv + 1024, c1h + 1024, atth);

        gemmT<64,128>(atth, DD, wol, x, DD, x, nullptr, TT, DD, DD, 0);

        rmsnorm_kernel<<<TT, 256>>>(x, nullptr, nxh);
        gemmT<128,128>(nxh, DD, f1, nullptr, FF, nullptr, tmph, TT, FF, DD, 1);
        bool last = (l == NL - 1);
        gemmT<64,128>(tmph, FF, f2, x, DD, x, last ? xh : nullptr, TT, DD, FF, 0);
    }

    gemmT<128,128>(xh, DD, wh + OFF_LMH, out, VV, nullptr, nullptr, TT, VV, DD, 0);
}